// round 12
// baseline (speedup 1.0000x reference)
#include <cuda_runtime.h>
#include <cuda_bf16.h>
#include <math.h>
#include <stdint.h>

#define Bb 32
#define Tt 500
#define Cc 512
#define Hh 8
#define Dd 64
#define Mrows (Bb*Tt)
#define NBUCKETS 49

// ---------------- scratch (static device globals; zero-initialized) ----------------
__device__ float g_res [(size_t)Mrows*Cc];
__device__ float g_x1  [(size_t)Mrows*Cc];
__device__ float g_res2[(size_t)Mrows*Cc];
__device__ unsigned char g_bucket[(size_t)Bb*Tt*Tt + 64];

// bf16 split buffers (padded; pad region stays zero)
__device__ __nv_bfloat16 g_qh[(size_t)(Bb*Hh*Tt + 64)*Dd], g_ql[(size_t)(Bb*Hh*Tt + 64)*Dd];
__device__ __nv_bfloat16 g_kh[(size_t)(Bb*Hh*Tt + 64)*Dd], g_kl[(size_t)(Bb*Hh*Tt + 64)*Dd];
__device__ __nv_bfloat16 g_vth[(size_t)Bb*Hh*Dd*512 + 1024], g_vtl[(size_t)Bb*Hh*Dd*512 + 1024];
__device__ __nv_bfloat16 g_ahi[(size_t)Mrows*1024 + 1024], g_alo[(size_t)Mrows*1024 + 1024];
__device__ __nv_bfloat16 g_bhi[(size_t)Mrows*1024 + 1024], g_blo[(size_t)Mrows*1024 + 1024];
__device__ __nv_bfloat16 g_wh_attn[1536*512], g_wl_attn[1536*512];
__device__ __nv_bfloat16 g_wh_proj[512*512],  g_wl_proj[512*512];
__device__ __nv_bfloat16 g_wh_fc[1024*512],   g_wl_fc[1024*512];
__device__ __nv_bfloat16 g_wh_fc2[512*1024],  g_wl_fc2[512*1024];

// ---------------- side stream + events, created before harness mem checkpoints ----
static cudaStream_t g_side;
static cudaEvent_t g_evF, g_evW, g_evJ;
static struct SideInit {
    SideInit() {
        cudaStreamCreateWithFlags(&g_side, cudaStreamNonBlocking);
        cudaEventCreateWithFlags(&g_evF, cudaEventDisableTiming);
        cudaEventCreateWithFlags(&g_evW, cudaEventDisableTiming);
        cudaEventCreateWithFlags(&g_evJ, cudaEventDisableTiming);
    }
} g_sideInit;

// ---------------- helpers ----------------
__device__ __forceinline__ uint32_t smem_u32(const void* p) {
    uint32_t a;
    asm("{ .reg .u64 t; cvta.to.shared.u64 t, %1; cvt.u32.u64 %0, t; }" : "=r"(a) : "l"(p));
    return a;
}
__device__ __forceinline__ uint32_t swz128(uint32_t o) { return o ^ ((o >> 3) & 0x70); }

__device__ __forceinline__ void cp16(uint32_t dst, const void* src) {
    asm volatile("cp.async.cg.shared.global [%0], [%1], 16;" :: "r"(dst), "l"(src));
}
__device__ __forceinline__ void cp_commit() {
    asm volatile("cp.async.commit_group;" ::: "memory");
}
template<int N> __device__ __forceinline__ void cp_wait() {
    asm volatile("cp.async.wait_group %0;" :: "n"(N) : "memory");
}

#define LDSM4(r, addr) \
    asm volatile("ldmatrix.sync.aligned.m8n8.x4.shared.b16 {%0,%1,%2,%3}, [%4];" \
        : "=r"((r)[0]),"=r"((r)[1]),"=r"((r)[2]),"=r"((r)[3]) : "r"(addr))

#define MMA16816(d, a, b0, b1) \
    asm volatile("mma.sync.aligned.m16n8k16.row.col.f32.bf16.bf16.f32 " \
        "{%0,%1,%2,%3}, {%4,%5,%6,%7}, {%8,%9}, {%0,%1,%2,%3};" \
        : "+f"((d)[0]),"+f"((d)[1]),"+f"((d)[2]),"+f"((d)[3]) \
        : "r"((a)[0]),"r"((a)[1]),"r"((a)[2]),"r"((a)[3]), "r"(b0),"r"(b1))

__device__ __forceinline__ void split_bf16(float v, unsigned short& h, unsigned short& l) {
    __nv_bfloat16 hb = __float2bfloat16(v);
    __nv_bfloat16 lb = __float2bfloat16(v - __bfloat162float(hb));
    h = __bfloat16_as_ushort(hb);
    l = __bfloat16_as_ushort(lb);
}

// ---------------- bucket ids: one block per (t, b), 32-entry rel->bucket table ----
__global__ void __launch_bounds__(128) bucket_kernel(const int* __restrict__ ct) {
    __shared__ unsigned char bres[32];
    const int t = blockIdx.x, b = blockIdx.y;
    if (threadIdx.x < 32) {
        float rel = (float)threadIdx.x;
        float idx;
        if (rel <= 12.0f) idx = rel;
        else idx = fminf(rintf(12.0f + logf(rel * (1.0f/12.0f)) * 5.7707801635558523f), 24.0f);
        bres[threadIdx.x] = (unsigned char)(int)(idx + 24.0f);
    }
    __syncthreads();
    const int j = threadIdx.x;
    if (j >= 125) return;
    const int2 c1 = ((const int2*)ct)[b*Tt + t];
    const int2* cs = ((const int2*)ct) + b*Tt + 4*j;
    uchar4 o;
    unsigned char* po = &o.x;
#pragma unroll
    for (int u = 0; u < 4; u++) {
        int2 c2 = cs[u];
        int dx = c1.x - c2.x, dy = c1.y - c2.y;
        int relI = (int)(sqrtf((float)(dx*dx + dy*dy)) * (1.0f/12.0f));
        po[u] = bres[relI];
    }
    *(uchar4*)(g_bucket + (size_t)b*(Tt*Tt) + (size_t)t*Tt + 4*j) = o;
}

// ---------------- bf16 split conversions ----------------
__global__ void __launch_bounds__(256) aconv_kernel(const float4* __restrict__ in,
    uint2* __restrict__ hi, uint2* __restrict__ lo, int n4)
{
    int i = blockIdx.x * blockDim.x + threadIdx.x;
    if (i >= n4) return;
    float4 f = in[i];
    unsigned short h0,h1,h2,h3,l0,l1,l2,l3;
    split_bf16(f.x, h0, l0); split_bf16(f.y, h1, l1);
    split_bf16(f.z, h2, l2); split_bf16(f.w, h3, l3);
    uint2 ho, lv;
    ho.x = (uint32_t)h0 | ((uint32_t)h1 << 16);
    ho.y = (uint32_t)h2 | ((uint32_t)h3 << 16);
    lv.x = (uint32_t)l0 | ((uint32_t)l1 << 16);
    lv.y = (uint32_t)l2 | ((uint32_t)l3 << 16);
    hi[i] = ho; lo[i] = lv;
}

// all four weights: W [K,N] fp32 -> WT [N,K] bf16 hi/lo, one merged launch
__global__ void __launch_bounds__(256) wconv_all(
    const float* __restrict__ W0, __nv_bfloat16* __restrict__ h0v, __nv_bfloat16* __restrict__ l0v,
    const float* __restrict__ W1, __nv_bfloat16* __restrict__ h1v, __nv_bfloat16* __restrict__ l1v,
    const float* __restrict__ W2, __nv_bfloat16* __restrict__ h2v, __nv_bfloat16* __restrict__ l2v,
    const float* __restrict__ W3, __nv_bfloat16* __restrict__ h3v, __nv_bfloat16* __restrict__ l3v)
{
    __shared__ float tile[32][33];
    int p = blockIdx.x;
    const float* W; __nv_bfloat16 *hi, *lo; int K, N, nb, kb;
    if (p < 768)       { W = W0; hi = h0v; lo = l0v; K = 512;  N = 1536; nb = p % 48;          kb = p / 48; }
    else if (p < 1024) { W = W1; hi = h1v; lo = l1v; K = 512;  N = 512;  nb = (p - 768) & 15;  kb = (p - 768) >> 4; }
    else if (p < 1536) { W = W2; hi = h2v; lo = l2v; K = 512;  N = 1024; nb = (p - 1024) & 31; kb = (p - 1024) >> 5; }
    else               { W = W3; hi = h3v; lo = l3v; K = 1024; N = 512;  nb = (p - 1536) & 15; kb = (p - 1536) >> 4; }
    nb <<= 5; kb <<= 5;
    int tx = threadIdx.x & 31, ty = threadIdx.x >> 5;
#pragma unroll
    for (int it = 0; it < 32; it += 8)
        tile[ty + it][tx] = W[(size_t)(kb + ty + it)*N + nb + tx];
    __syncthreads();
#pragma unroll
    for (int it = 0; it < 32; it += 8) {
        float f = tile[tx][ty + it];
        unsigned short h_, l_;
        split_bf16(f, h_, l_);
        size_t o = (size_t)(nb + ty + it)*K + kb + tx;
        hi[o] = __ushort_as_bfloat16(h_); lo[o] = __ushort_as_bfloat16(l_);
    }
}

// ---- mma.sync GEMM: CTA 128x64, KC=64, split bf16, cp.async 2-stage, 2 CTAs/SM ----
#define TA 16384
#define TB 8192
#define STAGE_B 49152
#define GSM_TOT 98304
template<int MODE>
__global__ void __launch_bounds__(256, 2) mma_gemm(
    const __nv_bfloat16* __restrict__ Ahi, const __nv_bfloat16* __restrict__ Alo,
    const __nv_bfloat16* __restrict__ Bhi, const __nv_bfloat16* __restrict__ Blo,
    const float* __restrict__ bias, float* __restrict__ Cout,
    const float* __restrict__ resid,
    __nv_bfloat16* __restrict__ Shi, __nv_bfloat16* __restrict__ Slo,
    int M, int N, int K)
{
    extern __shared__ char smraw[];
    const uint32_t sb = smem_u32(smraw);
    const int tid = threadIdx.x;
    const int wid = tid >> 5, lane = tid & 31;
    const int wm = wid & 3, wn = wid >> 2;
    const int m0 = blockIdx.y << 7, n0 = blockIdx.x << 6;

    const int ldr = tid >> 3, ldu = tid & 7;

    auto issue = [&](int kc, int buf) {
        uint32_t base = sb + buf*STAGE_B;
#pragma unroll
        for (int p = 0; p < 4; p++) {
            int row = ldr + (p << 5);
            uint32_t d = swz128((uint32_t)(row << 7) + (ldu << 4));
            size_t ao = (size_t)(m0 + row)*K + kc + (ldu << 3);
            cp16(base + d,      Ahi + ao);
            cp16(base + TA + d, Alo + ao);
        }
#pragma unroll
        for (int p = 0; p < 2; p++) {
            int row = ldr + (p << 5);
            uint32_t d = swz128((uint32_t)(row << 7) + (ldu << 4));
            size_t bo = (size_t)(n0 + row)*K + kc + (ldu << 3);
            cp16(base + 2*TA + d,      Bhi + bo);
            cp16(base + 2*TA + TB + d, Blo + bo);
        }
        cp_commit();
    };

    float acc[2][4][4] = {};

    const int grp = lane >> 3, rim = lane & 7;
    const int arow0 = (wm << 5) + ((grp & 1) << 3) + rim;
    const int aku0  = grp >> 1;
    const int brow0 = (wn << 5) + ((grp >> 1) << 3) + rim;
    const int bku0  = grp & 1;

    issue(0, 0);
    const int nch = K >> 6;
    for (int c = 0; c < nch; c++) {
        if (c + 1 < nch) { issue((c + 1) << 6, (c + 1) & 1); cp_wait<1>(); }
        else             { cp_wait<0>(); }
        __syncthreads();
        const uint32_t base = sb + (c & 1)*STAGE_B;
#pragma unroll
        for (int ks = 0; ks < 4; ks++) {
            uint32_t ah[2][4], al[2][4];
#pragma unroll
            for (int mt = 0; mt < 2; mt++) {
                uint32_t off = swz128((uint32_t)((arow0 + (mt << 4)) << 7) + ((aku0 + (ks << 1)) << 4));
                LDSM4(ah[mt], base + off);
                LDSM4(al[mt], base + TA + off);
            }
            uint32_t bh[2][4], bl[2][4];
#pragma unroll
            for (int nt2 = 0; nt2 < 2; nt2++) {
                uint32_t off = swz128((uint32_t)((brow0 + (nt2 << 4)) << 7) + ((bku0 + (ks << 1)) << 4));
                LDSM4(bh[nt2], base + 2*TA + off);
                LDSM4(bl[nt2], base + 2*TA + TB + off);
            }
#pragma unroll
            for (int mt = 0; mt < 2; mt++)
#pragma unroll
                for (int nt = 0; nt < 4; nt++) {
                    const uint32_t* fh = &bh[nt >> 1][(nt & 1) << 1];
                    const uint32_t* fl = &bl[nt >> 1][(nt & 1) << 1];
                    MMA16816(acc[mt][nt], ah[mt], fh[0], fh[1]);
                    MMA16816(acc[mt][nt], ah[mt], fl[0], fl[1]);
                    MMA16816(acc[mt][nt], al[mt], fh[0], fh[1]);
                }
        }
        __syncthreads();
    }

    // epilogue
#pragma unroll
    for (int mt = 0; mt < 2; mt++) {
#pragma unroll
        for (int half = 0; half < 2; half++) {
            int mrow = m0 + (wm << 5) + (mt << 4) + (half << 3) + (lane >> 2);
            int b_ = mrow / Tt, t = mrow - b_*Tt;
#pragma unroll
            for (int nt = 0; nt < 4; nt++) {
                int cix = n0 + (wn << 5) + (nt << 3) + ((lane & 3) << 1);
                float v0 = acc[mt][nt][half*2 + 0] + bias[cix];
                float v1 = acc[mt][nt][half*2 + 1] + bias[cix + 1];
                if (MODE == 0) {
                    unsigned short h0,l0,h1,l1;
                    split_bf16(v0, h0, l0); split_bf16(v1, h1, l1);
                    int sec = cix >> 9, cc2 = cix & 511, hh = cc2 >> 6, d = cc2 & 63;
                    int bh_ = b_*Hh + hh;
                    if (sec == 2) {
                        size_t r0i = ((size_t)(bh_*Dd + d))*512 + t;
                        size_t r1i = ((size_t)(bh_*Dd + d + 1))*512 + t;
                        g_vth[r0i] = __ushort_as_bfloat16(h0);
                        g_vth[r1i] = __ushort_as_bfloat16(h1);
                        g_vtl[r0i] = __ushort_as_bfloat16(l0);
                        g_vtl[r1i] = __ushort_as_bfloat16(l1);
                    } else {
                        size_t idx = ((size_t)(bh_*Tt + t))*Dd + d;
                        uint32_t ph = (uint32_t)h0 | ((uint32_t)h1 << 16);
                        uint32_t pl = (uint32_t)l0 | ((uint32_t)l1 << 16);
                        if (sec == 0) { *(uint32_t*)(g_qh + idx) = ph; *(uint32_t*)(g_ql + idx) = pl; }
                        else          { *(uint32_t*)(g_kh + idx) = ph; *(uint32_t*)(g_kl + idx) = pl; }
                    }
                } else if (MODE == 2) {
                    v0 = 0.5f * v0 * (1.0f + erff(v0 * 0.7071067811865475f));
                    v1 = 0.5f * v1 * (1.0f + erff(v1 * 0.7071067811865475f));
                    unsigned short h0,l0,h1,l1;
                    split_bf16(v0, h0, l0); split_bf16(v1, h1, l1);
                    size_t idx = (size_t)mrow*N + cix;
                    *(uint32_t*)(Shi + idx) = (uint32_t)h0 | ((uint32_t)h1 << 16);
                    *(uint32_t*)(Slo + idx) = (uint32_t)l0 | ((uint32_t)l1 << 16);
                } else {
                    float2 r = *(const float2*)(resid + (size_t)mrow*N + cix);
                    float2 o; o.x = v0 + r.x; o.y = v1 + r.y;
                    *(float2*)(Cout + (size_t)mrow*N + cix) = o;
                }
            }
        }
    }
}

// ---------------- mma.sync flash attention with RPE bias ----------------
#define SQH 0
#define SQL 8192
#define SKH 16384
#define SKL 24576
#define SVH 32768
#define SVL 40960
#define SPH 49152
#define SPL 57344
#define SPS 65536                    // float Ps[64][66] (S scores only)
#define SBK (SPS + 64*66*4)
#define SRP (SBK + 4096)
#define SRM (SRP + 256)
#define SRL (SRM + 256)
#define SRS (SRL + 256)
#define ASM_TOT (SRS + 256)

__global__ void __launch_bounds__(256) attn_mma(const float* __restrict__ rpe_table) {
    extern __shared__ char smraw[];
    const uint32_t sb = smem_u32(smraw);
    const int tid = threadIdx.x;
    const int wid = tid >> 5, lane = tid & 31;
    const int wm = wid & 3, wn = wid >> 2;
    const int qt = blockIdx.x;
    const int bh = blockIdx.y;
    const int b_ = bh >> 3, h = bh & 7;
    const int hp = bh >> 5, bp = bh & 31;
    const int t0 = qt << 6;

    float* rpe = (float*)(smraw + SRP);
    float* row_m = (float*)(smraw + SRM);
    float* row_l = (float*)(smraw + SRL);
    float* row_sc = (float*)(smraw + SRS);
    float* Ps = (float*)(smraw + SPS);
    unsigned char* bkt = (unsigned char*)(smraw + SBK);

    if (tid < NBUCKETS) rpe[tid] = rpe_table[hp*NBUCKETS + tid];
    if (tid < 64) { row_m[tid] = -INFINITY; row_l[tid] = 0.0f; }

    const int ldr = tid >> 3, ldu = tid & 7;

    {
        const __nv_bfloat16* qh = g_qh + ((size_t)bh*Tt + t0)*Dd;
        const __nv_bfloat16* ql = g_ql + ((size_t)bh*Tt + t0)*Dd;
#pragma unroll
        for (int p = 0; p < 2; p++) {
            int r = ldr + (p << 5);
            uint32_t d = swz128((uint32_t)(r << 7) + (ldu << 4));
            cp16(sb + SQH + d, qh + (size_t)r*Dd + (ldu << 3));
            cp16(sb + SQL + d, ql + (size_t)r*Dd + (ldu << 3));
        }
        cp_commit();
    }

    const int grp = lane >> 3, rim = lane & 7;
    const int arow0 = (wm << 4) + ((grp & 1) << 3) + rim;
    const int aku0  = grp >> 1;
    const int brow0 = (wn << 5) + ((grp >> 1) << 3) + rim;
    const int bku0  = grp & 1;

    float O[4][4] = {};
    const unsigned char* bkb = g_bucket + (size_t)bp*Tt*Tt;
    const int r0 = wm*16 + (lane >> 2);

    for (int s0 = 0; s0 < Tt; s0 += 64) {
        __syncthreads();
        {
            const __nv_bfloat16* kh = g_kh + ((size_t)bh*Tt + s0)*Dd;
            const __nv_bfloat16* kl = g_kl + ((size_t)bh*Tt + s0)*Dd;
            const __nv_bfloat16* vh = g_vth + (size_t)bh*Dd*512 + s0;
            const __nv_bfloat16* vl = g_vtl + (size_t)bh*Dd*512 + s0;
#pragma unroll
            for (int p = 0; p < 2; p++) {
                int r = ldr + (p << 5);
                uint32_t d = swz128((uint32_t)(r << 7) + (ldu << 4));
                cp16(sb + SKH + d, kh + (size_t)r*Dd + (ldu << 3));
                cp16(sb + SKL + d, kl + (size_t)r*Dd + (ldu << 3));
                cp16(sb + SVH + d, vh + (size_t)r*512 + (ldu << 3));
                cp16(sb + SVL + d, vl + (size_t)r*512 + (ldu << 3));
            }
            cp_commit();
        }
#pragma unroll
        for (int it = 0; it < 4; it++) {
            int f = tid + it*256;
            int r = f >> 4;
            int c4 = (f & 15) << 2;
            uchar4 u4 = make_uchar4(0,0,0,0);
            if (t0 + r < Tt && s0 + c4 < Tt)
                u4 = *(const uchar4*)(bkb + (size_t)(t0 + r)*Tt + s0 + c4);
            *(uchar4*)(bkt + r*64 + c4) = u4;
        }
        cp_wait<0>();
        __syncthreads();

        // ---- S = Q K^T (3-term split) ----
        float sacc[4][4] = {};
#pragma unroll
        for (int ks = 0; ks < 4; ks++) {
            uint32_t qhf[4], qlf[4];
            uint32_t aoff = swz128((uint32_t)(arow0 << 7) + ((aku0 + (ks << 1)) << 4));
            LDSM4(qhf, sb + SQH + aoff);
            LDSM4(qlf, sb + SQL + aoff);
#pragma unroll
            for (int nt2 = 0; nt2 < 2; nt2++) {
                uint32_t khf[4], klf[4];
                uint32_t boff = swz128((uint32_t)((brow0 + (nt2 << 4)) << 7) + ((bku0 + (ks << 1)) << 4));
                LDSM4(khf, sb + SKH + boff);
                LDSM4(klf, sb + SKL + boff);
#pragma unroll
                for (int hv = 0; hv < 2; hv++) {
                    int nt = nt2*2 + hv;
                    MMA16816(sacc[nt], qhf, khf[hv*2], khf[hv*2+1]);
                    MMA16816(sacc[nt], qhf, klf[hv*2], klf[hv*2+1]);
                    MMA16816(sacc[nt], qlf, khf[hv*2], khf[hv*2+1]);
                }
            }
        }
#pragma unroll
        for (int nt = 0; nt < 4; nt++) {
            int c0 = wn*32 + nt*8 + ((lane & 3) << 1);
            bool oob0 = (s0 + c0 >= Tt), oob1 = (s0 + c0 + 1 >= Tt);
#pragma unroll
            for (int rr = 0; rr < 2; rr++) {
                int r = r0 + rr*8;
                float v0 = sacc[nt][rr*2+0]*0.125f + rpe[bkt[r*64 + c0]];
                float v1 = sacc[nt][rr*2+1]*0.125f + rpe[bkt[r*64 + c0 + 1]];
                if (oob0) v0 = -INFINITY;
                if (oob1) v1 = -INFINITY;
                float2 o; o.x = v0; o.y = v1;
                *(float2*)&Ps[r*66 + c0] = o;
            }
        }
        __syncthreads();

        // ---- fused online softmax + P -> bf16 hi/lo (single pass, paired stores) ----
        {
            int r = tid >> 2, qq = tid & 3;
            int cbase = qq << 4;
            float mx = -INFINITY;
#pragma unroll
            for (int u = 0; u < 16; u++) mx = fmaxf(mx, Ps[r*66 + cbase + u]);
            mx = fmaxf(mx, __shfl_xor_sync(0xffffffffu, mx, 1));
            mx = fmaxf(mx, __shfl_xor_sync(0xffffffffu, mx, 2));
            float m_old = row_m[r];
            float m_new = fmaxf(m_old, mx);
            float ssum = 0.f;
#pragma unroll
            for (int u2 = 0; u2 < 8; u2++) {
                int c = cbase + (u2 << 1);
                float p0 = __expf(Ps[r*66 + c]     - m_new);
                float p1 = __expf(Ps[r*66 + c + 1] - m_new);
                ssum += p0;
                ssum += p1;
                unsigned short h0, l0, h1, l1;
                split_bf16(p0, h0, l0);
                split_bf16(p1, h1, l1);
                uint32_t off = swz128((uint32_t)(r << 7) + (c << 1));
                *(uint32_t*)(smraw + SPH + off) = (uint32_t)h0 | ((uint32_t)h1 << 16);
                *(uint32_t*)(smraw + SPL + off) = (uint32_t)l0 | ((uint32_t)l1 << 16);
            }
            ssum += __shfl_xor_sync(0xffffffffu, ssum, 1);
            ssum += __shfl_xor_sync(0xffffffffu, ssum, 2);
            if (qq == 0) {
                float sc = __expf(m_old - m_new);
                row_sc[r] = sc;
                row_l[r] = row_l[r]*sc + ssum;
                row_m[r] = m_new;
            }
        }
        __syncthreads();

        // ---- O = O*scale + P V ----
        {
            float sc0 = row_sc[r0], sc1 = row_sc[r0 + 8];
#pragma unroll
            for (int nt = 0; nt < 4; nt++) {
                O[nt][0] *= sc0; O[nt][1] *= sc0;
                O[nt][2] *= sc1; O[nt][3] *= sc1;
            }
#pragma unroll
            for (int ks = 0; ks < 4; ks++) {
                uint32_t phf[4], plf[4];
                uint32_t aoff = swz128((uint32_t)(arow0 << 7) + ((aku0 + (ks << 1)) << 4));
                LDSM4(phf, sb + SPH + aoff);
                LDSM4(plf, sb + SPL + aoff);
#pragma unroll
                for (int nt2 = 0; nt2 < 2; nt2++) {
                    uint32_t vhf[4], vlf[4];
                    uint32_t boff = swz128((uint32_t)((brow0 + (nt2 << 4)) << 7) + ((bku0 + (ks << 1)) << 4));
                    LDSM4(vhf, sb + SVH + boff);
                    LDSM4(vlf, sb + SVL + boff);
#pragma unroll
                    for (int hv = 0; hv < 2; hv++) {
                        int nt = nt2*2 + hv;
                        MMA16816(O[nt], phf, vhf[hv*2], vhf[hv*2+1]);
                        MMA16816(O[nt], phf, vlf[hv*2], vlf[hv*2+1]);
                        MMA16816(O[nt], plf, vhf[hv*2], vhf[hv*2+1]);
                    }
                }
            }
        }
    }

    // ---- finalize ----
    {
        float inv0 = 1.0f / row_l[r0];
        float inv1 = 1.0f / row_l[r0 + 8];
        int t_a = t0 + r0, t_b = t_a + 8;
#pragma unroll
        for (int nt = 0; nt < 4; nt++) {
            int c0 = wn*32 + nt*8 + ((lane & 3) << 1);
            if (t_a < Tt) {
                unsigned short h0,l0,h1,l1;
                split_bf16(O[nt][0]*inv0, h0, l0);
                split_bf16(O[nt][1]*inv0, h1, l1);
                size_t idx = ((size_t)(b_*Tt + t_a))*Cc + h*Dd + c0;
                *(uint32_t*)(g_ahi + idx) = (uint32_t)h0 | ((uint32_t)h1 << 16);
                *(uint32_t*)(g_alo + idx) = (uint32_t)l0 | ((uint32_t)l1 << 16);
            }
            if (t_b < Tt) {
                unsigned short h0,l0,h1,l1;
                split_bf16(O[nt][2]*inv1, h0, l0);
                split_bf16(O[nt][3]*inv1, h1, l1);
                size_t idx = ((size_t)(b_*Tt + t_b))*Cc + h*Dd + c0;
                *(uint32_t*)(g_ahi + idx) = (uint32_t)h0 | ((uint32_t)h1 << 16);
                *(uint32_t*)(g_alo + idx) = (uint32_t)l0 | ((uint32_t)l1 << 16);
            }
        }
    }
}

// ---------------- layernorm (optionally emits bf16 split) ----------------
__global__ void __launch_bounds__(256) ln_kernel(const float* __restrict__ in,
    const float* __restrict__ w, const float* __restrict__ b, float* __restrict__ out,
    __nv_bfloat16* __restrict__ shi, __nv_bfloat16* __restrict__ slo)
{
    __shared__ float red[8];
    int row = blockIdx.x;
    const float* x = in + (size_t)row*Cc;
    int tid = threadIdx.x;
    float v0 = x[tid], v1 = x[tid + 256];
    float s = v0 + v1;
#pragma unroll
    for (int o = 16; o > 0; o >>= 1) s += __shfl_xor_sync(0xffffffffu, s, o);
    if ((tid & 31) == 0) red[tid >> 5] = s;
    __syncthreads();
    float tot = red[0]+red[1]+red[2]+red[3]+red[4]+red[5]+red[6]+red[7];
    float mean = tot * (1.0f/512.0f);
    float d0 = v0 - mean, d1 = v1 - mean;
    float s2 = d0*d0 + d1*d1;
#pragma unroll
    for (int o = 16; o > 0; o >>= 1) s2 += __shfl_xor_sync(0xffffffffu, s2, o);
    __syncthreads();
    if ((tid & 31) == 0) red[tid >> 5] = s2;
    __syncthreads();
    float tot2 = red[0]+red[1]+red[2]+red[3]+red[4]+red[5]+red[6]+red[7];
    float inv = rsqrtf(tot2 * (1.0f/512.0f) + 1e-5f);
    float o0 = d0*inv*w[tid]       + b[tid];
    float o1 = d1*inv*w[tid + 256] + b[tid + 256];
    out[(size_t)row*Cc + tid]       = o0;
    out[(size_t)row*Cc + tid + 256] = o1;
    if (shi) {
        unsigned short h0,l0,h1,l1;
        split_bf16(o0, h0, l0); split_bf16(o1, h1, l1);
        shi[(size_t)row*Cc + tid]       = __ushort_as_bfloat16(h0);
        shi[(size_t)row*Cc + tid + 256] = __ushort_as_bfloat16(h1);
        slo[(size_t)row*Cc + tid]       = __ushort_as_bfloat16(l0);
        slo[(size_t)row*Cc + tid + 256] = __ushort_as_bfloat16(l1);
    }
}

// ---------------- launch ----------------
extern "C" void kernel_launch(void* const* d_in, const int* in_sizes, int n_in,
                              void* d_out, int out_size) {
    (void)in_sizes; (void)n_in; (void)out_size;
    const float* x         = (const float*)d_in[0];
    const int*   ct        = (const int*)  d_in[1];
    const float* w_attn    = (const float*)d_in[2];
    const float* b_attn    = (const float*)d_in[3];
    const float* w_proj    = (const float*)d_in[4];
    const float* b_proj    = (const float*)d_in[5];
    const float* rpe_table = (const float*)d_in[6];
    const float* ln1_w     = (const float*)d_in[7];
    const float* ln1_b     = (const float*)d_in[8];
    const float* ln2_w     = (const float*)d_in[9];
    const float* ln2_b     = (const float*)d_in[10];
    const float* w_fc      = (const float*)d_in[11];
    const float* b_fc      = (const float*)d_in[12];
    const float* w_fc2     = (const float*)d_in[13];
    const float* b_fc2     = (const float*)d_in[14];
    float* out = (float*)d_out;

    float *res_, *x1_, *res2_;
    cudaGetSymbolAddress((void**)&res_,  g_res);
    cudaGetSymbolAddress((void**)&x1_,   g_x1);
    cudaGetSymbolAddress((void**)&res2_, g_res2);
    __nv_bfloat16 *ahi, *alo, *bhi, *blo;
    __nv_bfloat16 *wha, *wla, *whp, *wlp, *whf, *wlf, *whf2, *wlf2;
    cudaGetSymbolAddress((void**)&ahi,  g_ahi);
    cudaGetSymbolAddress((void**)&alo,  g_alo);
    cudaGetSymbolAddress((void**)&bhi,  g_bhi);
    cudaGetSymbolAddress((void**)&blo,  g_blo);
    cudaGetSymbolAddress((void**)&wha,  g_wh_attn);
    cudaGetSymbolAddress((void**)&wla,  g_wl_attn);
    cudaGetSymbolAddress((void**)&whp,  g_wh_proj);
    cudaGetSymbolAddress((void**)&wlp,  g_wl_proj);
    cudaGetSymbolAddress((void**)&whf,  g_wh_fc);
    cudaGetSymbolAddress((void**)&wlf,  g_wl_fc);
    cudaGetSymbolAddress((void**)&whf2, g_wh_fc2);
    cudaGetSymbolAddress((void**)&wlf2, g_wl_fc2);

    cudaFuncSetAttribute(attn_mma, cudaFuncAttributeMaxDynamicSharedMemorySize, ASM_TOT);
    cudaFuncSetAttribute(mma_gemm<0>, cudaFuncAttributeMaxDynamicSharedMemorySize, GSM_TOT);
    cudaFuncSetAttribute(mma_gemm<1>, cudaFuncAttributeMaxDynamicSharedMemorySize, GSM_TOT);
    cudaFuncSetAttribute(mma_gemm<2>, cudaFuncAttributeMaxDynamicSharedMemorySize, GSM_TOT);
    cudaFuncSetAttribute(mma_gemm<3>, cudaFuncAttributeMaxDynamicSharedMemorySize, GSM_TOT);

    // fork: side stream does wconv (needed by gemm0) then bucket (needed by attn)
    cudaEventRecord(g_evF, 0);
    cudaStreamWaitEvent(g_side, g_evF, 0);
    wconv_all<<<2048, 256, 0, g_side>>>(w_attn, wha, wla, w_proj, whp, wlp,
                                        w_fc, whf, wlf, w_fc2, whf2, wlf2);
    cudaEventRecord(g_evW, g_side);
    bucket_kernel<<<dim3(Tt, Bb), 128, 0, g_side>>>(ct);
    cudaEventRecord(g_evJ, g_side);

    // main stream: activation split runs concurrently with wconv
    aconv_kernel<<<(Mrows*Cc/4 + 255)/256, 256>>>((const float4*)x, (uint2*)ahi, (uint2*)alo, Mrows*Cc/4);
    cudaStreamWaitEvent(0, g_evW, 0);
    mma_gemm<0><<<dim3(24, 125), 256, GSM_TOT>>>(ahi, alo, wha, wla, b_attn,
                                                 nullptr, nullptr, nullptr, nullptr, Mrows, 3*Cc, Cc);

    // join: attention needs the bucket array
    cudaStreamWaitEvent(0, g_evJ, 0);
    attn_mma<<<dim3(8, Bb*Hh), 256, ASM_TOT>>>(rpe_table);

    // proj + resid -> ln1 (emits x1 split)
    mma_gemm<1><<<dim3(8, 125), 256, GSM_TOT>>>(ahi, alo, whp, wlp, b_proj,
                                                res_, x, nullptr, nullptr, Mrows, Cc, Cc);
    ln_kernel<<<Mrows, 256>>>(res_, ln1_w, ln1_b, x1_, ahi, alo);

    // fc + gelu (emits h split) -> fc2 + resid -> ln2
    mma_gemm<2><<<dim3(16, 125), 256, GSM_TOT>>>(ahi, alo, whf, wlf, b_fc,
                                                 nullptr, nullptr, bhi, blo, Mrows, 2*Cc, Cc);
    mma_gemm<3><<<dim3(8, 125), 256, GSM_TOT>>>(bhi, blo, whf2, wlf2, b_fc2,
                                                res2_, x1_, nullptr, nullptr, Mrows, Cc, 2*Cc);
    ln_kernel<<<Mrows, 256>>>(res2_, ln2_w, ln2_b, out, nullptr, nullptr);
}

// round 13
// speedup vs baseline: 1.5297x; 1.5297x over previous
#include <cuda_runtime.h>
#include <cuda_bf16.h>
#include <math.h>
#include <stdint.h>

#define Bb 32
#define Tt 500
#define Cc 512
#define Hh 8
#define Dd 64
#define Mrows (Bb*Tt)
#define NBUCKETS 49

// ---------------- scratch (static device globals; zero-initialized) ----------------
__device__ float g_res [(size_t)Mrows*Cc];
__device__ float g_x1  [(size_t)Mrows*Cc];
__device__ float g_res2[(size_t)Mrows*Cc];
__device__ unsigned char g_bucket[(size_t)Bb*Tt*Tt + 64];

// bf16 split buffers (padded; pad region stays zero)
__device__ __nv_bfloat16 g_qh[(size_t)(Bb*Hh*Tt + 64)*Dd], g_ql[(size_t)(Bb*Hh*Tt + 64)*Dd];
__device__ __nv_bfloat16 g_kh[(size_t)(Bb*Hh*Tt + 64)*Dd], g_kl[(size_t)(Bb*Hh*Tt + 64)*Dd];
__device__ __nv_bfloat16 g_vth[(size_t)Bb*Hh*Dd*512 + 1024], g_vtl[(size_t)Bb*Hh*Dd*512 + 1024];
__device__ __nv_bfloat16 g_ahi[(size_t)Mrows*1024 + 1024], g_alo[(size_t)Mrows*1024 + 1024];
__device__ __nv_bfloat16 g_bhi[(size_t)Mrows*1024 + 1024], g_blo[(size_t)Mrows*1024 + 1024];
__device__ __nv_bfloat16 g_wh_attn[1536*512], g_wl_attn[1536*512];
__device__ __nv_bfloat16 g_wh_proj[512*512],  g_wl_proj[512*512];
__device__ __nv_bfloat16 g_wh_fc[1024*512],   g_wl_fc[1024*512];
__device__ __nv_bfloat16 g_wh_fc2[512*1024],  g_wl_fc2[512*1024];

// ---------------- side stream + events, created before harness mem checkpoints ----
static cudaStream_t g_side;
static cudaEvent_t g_evF, g_evW, g_evJ;
static struct SideInit {
    SideInit() {
        cudaStreamCreateWithFlags(&g_side, cudaStreamNonBlocking);
        cudaEventCreateWithFlags(&g_evF, cudaEventDisableTiming);
        cudaEventCreateWithFlags(&g_evW, cudaEventDisableTiming);
        cudaEventCreateWithFlags(&g_evJ, cudaEventDisableTiming);
    }
} g_sideInit;

// ---------------- helpers ----------------
__device__ __forceinline__ uint32_t smem_u32(const void* p) {
    uint32_t a;
    asm("{ .reg .u64 t; cvta.to.shared.u64 t, %1; cvt.u32.u64 %0, t; }" : "=r"(a) : "l"(p));
    return a;
}
__device__ __forceinline__ uint32_t swz128(uint32_t o) { return o ^ ((o >> 3) & 0x70); }

__device__ __forceinline__ void cp16(uint32_t dst, const void* src) {
    asm volatile("cp.async.cg.shared.global [%0], [%1], 16;" :: "r"(dst), "l"(src));
}
__device__ __forceinline__ void cp_commit() {
    asm volatile("cp.async.commit_group;" ::: "memory");
}
template<int N> __device__ __forceinline__ void cp_wait() {
    asm volatile("cp.async.wait_group %0;" :: "n"(N) : "memory");
}

#define LDSM4(r, addr) \
    asm volatile("ldmatrix.sync.aligned.m8n8.x4.shared.b16 {%0,%1,%2,%3}, [%4];" \
        : "=r"((r)[0]),"=r"((r)[1]),"=r"((r)[2]),"=r"((r)[3]) : "r"(addr))

#define MMA16816(d, a, b0, b1) \
    asm volatile("mma.sync.aligned.m16n8k16.row.col.f32.bf16.bf16.f32 " \
        "{%0,%1,%2,%3}, {%4,%5,%6,%7}, {%8,%9}, {%0,%1,%2,%3};" \
        : "+f"((d)[0]),"+f"((d)[1]),"+f"((d)[2]),"+f"((d)[3]) \
        : "r"((a)[0]),"r"((a)[1]),"r"((a)[2]),"r"((a)[3]), "r"(b0),"r"(b1))

__device__ __forceinline__ void split_bf16(float v, unsigned short& h, unsigned short& l) {
    __nv_bfloat16 hb = __float2bfloat16(v);
    __nv_bfloat16 lb = __float2bfloat16(v - __bfloat162float(hb));
    h = __bfloat16_as_ushort(hb);
    l = __bfloat16_as_ushort(lb);
}

// ---------------- bucket ids: one block per (t, b), 32-entry rel->bucket table ----
__global__ void __launch_bounds__(128) bucket_kernel(const int* __restrict__ ct) {
    __shared__ unsigned char bres[32];
    const int t = blockIdx.x, b = blockIdx.y;
    if (threadIdx.x < 32) {
        float rel = (float)threadIdx.x;
        float idx;
        if (rel <= 12.0f) idx = rel;
        else idx = fminf(rintf(12.0f + logf(rel * (1.0f/12.0f)) * 5.7707801635558523f), 24.0f);
        bres[threadIdx.x] = (unsigned char)(int)(idx + 24.0f);
    }
    __syncthreads();
    const int j = threadIdx.x;
    if (j >= 125) return;
    const int2 c1 = ((const int2*)ct)[b*Tt + t];
    const int2* cs = ((const int2*)ct) + b*Tt + 4*j;
    uchar4 o;
    unsigned char* po = &o.x;
#pragma unroll
    for (int u = 0; u < 4; u++) {
        int2 c2 = cs[u];
        int dx = c1.x - c2.x, dy = c1.y - c2.y;
        int relI = (int)(sqrtf((float)(dx*dx + dy*dy)) * (1.0f/12.0f));
        po[u] = bres[relI];
    }
    *(uchar4*)(g_bucket + (size_t)b*(Tt*Tt) + (size_t)t*Tt + 4*j) = o;
}

// ---------------- bf16 split conversions ----------------
__global__ void __launch_bounds__(256) aconv_kernel(const float4* __restrict__ in,
    uint2* __restrict__ hi, uint2* __restrict__ lo, int n4)
{
    int i = blockIdx.x * blockDim.x + threadIdx.x;
    if (i >= n4) return;
    float4 f = in[i];
    unsigned short h0,h1,h2,h3,l0,l1,l2,l3;
    split_bf16(f.x, h0, l0); split_bf16(f.y, h1, l1);
    split_bf16(f.z, h2, l2); split_bf16(f.w, h3, l3);
    uint2 ho, lv;
    ho.x = (uint32_t)h0 | ((uint32_t)h1 << 16);
    ho.y = (uint32_t)h2 | ((uint32_t)h3 << 16);
    lv.x = (uint32_t)l0 | ((uint32_t)l1 << 16);
    lv.y = (uint32_t)l2 | ((uint32_t)l3 << 16);
    hi[i] = ho; lo[i] = lv;
}

// all four weights: W [K,N] fp32 -> WT [N,K] bf16 hi/lo, one merged launch
__global__ void __launch_bounds__(256) wconv_all(
    const float* __restrict__ W0, __nv_bfloat16* __restrict__ h0v, __nv_bfloat16* __restrict__ l0v,
    const float* __restrict__ W1, __nv_bfloat16* __restrict__ h1v, __nv_bfloat16* __restrict__ l1v,
    const float* __restrict__ W2, __nv_bfloat16* __restrict__ h2v, __nv_bfloat16* __restrict__ l2v,
    const float* __restrict__ W3, __nv_bfloat16* __restrict__ h3v, __nv_bfloat16* __restrict__ l3v)
{
    __shared__ float tile[32][33];
    int p = blockIdx.x;
    const float* W; __nv_bfloat16 *hi, *lo; int K, N, nb, kb;
    if (p < 768)       { W = W0; hi = h0v; lo = l0v; K = 512;  N = 1536; nb = p % 48;          kb = p / 48; }
    else if (p < 1024) { W = W1; hi = h1v; lo = l1v; K = 512;  N = 512;  nb = (p - 768) & 15;  kb = (p - 768) >> 4; }
    else if (p < 1536) { W = W2; hi = h2v; lo = l2v; K = 512;  N = 1024; nb = (p - 1024) & 31; kb = (p - 1024) >> 5; }
    else               { W = W3; hi = h3v; lo = l3v; K = 1024; N = 512;  nb = (p - 1536) & 15; kb = (p - 1536) >> 4; }
    nb <<= 5; kb <<= 5;
    int tx = threadIdx.x & 31, ty = threadIdx.x >> 5;
#pragma unroll
    for (int it = 0; it < 32; it += 8)
        tile[ty + it][tx] = W[(size_t)(kb + ty + it)*N + nb + tx];
    __syncthreads();
#pragma unroll
    for (int it = 0; it < 32; it += 8) {
        float f = tile[tx][ty + it];
        unsigned short h_, l_;
        split_bf16(f, h_, l_);
        size_t o = (size_t)(nb + ty + it)*K + kb + tx;
        hi[o] = __ushort_as_bfloat16(h_); lo[o] = __ushort_as_bfloat16(l_);
    }
}

// ---- mma.sync GEMM: CTA 128x64, KC=64, split bf16, cp.async 2-stage, 2 CTAs/SM ----
#define TA 16384
#define TB 8192
#define STAGE_B 49152
#define GSM_TOT 98304
template<int MODE>
__global__ void __launch_bounds__(256, 2) mma_gemm(
    const __nv_bfloat16* __restrict__ Ahi, const __nv_bfloat16* __restrict__ Alo,
    const __nv_bfloat16* __restrict__ Bhi, const __nv_bfloat16* __restrict__ Blo,
    const float* __restrict__ bias, float* __restrict__ Cout,
    const float* __restrict__ resid,
    __nv_bfloat16* __restrict__ Shi, __nv_bfloat16* __restrict__ Slo,
    int M, int N, int K)
{
    extern __shared__ char smraw[];
    const uint32_t sb = smem_u32(smraw);
    const int tid = threadIdx.x;
    const int wid = tid >> 5, lane = tid & 31;
    const int wm = wid & 3, wn = wid >> 2;
    const int m0 = blockIdx.y << 7, n0 = blockIdx.x << 6;

    const int ldr = tid >> 3, ldu = tid & 7;

    auto issue = [&](int kc, int buf) {
        uint32_t base = sb + buf*STAGE_B;
#pragma unroll
        for (int p = 0; p < 4; p++) {
            int row = ldr + (p << 5);
            uint32_t d = swz128((uint32_t)(row << 7) + (ldu << 4));
            size_t ao = (size_t)(m0 + row)*K + kc + (ldu << 3);
            cp16(base + d,      Ahi + ao);
            cp16(base + TA + d, Alo + ao);
        }
#pragma unroll
        for (int p = 0; p < 2; p++) {
            int row = ldr + (p << 5);
            uint32_t d = swz128((uint32_t)(row << 7) + (ldu << 4));
            size_t bo = (size_t)(n0 + row)*K + kc + (ldu << 3);
            cp16(base + 2*TA + d,      Bhi + bo);
            cp16(base + 2*TA + TB + d, Blo + bo);
        }
        cp_commit();
    };

    float acc[2][4][4] = {};

    const int grp = lane >> 3, rim = lane & 7;
    const int arow0 = (wm << 5) + ((grp & 1) << 3) + rim;
    const int aku0  = grp >> 1;
    const int brow0 = (wn << 5) + ((grp >> 1) << 3) + rim;
    const int bku0  = grp & 1;

    issue(0, 0);
    const int nch = K >> 6;
    for (int c = 0; c < nch; c++) {
        if (c + 1 < nch) { issue((c + 1) << 6, (c + 1) & 1); cp_wait<1>(); }
        else             { cp_wait<0>(); }
        __syncthreads();
        const uint32_t base = sb + (c & 1)*STAGE_B;
#pragma unroll
        for (int ks = 0; ks < 4; ks++) {
            uint32_t ah[2][4], al[2][4];
#pragma unroll
            for (int mt = 0; mt < 2; mt++) {
                uint32_t off = swz128((uint32_t)((arow0 + (mt << 4)) << 7) + ((aku0 + (ks << 1)) << 4));
                LDSM4(ah[mt], base + off);
                LDSM4(al[mt], base + TA + off);
            }
            uint32_t bh[2][4], bl[2][4];
#pragma unroll
            for (int nt2 = 0; nt2 < 2; nt2++) {
                uint32_t off = swz128((uint32_t)((brow0 + (nt2 << 4)) << 7) + ((bku0 + (ks << 1)) << 4));
                LDSM4(bh[nt2], base + 2*TA + off);
                LDSM4(bl[nt2], base + 2*TA + TB + off);
            }
#pragma unroll
            for (int mt = 0; mt < 2; mt++)
#pragma unroll
                for (int nt = 0; nt < 4; nt++) {
                    const uint32_t* fh = &bh[nt >> 1][(nt & 1) << 1];
                    const uint32_t* fl = &bl[nt >> 1][(nt & 1) << 1];
                    MMA16816(acc[mt][nt], ah[mt], fh[0], fh[1]);
                    MMA16816(acc[mt][nt], ah[mt], fl[0], fl[1]);
                    MMA16816(acc[mt][nt], al[mt], fh[0], fh[1]);
                }
        }
        __syncthreads();
    }

    // epilogue
#pragma unroll
    for (int mt = 0; mt < 2; mt++) {
#pragma unroll
        for (int half = 0; half < 2; half++) {
            int mrow = m0 + (wm << 5) + (mt << 4) + (half << 3) + (lane >> 2);
            int b_ = mrow / Tt, t = mrow - b_*Tt;
#pragma unroll
            for (int nt = 0; nt < 4; nt++) {
                int cix = n0 + (wn << 5) + (nt << 3) + ((lane & 3) << 1);
                float v0 = acc[mt][nt][half*2 + 0] + bias[cix];
                float v1 = acc[mt][nt][half*2 + 1] + bias[cix + 1];
                if (MODE == 0) {
                    unsigned short h0,l0,h1,l1;
                    split_bf16(v0, h0, l0); split_bf16(v1, h1, l1);
                    int sec = cix >> 9, cc2 = cix & 511, hh = cc2 >> 6, d = cc2 & 63;
                    int bh_ = b_*Hh + hh;
                    if (sec == 2) {
                        size_t r0i = ((size_t)(bh_*Dd + d))*512 + t;
                        size_t r1i = ((size_t)(bh_*Dd + d + 1))*512 + t;
                        g_vth[r0i] = __ushort_as_bfloat16(h0);
                        g_vth[r1i] = __ushort_as_bfloat16(h1);
                        g_vtl[r0i] = __ushort_as_bfloat16(l0);
                        g_vtl[r1i] = __ushort_as_bfloat16(l1);
                    } else {
                        size_t idx = ((size_t)(bh_*Tt + t))*Dd + d;
                        uint32_t ph = (uint32_t)h0 | ((uint32_t)h1 << 16);
                        uint32_t pl = (uint32_t)l0 | ((uint32_t)l1 << 16);
                        if (sec == 0) { *(uint32_t*)(g_qh + idx) = ph; *(uint32_t*)(g_ql + idx) = pl; }
                        else          { *(uint32_t*)(g_kh + idx) = ph; *(uint32_t*)(g_kl + idx) = pl; }
                    }
                } else if (MODE == 2) {
                    v0 = 0.5f * v0 * (1.0f + erff(v0 * 0.7071067811865475f));
                    v1 = 0.5f * v1 * (1.0f + erff(v1 * 0.7071067811865475f));
                    unsigned short h0,l0,h1,l1;
                    split_bf16(v0, h0, l0); split_bf16(v1, h1, l1);
                    size_t idx = (size_t)mrow*N + cix;
                    *(uint32_t*)(Shi + idx) = (uint32_t)h0 | ((uint32_t)h1 << 16);
                    *(uint32_t*)(Slo + idx) = (uint32_t)l0 | ((uint32_t)l1 << 16);
                } else {
                    float2 r = *(const float2*)(resid + (size_t)mrow*N + cix);
                    float2 o; o.x = v0 + r.x; o.y = v1 + r.y;
                    *(float2*)(Cout + (size_t)mrow*N + cix) = o;
                }
            }
        }
    }
}

// ---------------- mma.sync flash attention with RPE bias ----------------
#define SQH 0
#define SQL 8192
#define SKH 16384
#define SKL 24576
#define SVH 32768
#define SVL 40960
#define SPH 49152
#define SPL 57344
#define SPS 65536                    // float Ps[64][66] (S scores only)
#define SBK (SPS + 64*66*4)
#define SRP (SBK + 4096)
#define SRM (SRP + 256)
#define SRL (SRM + 256)
#define SRS (SRL + 256)
#define ASM_TOT (SRS + 256)

__global__ void __launch_bounds__(256) attn_mma(const float* __restrict__ rpe_table) {
    extern __shared__ char smraw[];
    const uint32_t sb = smem_u32(smraw);
    const int tid = threadIdx.x;
    const int wid = tid >> 5, lane = tid & 31;
    const int wm = wid & 3, wn = wid >> 2;
    const int qt = blockIdx.x;
    const int bh = blockIdx.y;
    const int b_ = bh >> 3, h = bh & 7;
    const int hp = bh >> 5, bp = bh & 31;
    const int t0 = qt << 6;

    float* rpe = (float*)(smraw + SRP);
    float* row_m = (float*)(smraw + SRM);
    float* row_l = (float*)(smraw + SRL);
    float* row_sc = (float*)(smraw + SRS);
    float* Ps = (float*)(smraw + SPS);
    unsigned char* bkt = (unsigned char*)(smraw + SBK);

    if (tid < NBUCKETS) rpe[tid] = rpe_table[hp*NBUCKETS + tid];
    if (tid < 64) { row_m[tid] = -INFINITY; row_l[tid] = 0.0f; }

    const int ldr = tid >> 3, ldu = tid & 7;

    {
        const __nv_bfloat16* qh = g_qh + ((size_t)bh*Tt + t0)*Dd;
        const __nv_bfloat16* ql = g_ql + ((size_t)bh*Tt + t0)*Dd;
#pragma unroll
        for (int p = 0; p < 2; p++) {
            int r = ldr + (p << 5);
            uint32_t d = swz128((uint32_t)(r << 7) + (ldu << 4));
            cp16(sb + SQH + d, qh + (size_t)r*Dd + (ldu << 3));
            cp16(sb + SQL + d, ql + (size_t)r*Dd + (ldu << 3));
        }
        cp_commit();
    }

    const int grp = lane >> 3, rim = lane & 7;
    const int arow0 = (wm << 4) + ((grp & 1) << 3) + rim;
    const int aku0  = grp >> 1;
    const int brow0 = (wn << 5) + ((grp >> 1) << 3) + rim;
    const int bku0  = grp & 1;

    float O[4][4] = {};
    const unsigned char* bkb = g_bucket + (size_t)bp*Tt*Tt;
    const int r0 = wm*16 + (lane >> 2);

    for (int s0 = 0; s0 < Tt; s0 += 64) {
        __syncthreads();
        {
            const __nv_bfloat16* kh = g_kh + ((size_t)bh*Tt + s0)*Dd;
            const __nv_bfloat16* kl = g_kl + ((size_t)bh*Tt + s0)*Dd;
            const __nv_bfloat16* vh = g_vth + (size_t)bh*Dd*512 + s0;
            const __nv_bfloat16* vl = g_vtl + (size_t)bh*Dd*512 + s0;
#pragma unroll
            for (int p = 0; p < 2; p++) {
                int r = ldr + (p << 5);
                uint32_t d = swz128((uint32_t)(r << 7) + (ldu << 4));
                cp16(sb + SKH + d, kh + (size_t)r*Dd + (ldu << 3));
                cp16(sb + SKL + d, kl + (size_t)r*Dd + (ldu << 3));
                cp16(sb + SVH + d, vh + (size_t)r*512 + (ldu << 3));
                cp16(sb + SVL + d, vl + (size_t)r*512 + (ldu << 3));
            }
            cp_commit();
        }
#pragma unroll
        for (int it = 0; it < 4; it++) {
            int f = tid + it*256;
            int r = f >> 4;
            int c4 = (f & 15) << 2;
            uchar4 u4 = make_uchar4(0,0,0,0);
            if (t0 + r < Tt && s0 + c4 < Tt)
                u4 = *(const uchar4*)(bkb + (size_t)(t0 + r)*Tt + s0 + c4);
            *(uchar4*)(bkt + r*64 + c4) = u4;
        }
        cp_wait<0>();
        __syncthreads();

        // ---- S = Q K^T (3-term split) ----
        float sacc[4][4] = {};
#pragma unroll
        for (int ks = 0; ks < 4; ks++) {
            uint32_t qhf[4], qlf[4];
            uint32_t aoff = swz128((uint32_t)(arow0 << 7) + ((aku0 + (ks << 1)) << 4));
            LDSM4(qhf, sb + SQH + aoff);
            LDSM4(qlf, sb + SQL + aoff);
#pragma unroll
            for (int nt2 = 0; nt2 < 2; nt2++) {
                uint32_t khf[4], klf[4];
                uint32_t boff = swz128((uint32_t)((brow0 + (nt2 << 4)) << 7) + ((bku0 + (ks << 1)) << 4));
                LDSM4(khf, sb + SKH + boff);
                LDSM4(klf, sb + SKL + boff);
#pragma unroll
                for (int hv = 0; hv < 2; hv++) {
                    int nt = nt2*2 + hv;
                    MMA16816(sacc[nt], qhf, khf[hv*2], khf[hv*2+1]);
                    MMA16816(sacc[nt], qhf, klf[hv*2], klf[hv*2+1]);
                    MMA16816(sacc[nt], qlf, khf[hv*2], khf[hv*2+1]);
                }
            }
        }
#pragma unroll
        for (int nt = 0; nt < 4; nt++) {
            int c0 = wn*32 + nt*8 + ((lane & 3) << 1);
            bool oob0 = (s0 + c0 >= Tt), oob1 = (s0 + c0 + 1 >= Tt);
#pragma unroll
            for (int rr = 0; rr < 2; rr++) {
                int r = r0 + rr*8;
                float v0 = sacc[nt][rr*2+0]*0.125f + rpe[bkt[r*64 + c0]];
                float v1 = sacc[nt][rr*2+1]*0.125f + rpe[bkt[r*64 + c0 + 1]];
                if (oob0) v0 = -INFINITY;
                if (oob1) v1 = -INFINITY;
                float2 o; o.x = v0; o.y = v1;
                *(float2*)&Ps[r*66 + c0] = o;
            }
        }
        __syncthreads();

        // ---- fused online softmax + P -> bf16 hi/lo (single pass, paired stores) ----
        {
            int r = tid >> 2, qq = tid & 3;
            int cbase = qq << 4;
            float mx = -INFINITY;
#pragma unroll
            for (int u = 0; u < 16; u++) mx = fmaxf(mx, Ps[r*66 + cbase + u]);
            mx = fmaxf(mx, __shfl_xor_sync(0xffffffffu, mx, 1));
            mx = fmaxf(mx, __shfl_xor_sync(0xffffffffu, mx, 2));
            float m_old = row_m[r];
            float m_new = fmaxf(m_old, mx);
            float ssum = 0.f;
#pragma unroll
            for (int u2 = 0; u2 < 8; u2++) {
                int c = cbase + (u2 << 1);
                float p0 = __expf(Ps[r*66 + c]     - m_new);
                float p1 = __expf(Ps[r*66 + c + 1] - m_new);
                ssum += p0;
                ssum += p1;
                unsigned short h0, l0, h1, l1;
                split_bf16(p0, h0, l0);
                split_bf16(p1, h1, l1);
                uint32_t off = swz128((uint32_t)(r << 7) + (c << 1));
                *(uint32_t*)(smraw + SPH + off) = (uint32_t)h0 | ((uint32_t)h1 << 16);
                *(uint32_t*)(smraw + SPL + off) = (uint32_t)l0 | ((uint32_t)l1 << 16);
            }
            ssum += __shfl_xor_sync(0xffffffffu, ssum, 1);
            ssum += __shfl_xor_sync(0xffffffffu, ssum, 2);
            if (qq == 0) {
                float sc = __expf(m_old - m_new);
                row_sc[r] = sc;
                row_l[r] = row_l[r]*sc + ssum;
                row_m[r] = m_new;
            }
        }
        __syncthreads();

        // ---- O = O*scale + P V ----
        {
            float sc0 = row_sc[r0], sc1 = row_sc[r0 + 8];
#pragma unroll
            for (int nt = 0; nt < 4; nt++) {
                O[nt][0] *= sc0; O[nt][1] *= sc0;
                O[nt][2] *= sc1; O[nt][3] *= sc1;
            }
#pragma unroll
            for (int ks = 0; ks < 4; ks++) {
                uint32_t phf[4], plf[4];
                uint32_t aoff = swz128((uint32_t)(arow0 << 7) + ((aku0 + (ks << 1)) << 4));
                LDSM4(phf, sb + SPH + aoff);
                LDSM4(plf, sb + SPL + aoff);
#pragma unroll
                for (int nt2 = 0; nt2 < 2; nt2++) {
                    uint32_t vhf[4], vlf[4];
                    uint32_t boff = swz128((uint32_t)((brow0 + (nt2 << 4)) << 7) + ((bku0 + (ks << 1)) << 4));
                    LDSM4(vhf, sb + SVH + boff);
                    LDSM4(vlf, sb + SVL + boff);
#pragma unroll
                    for (int hv = 0; hv < 2; hv++) {
                        int nt = nt2*2 + hv;
                        MMA16816(O[nt], phf, vhf[hv*2], vhf[hv*2+1]);
                        MMA16816(O[nt], phf, vlf[hv*2], vlf[hv*2+1]);
                        MMA16816(O[nt], plf, vhf[hv*2], vhf[hv*2+1]);
                    }
                }
            }
        }
    }

    // ---- finalize ----
    {
        float inv0 = 1.0f / row_l[r0];
        float inv1 = 1.0f / row_l[r0 + 8];
        int t_a = t0 + r0, t_b = t_a + 8;
#pragma unroll
        for (int nt = 0; nt < 4; nt++) {
            int c0 = wn*32 + nt*8 + ((lane & 3) << 1);
            if (t_a < Tt) {
                unsigned short h0,l0,h1,l1;
                split_bf16(O[nt][0]*inv0, h0, l0);
                split_bf16(O[nt][1]*inv0, h1, l1);
                size_t idx = ((size_t)(b_*Tt + t_a))*Cc + h*Dd + c0;
                *(uint32_t*)(g_ahi + idx) = (uint32_t)h0 | ((uint32_t)h1 << 16);
                *(uint32_t*)(g_alo + idx) = (uint32_t)l0 | ((uint32_t)l1 << 16);
            }
            if (t_b < Tt) {
                unsigned short h0,l0,h1,l1;
                split_bf16(O[nt][2]*inv1, h0, l0);
                split_bf16(O[nt][3]*inv1, h1, l1);
                size_t idx = ((size_t)(b_*Tt + t_b))*Cc + h*Dd + c0;
                *(uint32_t*)(g_ahi + idx) = (uint32_t)h0 | ((uint32_t)h1 << 16);
                *(uint32_t*)(g_alo + idx) = (uint32_t)l0 | ((uint32_t)l1 << 16);
            }
        }
    }
}

// ---------------- layernorm (optionally emits bf16 split) ----------------
__global__ void __launch_bounds__(256) ln_kernel(const float* __restrict__ in,
    const float* __restrict__ w, const float* __restrict__ b, float* __restrict__ out,
    __nv_bfloat16* __restrict__ shi, __nv_bfloat16* __restrict__ slo)
{
    __shared__ float red[8];
    int row = blockIdx.x;
    const float* x = in + (size_t)row*Cc;
    int tid = threadIdx.x;
    float v0 = x[tid], v1 = x[tid + 256];
    float s = v0 + v1;
#pragma unroll
    for (int o = 16; o > 0; o >>= 1) s += __shfl_xor_sync(0xffffffffu, s, o);
    if ((tid & 31) == 0) red[tid >> 5] = s;
    __syncthreads();
    float tot = red[0]+red[1]+red[2]+red[3]+red[4]+red[5]+red[6]+red[7];
    float mean = tot * (1.0f/512.0f);
    float d0 = v0 - mean, d1 = v1 - mean;
    float s2 = d0*d0 + d1*d1;
#pragma unroll
    for (int o = 16; o > 0; o >>= 1) s2 += __shfl_xor_sync(0xffffffffu, s2, o);
    __syncthreads();
    if ((tid & 31) == 0) red[tid >> 5] = s2;
    __syncthreads();
    float tot2 = red[0]+red[1]+red[2]+red[3]+red[4]+red[5]+red[6]+red[7];
    float inv = rsqrtf(tot2 * (1.0f/512.0f) + 1e-5f);
    float o0 = d0*inv*w[tid]       + b[tid];
    float o1 = d1*inv*w[tid + 256] + b[tid + 256];
    out[(size_t)row*Cc + tid]       = o0;
    out[(size_t)row*Cc + tid + 256] = o1;
    if (shi) {
        unsigned short h0,l0,h1,l1;
        split_bf16(o0, h0, l0); split_bf16(o1, h1, l1);
        shi[(size_t)row*Cc + tid]       = __ushort_as_bfloat16(h0);
        shi[(size_t)row*Cc + tid + 256] = __ushort_as_bfloat16(h1);
        slo[(size_t)row*Cc + tid]       = __ushort_as_bfloat16(l0);
        slo[(size_t)row*Cc + tid + 256] = __ushort_as_bfloat16(l1);
    }
}

// ---------------- launch ----------------
extern "C" void kernel_launch(void* const* d_in, const int* in_sizes, int n_in,
                              void* d_out, int out_size) {
    (void)in_sizes; (void)n_in; (void)out_size;
    const float* x         = (const float*)d_in[0];
    const int*   ct        = (const int*)  d_in[1];
    const float* w_attn    = (const float*)d_in[2];
    const float* b_attn    = (const float*)d_in[3];
    const float* w_proj    = (const float*)d_in[4];
    const float* b_proj    = (const float*)d_in[5];
    const float* rpe_table = (const float*)d_in[6];
    const float* ln1_w     = (const float*)d_in[7];
    const float* ln1_b     = (const float*)d_in[8];
    const float* ln2_w     = (const float*)d_in[9];
    const float* ln2_b     = (const float*)d_in[10];
    const float* w_fc      = (const float*)d_in[11];
    const float* b_fc      = (const float*)d_in[12];
    const float* w_fc2     = (const float*)d_in[13];
    const float* b_fc2     = (const float*)d_in[14];
    float* out = (float*)d_out;

    float *res_, *x1_, *res2_;
    cudaGetSymbolAddress((void**)&res_,  g_res);
    cudaGetSymbolAddress((void**)&x1_,   g_x1);
    cudaGetSymbolAddress((void**)&res2_, g_res2);
    __nv_bfloat16 *ahi, *alo, *bhi, *blo;
    __nv_bfloat16 *wha, *wla, *whp, *wlp, *whf, *wlf, *whf2, *wlf2;
    cudaGetSymbolAddress((void**)&ahi,  g_ahi);
    cudaGetSymbolAddress((void**)&alo,  g_alo);
    cudaGetSymbolAddress((void**)&bhi,  g_bhi);
    cudaGetSymbolAddress((void**)&blo,  g_blo);
    cudaGetSymbolAddress((void**)&wha,  g_wh_attn);
    cudaGetSymbolAddress((void**)&wla,  g_wl_attn);
    cudaGetSymbolAddress((void**)&whp,  g_wh_proj);
    cudaGetSymbolAddress((void**)&wlp,  g_wl_proj);
    cudaGetSymbolAddress((void**)&whf,  g_wh_fc);
    cudaGetSymbolAddress((void**)&wlf,  g_wl_fc);
    cudaGetSymbolAddress((void**)&whf2, g_wh_fc2);
    cudaGetSymbolAddress((void**)&wlf2, g_wl_fc2);

    cudaFuncSetAttribute(attn_mma, cudaFuncAttributeMaxDynamicSharedMemorySize, ASM_TOT);
    cudaFuncSetAttribute(mma_gemm<0>, cudaFuncAttributeMaxDynamicSharedMemorySize, GSM_TOT);
    cudaFuncSetAttribute(mma_gemm<1>, cudaFuncAttributeMaxDynamicSharedMemorySize, GSM_TOT);
    cudaFuncSetAttribute(mma_gemm<2>, cudaFuncAttributeMaxDynamicSharedMemorySize, GSM_TOT);
    cudaFuncSetAttribute(mma_gemm<3>, cudaFuncAttributeMaxDynamicSharedMemorySize, GSM_TOT);

    // fork: side stream does wconv (needed by gemm0) then bucket (needed by attn)
    cudaEventRecord(g_evF, 0);
    cudaStreamWaitEvent(g_side, g_evF, 0);
    wconv_all<<<2048, 256, 0, g_side>>>(w_attn, wha, wla, w_proj, whp, wlp,
                                        w_fc, whf, wlf, w_fc2, whf2, wlf2);
    cudaEventRecord(g_evW, g_side);
    bucket_kernel<<<dim3(Tt, Bb), 128, 0, g_side>>>(ct);
    cudaEventRecord(g_evJ, g_side);

    // main stream: activation split runs concurrently with wconv
    aconv_kernel<<<(Mrows*Cc/4 + 255)/256, 256>>>((const float4*)x, (uint2*)ahi, (uint2*)alo, Mrows*Cc/4);
    cudaStreamWaitEvent(0, g_evW, 0);
    mma_gemm<0><<<dim3(24, 125), 256, GSM_TOT>>>(ahi, alo, wha, wla, b_attn,
                                                 nullptr, nullptr, nullptr, nullptr, Mrows, 3*Cc, Cc);

    // join: attention needs the bucket array
    cudaStreamWaitEvent(0, g_evJ, 0);
    attn_mma<<<dim3(8, Bb*Hh), 256, ASM_TOT>>>(rpe_table);

    // proj + resid -> ln1 (emits x1 split)
    mma_gemm<1><<<dim3(8, 125), 256, GSM_TOT>>>(ahi, alo, whp, wlp, b_proj,
                                                res_, x, nullptr, nullptr, Mrows, Cc, Cc);
    ln_kernel<<<Mrows, 256>>>(res_, ln1_w, ln1_b, x1_, ahi, alo);

    // fc + gelu (emits h split) -> fc2 + resid -> ln2
    mma_gemm<2><<<dim3(16, 125), 256, GSM_TOT>>>(ahi, alo, whf, wlf, b_fc,
                                                 nullptr, nullptr, bhi, blo, Mrows, 2*Cc, Cc);
    mma_gemm<3><<<dim3(8, 125), 256, GSM_TOT>>>(bhi, blo, whf2, wlf2, b_fc2,
                                                res2_, x1_, nullptr, nullptr, Mrows, Cc, 2*Cc);
    ln_kernel<<<Mrows, 256>>>(res2_, ln2_w, ln2_b, out, nullptr, nullptr);
}

// round 14
// speedup vs baseline: 1.5299x; 1.0001x over previous
#include <cuda_runtime.h>
#include <cuda_bf16.h>
#include <math.h>
#include <stdint.h>

#define Bb 32
#define Tt 500
#define Cc 512
#define Hh 8
#define Dd 64
#define Mrows (Bb*Tt)
#define NBUCKETS 49

// ---------------- scratch (static device globals; zero-initialized) ----------------
__device__ float g_res [(size_t)Mrows*Cc];
__device__ float g_x1  [(size_t)Mrows*Cc];
__device__ float g_res2[(size_t)Mrows*Cc];
__device__ unsigned char g_bucket[(size_t)Bb*Tt*Tt + 64];

// bf16 split buffers (padded; pad region stays zero)
__device__ __nv_bfloat16 g_qh[(size_t)(Bb*Hh*Tt + 64)*Dd], g_ql[(size_t)(Bb*Hh*Tt + 64)*Dd];
__device__ __nv_bfloat16 g_kh[(size_t)(Bb*Hh*Tt + 64)*Dd], g_kl[(size_t)(Bb*Hh*Tt + 64)*Dd];
__device__ __nv_bfloat16 g_vth[(size_t)Bb*Hh*Dd*512 + 1024], g_vtl[(size_t)Bb*Hh*Dd*512 + 1024];
__device__ __nv_bfloat16 g_ahi[(size_t)Mrows*1024 + 1024], g_alo[(size_t)Mrows*1024 + 1024];
__device__ __nv_bfloat16 g_bhi[(size_t)Mrows*1024 + 1024], g_blo[(size_t)Mrows*1024 + 1024];
__device__ __nv_bfloat16 g_wh_attn[1536*512], g_wl_attn[1536*512];
__device__ __nv_bfloat16 g_wh_proj[512*512],  g_wl_proj[512*512];
__device__ __nv_bfloat16 g_wh_fc[1024*512],   g_wl_fc[1024*512];
__device__ __nv_bfloat16 g_wh_fc2[512*1024],  g_wl_fc2[512*1024];

// ---------------- side stream + events, created before harness mem checkpoints ----
static cudaStream_t g_side;
static cudaEvent_t g_evF, g_evW, g_evJ;
static struct SideInit {
    SideInit() {
        cudaStreamCreateWithFlags(&g_side, cudaStreamNonBlocking);
        cudaEventCreateWithFlags(&g_evF, cudaEventDisableTiming);
        cudaEventCreateWithFlags(&g_evW, cudaEventDisableTiming);
        cudaEventCreateWithFlags(&g_evJ, cudaEventDisableTiming);
    }
} g_sideInit;

// ---------------- helpers ----------------
__device__ __forceinline__ uint32_t smem_u32(const void* p) {
    uint32_t a;
    asm("{ .reg .u64 t; cvta.to.shared.u64 t, %1; cvt.u32.u64 %0, t; }" : "=r"(a) : "l"(p));
    return a;
}
__device__ __forceinline__ uint32_t swz128(uint32_t o) { return o ^ ((o >> 3) & 0x70); }

__device__ __forceinline__ void cp16(uint32_t dst, const void* src) {
    asm volatile("cp.async.cg.shared.global [%0], [%1], 16;" :: "r"(dst), "l"(src));
}
__device__ __forceinline__ void cp_commit() {
    asm volatile("cp.async.commit_group;" ::: "memory");
}
template<int N> __device__ __forceinline__ void cp_wait() {
    asm volatile("cp.async.wait_group %0;" :: "n"(N) : "memory");
}

#define LDSM4(r, addr) \
    asm volatile("ldmatrix.sync.aligned.m8n8.x4.shared.b16 {%0,%1,%2,%3}, [%4];" \
        : "=r"((r)[0]),"=r"((r)[1]),"=r"((r)[2]),"=r"((r)[3]) : "r"(addr))

#define MMA16816(d, a, b0, b1) \
    asm volatile("mma.sync.aligned.m16n8k16.row.col.f32.bf16.bf16.f32 " \
        "{%0,%1,%2,%3}, {%4,%5,%6,%7}, {%8,%9}, {%0,%1,%2,%3};" \
        : "+f"((d)[0]),"+f"((d)[1]),"+f"((d)[2]),"+f"((d)[3]) \
        : "r"((a)[0]),"r"((a)[1]),"r"((a)[2]),"r"((a)[3]), "r"(b0),"r"(b1))

__device__ __forceinline__ void split_bf16(float v, unsigned short& h, unsigned short& l) {
    __nv_bfloat16 hb = __float2bfloat16(v);
    __nv_bfloat16 lb = __float2bfloat16(v - __bfloat162float(hb));
    h = __bfloat16_as_ushort(hb);
    l = __bfloat16_as_ushort(lb);
}

// ---------------- bucket ids: one block per (t, b), 32-entry rel->bucket table ----
__global__ void __launch_bounds__(128) bucket_kernel(const int* __restrict__ ct) {
    __shared__ unsigned char bres[32];
    const int t = blockIdx.x, b = blockIdx.y;
    if (threadIdx.x < 32) {
        float rel = (float)threadIdx.x;
        float idx;
        if (rel <= 12.0f) idx = rel;
        else idx = fminf(rintf(12.0f + logf(rel * (1.0f/12.0f)) * 5.7707801635558523f), 24.0f);
        bres[threadIdx.x] = (unsigned char)(int)(idx + 24.0f);
    }
    __syncthreads();
    const int j = threadIdx.x;
    if (j >= 125) return;
    const int2 c1 = ((const int2*)ct)[b*Tt + t];
    const int2* cs = ((const int2*)ct) + b*Tt + 4*j;
    uchar4 o;
    unsigned char* po = &o.x;
#pragma unroll
    for (int u = 0; u < 4; u++) {
        int2 c2 = cs[u];
        int dx = c1.x - c2.x, dy = c1.y - c2.y;
        int relI = (int)(sqrtf((float)(dx*dx + dy*dy)) * (1.0f/12.0f));
        po[u] = bres[relI];
    }
    *(uchar4*)(g_bucket + (size_t)b*(Tt*Tt) + (size_t)t*Tt + 4*j) = o;
}

// ---------------- bf16 split conversions ----------------
__global__ void __launch_bounds__(256) aconv_kernel(const float4* __restrict__ in,
    uint2* __restrict__ hi, uint2* __restrict__ lo, int n4)
{
    int i = blockIdx.x * blockDim.x + threadIdx.x;
    if (i >= n4) return;
    float4 f = in[i];
    unsigned short h0,h1,h2,h3,l0,l1,l2,l3;
    split_bf16(f.x, h0, l0); split_bf16(f.y, h1, l1);
    split_bf16(f.z, h2, l2); split_bf16(f.w, h3, l3);
    uint2 ho, lv;
    ho.x = (uint32_t)h0 | ((uint32_t)h1 << 16);
    ho.y = (uint32_t)h2 | ((uint32_t)h3 << 16);
    lv.x = (uint32_t)l0 | ((uint32_t)l1 << 16);
    lv.y = (uint32_t)l2 | ((uint32_t)l3 << 16);
    hi[i] = ho; lo[i] = lv;
}

// all four weights: W [K,N] fp32 -> WT [N,K] bf16 hi/lo, one merged launch
__global__ void __launch_bounds__(256) wconv_all(
    const float* __restrict__ W0, __nv_bfloat16* __restrict__ h0v, __nv_bfloat16* __restrict__ l0v,
    const float* __restrict__ W1, __nv_bfloat16* __restrict__ h1v, __nv_bfloat16* __restrict__ l1v,
    const float* __restrict__ W2, __nv_bfloat16* __restrict__ h2v, __nv_bfloat16* __restrict__ l2v,
    const float* __restrict__ W3, __nv_bfloat16* __restrict__ h3v, __nv_bfloat16* __restrict__ l3v)
{
    __shared__ float tile[32][33];
    int p = blockIdx.x;
    const float* W; __nv_bfloat16 *hi, *lo; int K, N, nb, kb;
    if (p < 768)       { W = W0; hi = h0v; lo = l0v; K = 512;  N = 1536; nb = p % 48;          kb = p / 48; }
    else if (p < 1024) { W = W1; hi = h1v; lo = l1v; K = 512;  N = 512;  nb = (p - 768) & 15;  kb = (p - 768) >> 4; }
    else if (p < 1536) { W = W2; hi = h2v; lo = l2v; K = 512;  N = 1024; nb = (p - 1024) & 31; kb = (p - 1024) >> 5; }
    else               { W = W3; hi = h3v; lo = l3v; K = 1024; N = 512;  nb = (p - 1536) & 15; kb = (p - 1536) >> 4; }
    nb <<= 5; kb <<= 5;
    int tx = threadIdx.x & 31, ty = threadIdx.x >> 5;
#pragma unroll
    for (int it = 0; it < 32; it += 8)
        tile[ty + it][tx] = W[(size_t)(kb + ty + it)*N + nb + tx];
    __syncthreads();
#pragma unroll
    for (int it = 0; it < 32; it += 8) {
        float f = tile[tx][ty + it];
        unsigned short h_, l_;
        split_bf16(f, h_, l_);
        size_t o = (size_t)(nb + ty + it)*K + kb + tx;
        hi[o] = __ushort_as_bfloat16(h_); lo[o] = __ushort_as_bfloat16(l_);
    }
}

// ---- mma.sync GEMM: CTA 128x64, KC=64, split bf16, cp.async 2-stage, 2 CTAs/SM ----
#define TA 16384
#define TB 8192
#define STAGE_B 49152
#define GSM_TOT 98304
template<int MODE>
__global__ void __launch_bounds__(256, 2) mma_gemm(
    const __nv_bfloat16* __restrict__ Ahi, const __nv_bfloat16* __restrict__ Alo,
    const __nv_bfloat16* __restrict__ Bhi, const __nv_bfloat16* __restrict__ Blo,
    const float* __restrict__ bias, float* __restrict__ Cout,
    const float* __restrict__ resid,
    __nv_bfloat16* __restrict__ Shi, __nv_bfloat16* __restrict__ Slo,
    int M, int N, int K)
{
    extern __shared__ char smraw[];
    const uint32_t sb = smem_u32(smraw);
    const int tid = threadIdx.x;
    const int wid = tid >> 5, lane = tid & 31;
    const int wm = wid & 3, wn = wid >> 2;
    const int m0 = blockIdx.y << 7, n0 = blockIdx.x << 6;

    const int ldr = tid >> 3, ldu = tid & 7;

    auto issue = [&](int kc, int buf) {
        uint32_t base = sb + buf*STAGE_B;
#pragma unroll
        for (int p = 0; p < 4; p++) {
            int row = ldr + (p << 5);
            uint32_t d = swz128((uint32_t)(row << 7) + (ldu << 4));
            size_t ao = (size_t)(m0 + row)*K + kc + (ldu << 3);
            cp16(base + d,      Ahi + ao);
            cp16(base + TA + d, Alo + ao);
        }
#pragma unroll
        for (int p = 0; p < 2; p++) {
            int row = ldr + (p << 5);
            uint32_t d = swz128((uint32_t)(row << 7) + (ldu << 4));
            size_t bo = (size_t)(n0 + row)*K + kc + (ldu << 3);
            cp16(base + 2*TA + d,      Bhi + bo);
            cp16(base + 2*TA + TB + d, Blo + bo);
        }
        cp_commit();
    };

    float acc[2][4][4] = {};

    const int grp = lane >> 3, rim = lane & 7;
    const int arow0 = (wm << 5) + ((grp & 1) << 3) + rim;
    const int aku0  = grp >> 1;
    const int brow0 = (wn << 5) + ((grp >> 1) << 3) + rim;
    const int bku0  = grp & 1;

    issue(0, 0);
    const int nch = K >> 6;
    for (int c = 0; c < nch; c++) {
        if (c + 1 < nch) { issue((c + 1) << 6, (c + 1) & 1); cp_wait<1>(); }
        else             { cp_wait<0>(); }
        __syncthreads();
        const uint32_t base = sb + (c & 1)*STAGE_B;
#pragma unroll
        for (int ks = 0; ks < 4; ks++) {
            uint32_t ah[2][4], al[2][4];
#pragma unroll
            for (int mt = 0; mt < 2; mt++) {
                uint32_t off = swz128((uint32_t)((arow0 + (mt << 4)) << 7) + ((aku0 + (ks << 1)) << 4));
                LDSM4(ah[mt], base + off);
                LDSM4(al[mt], base + TA + off);
            }
            uint32_t bh[2][4], bl[2][4];
#pragma unroll
            for (int nt2 = 0; nt2 < 2; nt2++) {
                uint32_t off = swz128((uint32_t)((brow0 + (nt2 << 4)) << 7) + ((bku0 + (ks << 1)) << 4));
                LDSM4(bh[nt2], base + 2*TA + off);
                LDSM4(bl[nt2], base + 2*TA + TB + off);
            }
            // term-major: 8 independent MMAs between successive writes to any acc
#pragma unroll
            for (int mt = 0; mt < 2; mt++)
#pragma unroll
                for (int nt = 0; nt < 4; nt++) {
                    const uint32_t* fh = &bh[nt >> 1][(nt & 1) << 1];
                    MMA16816(acc[mt][nt], ah[mt], fh[0], fh[1]);
                }
#pragma unroll
            for (int mt = 0; mt < 2; mt++)
#pragma unroll
                for (int nt = 0; nt < 4; nt++) {
                    const uint32_t* fl = &bl[nt >> 1][(nt & 1) << 1];
                    MMA16816(acc[mt][nt], ah[mt], fl[0], fl[1]);
                }
#pragma unroll
            for (int mt = 0; mt < 2; mt++)
#pragma unroll
                for (int nt = 0; nt < 4; nt++) {
                    const uint32_t* fh = &bh[nt >> 1][(nt & 1) << 1];
                    MMA16816(acc[mt][nt], al[mt], fh[0], fh[1]);
                }
        }
        __syncthreads();
    }

    // epilogue
#pragma unroll
    for (int mt = 0; mt < 2; mt++) {
#pragma unroll
        for (int half = 0; half < 2; half++) {
            int mrow = m0 + (wm << 5) + (mt << 4) + (half << 3) + (lane >> 2);
            int b_ = mrow / Tt, t = mrow - b_*Tt;
#pragma unroll
            for (int nt = 0; nt < 4; nt++) {
                int cix = n0 + (wn << 5) + (nt << 3) + ((lane & 3) << 1);
                float v0 = acc[mt][nt][half*2 + 0] + bias[cix];
                float v1 = acc[mt][nt][half*2 + 1] + bias[cix + 1];
                if (MODE == 0) {
                    unsigned short h0,l0,h1,l1;
                    split_bf16(v0, h0, l0); split_bf16(v1, h1, l1);
                    int sec = cix >> 9, cc2 = cix & 511, hh = cc2 >> 6, d = cc2 & 63;
                    int bh_ = b_*Hh + hh;
                    if (sec == 2) {
                        size_t r0i = ((size_t)(bh_*Dd + d))*512 + t;
                        size_t r1i = ((size_t)(bh_*Dd + d + 1))*512 + t;
                        g_vth[r0i] = __ushort_as_bfloat16(h0);
                        g_vth[r1i] = __ushort_as_bfloat16(h1);
                        g_vtl[r0i] = __ushort_as_bfloat16(l0);
                        g_vtl[r1i] = __ushort_as_bfloat16(l1);
                    } else {
                        size_t idx = ((size_t)(bh_*Tt + t))*Dd + d;
                        uint32_t ph = (uint32_t)h0 | ((uint32_t)h1 << 16);
                        uint32_t pl = (uint32_t)l0 | ((uint32_t)l1 << 16);
                        if (sec == 0) { *(uint32_t*)(g_qh + idx) = ph; *(uint32_t*)(g_ql + idx) = pl; }
                        else          { *(uint32_t*)(g_kh + idx) = ph; *(uint32_t*)(g_kl + idx) = pl; }
                    }
                } else if (MODE == 2) {
                    v0 = 0.5f * v0 * (1.0f + erff(v0 * 0.7071067811865475f));
                    v1 = 0.5f * v1 * (1.0f + erff(v1 * 0.7071067811865475f));
                    unsigned short h0,l0,h1,l1;
                    split_bf16(v0, h0, l0); split_bf16(v1, h1, l1);
                    size_t idx = (size_t)mrow*N + cix;
                    *(uint32_t*)(Shi + idx) = (uint32_t)h0 | ((uint32_t)h1 << 16);
                    *(uint32_t*)(Slo + idx) = (uint32_t)l0 | ((uint32_t)l1 << 16);
                } else {
                    float2 r = *(const float2*)(resid + (size_t)mrow*N + cix);
                    float2 o; o.x = v0 + r.x; o.y = v1 + r.y;
                    *(float2*)(Cout + (size_t)mrow*N + cix) = o;
                }
            }
        }
    }
}

// ---------------- mma.sync flash attention with RPE bias ----------------
#define SQH 0
#define SQL 8192
#define SKH 16384
#define SKL 24576
#define SVH 32768
#define SVL 40960
#define SPH 49152
#define SPL 57344
#define SPS 65536                    // float Ps[64][66]
#define SBK (SPS + 64*66*4)
#define SRP (SBK + 4096)
#define SRM (SRP + 256)
#define SRL (SRM + 256)
#define SRS (SRL + 256)
#define ASM_TOT (SRS + 256)

__global__ void __launch_bounds__(256) attn_mma(const float* __restrict__ rpe_table) {
    extern __shared__ char smraw[];
    const uint32_t sb = smem_u32(smraw);
    const int tid = threadIdx.x;
    const int wid = tid >> 5, lane = tid & 31;
    const int wm = wid & 3, wn = wid >> 2;
    const int qt = blockIdx.x;
    const int bh = blockIdx.y;
    const int b_ = bh >> 3, h = bh & 7;
    const int hp = bh >> 5, bp = bh & 31;
    const int t0 = qt << 6;

    float* rpe = (float*)(smraw + SRP);
    float* row_m = (float*)(smraw + SRM);
    float* row_l = (float*)(smraw + SRL);
    float* row_sc = (float*)(smraw + SRS);
    float* Ps = (float*)(smraw + SPS);
    unsigned char* bkt = (unsigned char*)(smraw + SBK);

    if (tid < NBUCKETS) rpe[tid] = rpe_table[hp*NBUCKETS + tid];
    if (tid < 64) { row_m[tid] = -INFINITY; row_l[tid] = 0.0f; }

    const int ldr = tid >> 3, ldu = tid & 7;

    {
        const __nv_bfloat16* qh = g_qh + ((size_t)bh*Tt + t0)*Dd;
        const __nv_bfloat16* ql = g_ql + ((size_t)bh*Tt + t0)*Dd;
#pragma unroll
        for (int p = 0; p < 2; p++) {
            int r = ldr + (p << 5);
            uint32_t d = swz128((uint32_t)(r << 7) + (ldu << 4));
            cp16(sb + SQH + d, qh + (size_t)r*Dd + (ldu << 3));
            cp16(sb + SQL + d, ql + (size_t)r*Dd + (ldu << 3));
        }
        cp_commit();
    }

    const int grp = lane >> 3, rim = lane & 7;
    const int arow0 = (wm << 4) + ((grp & 1) << 3) + rim;
    const int aku0  = grp >> 1;
    const int brow0 = (wn << 5) + ((grp >> 1) << 3) + rim;
    const int bku0  = grp & 1;

    float O[4][4] = {};
    const unsigned char* bkb = g_bucket + (size_t)bp*Tt*Tt;
    const int r0 = wm*16 + (lane >> 2);

    for (int s0 = 0; s0 < Tt; s0 += 64) {
        __syncthreads();
        {
            const __nv_bfloat16* kh = g_kh + ((size_t)bh*Tt + s0)*Dd;
            const __nv_bfloat16* kl = g_kl + ((size_t)bh*Tt + s0)*Dd;
            const __nv_bfloat16* vh = g_vth + (size_t)bh*Dd*512 + s0;
            const __nv_bfloat16* vl = g_vtl + (size_t)bh*Dd*512 + s0;
#pragma unroll
            for (int p = 0; p < 2; p++) {
                int r = ldr + (p << 5);
                uint32_t d = swz128((uint32_t)(r << 7) + (ldu << 4));
                cp16(sb + SKH + d, kh + (size_t)r*Dd + (ldu << 3));
                cp16(sb + SKL + d, kl + (size_t)r*Dd + (ldu << 3));
                cp16(sb + SVH + d, vh + (size_t)r*512 + (ldu << 3));
                cp16(sb + SVL + d, vl + (size_t)r*512 + (ldu << 3));
            }
            cp_commit();
        }
#pragma unroll
        for (int it = 0; it < 4; it++) {
            int f = tid + it*256;
            int r = f >> 4;
            int c4 = (f & 15) << 2;
            uchar4 u4 = make_uchar4(0,0,0,0);
            if (t0 + r < Tt && s0 + c4 < Tt)
                u4 = *(const uchar4*)(bkb + (size_t)(t0 + r)*Tt + s0 + c4);
            *(uchar4*)(bkt + r*64 + c4) = u4;
        }
        cp_wait<0>();
        __syncthreads();

        // ---- S = Q K^T (3-term split, term-major issue) ----
        float sacc[4][4] = {};
#pragma unroll
        for (int ks = 0; ks < 4; ks++) {
            uint32_t qhf[4], qlf[4];
            uint32_t aoff = swz128((uint32_t)(arow0 << 7) + ((aku0 + (ks << 1)) << 4));
            LDSM4(qhf, sb + SQH + aoff);
            LDSM4(qlf, sb + SQL + aoff);
            uint32_t khf[2][4], klf[2][4];
#pragma unroll
            for (int nt2 = 0; nt2 < 2; nt2++) {
                uint32_t boff = swz128((uint32_t)((brow0 + (nt2 << 4)) << 7) + ((bku0 + (ks << 1)) << 4));
                LDSM4(khf[nt2], sb + SKH + boff);
                LDSM4(klf[nt2], sb + SKL + boff);
            }
#pragma unroll
            for (int nt = 0; nt < 4; nt++)
                MMA16816(sacc[nt], qhf, khf[nt >> 1][(nt & 1)*2], khf[nt >> 1][(nt & 1)*2 + 1]);
#pragma unroll
            for (int nt = 0; nt < 4; nt++)
                MMA16816(sacc[nt], qhf, klf[nt >> 1][(nt & 1)*2], klf[nt >> 1][(nt & 1)*2 + 1]);
#pragma unroll
            for (int nt = 0; nt < 4; nt++)
                MMA16816(sacc[nt], qlf, khf[nt >> 1][(nt & 1)*2], khf[nt >> 1][(nt & 1)*2 + 1]);
        }
#pragma unroll
        for (int nt = 0; nt < 4; nt++) {
            int c0 = wn*32 + nt*8 + ((lane & 3) << 1);
            bool oob0 = (s0 + c0 >= Tt), oob1 = (s0 + c0 + 1 >= Tt);
#pragma unroll
            for (int rr = 0; rr < 2; rr++) {
                int r = r0 + rr*8;
                float v0 = sacc[nt][rr*2+0]*0.125f + rpe[bkt[r*64 + c0]];
                float v1 = sacc[nt][rr*2+1]*0.125f + rpe[bkt[r*64 + c0 + 1]];
                if (oob0) v0 = -INFINITY;
                if (oob1) v1 = -INFINITY;
                float2 o; o.x = v0; o.y = v1;
                *(float2*)&Ps[r*66 + c0] = o;
            }
        }
        __syncthreads();

        // ---- fused online softmax + P -> bf16 hi/lo ----
        {
            int r = tid >> 2, qq = tid & 3;
            int cbase = qq << 4;
            float mx = -INFINITY;
#pragma unroll
            for (int u = 0; u < 16; u++) mx = fmaxf(mx, Ps[r*66 + cbase + u]);
            mx = fmaxf(mx, __shfl_xor_sync(0xffffffffu, mx, 1));
            mx = fmaxf(mx, __shfl_xor_sync(0xffffffffu, mx, 2));
            float m_old = row_m[r];
            float m_new = fmaxf(m_old, mx);
            float ssum = 0.f;
#pragma unroll
            for (int u2 = 0; u2 < 8; u2++) {
                int c = cbase + (u2 << 1);
                float p0 = __expf(Ps[r*66 + c]     - m_new);
                float p1 = __expf(Ps[r*66 + c + 1] - m_new);
                ssum += p0;
                ssum += p1;
                unsigned short h0, l0, h1, l1;
                split_bf16(p0, h0, l0);
                split_bf16(p1, h1, l1);
                uint32_t off = swz128((uint32_t)(r << 7) + (c << 1));
                *(uint32_t*)(smraw + SPH + off) = (uint32_t)h0 | ((uint32_t)h1 << 16);
                *(uint32_t*)(smraw + SPL + off) = (uint32_t)l0 | ((uint32_t)l1 << 16);
            }
            ssum += __shfl_xor_sync(0xffffffffu, ssum, 1);
            ssum += __shfl_xor_sync(0xffffffffu, ssum, 2);
            if (qq == 0) {
                float sc = __expf(m_old - m_new);
                row_sc[r] = sc;
                row_l[r] = row_l[r]*sc + ssum;
                row_m[r] = m_new;
            }
        }
        __syncthreads();

        // ---- O = O*scale + P V (term-major issue) ----
        {
            float sc0 = row_sc[r0], sc1 = row_sc[r0 + 8];
#pragma unroll
            for (int nt = 0; nt < 4; nt++) {
                O[nt][0] *= sc0; O[nt][1] *= sc0;
                O[nt][2] *= sc1; O[nt][3] *= sc1;
            }
#pragma unroll
            for (int ks = 0; ks < 4; ks++) {
                uint32_t phf[4], plf[4];
                uint32_t aoff = swz128((uint32_t)(arow0 << 7) + ((aku0 + (ks << 1)) << 4));
                LDSM4(phf, sb + SPH + aoff);
                LDSM4(plf, sb + SPL + aoff);
                uint32_t vhf[2][4], vlf[2][4];
#pragma unroll
                for (int nt2 = 0; nt2 < 2; nt2++) {
                    uint32_t boff = swz128((uint32_t)((brow0 + (nt2 << 4)) << 7) + ((bku0 + (ks << 1)) << 4));
                    LDSM4(vhf[nt2], sb + SVH + boff);
                    LDSM4(vlf[nt2], sb + SVL + boff);
                }
#pragma unroll
                for (int nt = 0; nt < 4; nt++)
                    MMA16816(O[nt], phf, vhf[nt >> 1][(nt & 1)*2], vhf[nt >> 1][(nt & 1)*2 + 1]);
#pragma unroll
                for (int nt = 0; nt < 4; nt++)
                    MMA16816(O[nt], phf, vlf[nt >> 1][(nt & 1)*2], vlf[nt >> 1][(nt & 1)*2 + 1]);
#pragma unroll
                for (int nt = 0; nt < 4; nt++)
                    MMA16816(O[nt], plf, vhf[nt >> 1][(nt & 1)*2], vhf[nt >> 1][(nt & 1)*2 + 1]);
            }
        }
    }

    // ---- finalize ----
    {
        float inv0 = 1.0f / row_l[r0];
        float inv1 = 1.0f / row_l[r0 + 8];
        int t_a = t0 + r0, t_b = t_a + 8;
#pragma unroll
        for (int nt = 0; nt < 4; nt++) {
            int c0 = wn*32 + nt*8 + ((lane & 3) << 1);
            if (t_a < Tt) {
                unsigned short h0,l0,h1,l1;
                split_bf16(O[nt][0]*inv0, h0, l0);
                split_bf16(O[nt][1]*inv0, h1, l1);
                size_t idx = ((size_t)(b_*Tt + t_a))*Cc + h*Dd + c0;
                *(uint32_t*)(g_ahi + idx) = (uint32_t)h0 | ((uint32_t)h1 << 16);
                *(uint32_t*)(g_alo + idx) = (uint32_t)l0 | ((uint32_t)l1 << 16);
            }
            if (t_b < Tt) {
                unsigned short h0,l0,h1,l1;
                split_bf16(O[nt][2]*inv1, h0, l0);
                split_bf16(O[nt][3]*inv1, h1, l1);
                size_t idx = ((size_t)(b_*Tt + t_b))*Cc + h*Dd + c0;
                *(uint32_t*)(g_ahi + idx) = (uint32_t)h0 | ((uint32_t)h1 << 16);
                *(uint32_t*)(g_alo + idx) = (uint32_t)l0 | ((uint32_t)l1 << 16);
            }
        }
    }
}

// ---------------- layernorm (optionally emits bf16 split) ----------------
__global__ void __launch_bounds__(256) ln_kernel(const float* __restrict__ in,
    const float* __restrict__ w, const float* __restrict__ b, float* __restrict__ out,
    __nv_bfloat16* __restrict__ shi, __nv_bfloat16* __restrict__ slo)
{
    __shared__ float red[8];
    int row = blockIdx.x;
    const float* x = in + (size_t)row*Cc;
    int tid = threadIdx.x;
    float v0 = x[tid], v1 = x[tid + 256];
    float s = v0 + v1;
#pragma unroll
    for (int o = 16; o > 0; o >>= 1) s += __shfl_xor_sync(0xffffffffu, s, o);
    if ((tid & 31) == 0) red[tid >> 5] = s;
    __syncthreads();
    float tot = red[0]+red[1]+red[2]+red[3]+red[4]+red[5]+red[6]+red[7];
    float mean = tot * (1.0f/512.0f);
    float d0 = v0 - mean, d1 = v1 - mean;
    float s2 = d0*d0 + d1*d1;
#pragma unroll
    for (int o = 16; o > 0; o >>= 1) s2 += __shfl_xor_sync(0xffffffffu, s2, o);
    __syncthreads();
    if ((tid & 31) == 0) red[tid >> 5] = s2;
    __syncthreads();
    float tot2 = red[0]+red[1]+red[2]+red[3]+red[4]+red[5]+red[6]+red[7];
    float inv = rsqrtf(tot2 * (1.0f/512.0f) + 1e-5f);
    float o0 = d0*inv*w[tid]       + b[tid];
    float o1 = d1*inv*w[tid + 256] + b[tid + 256];
    out[(size_t)row*Cc + tid]       = o0;
    out[(size_t)row*Cc + tid + 256] = o1;
    if (shi) {
        unsigned short h0,l0,h1,l1;
        split_bf16(o0, h0, l0); split_bf16(o1, h1, l1);
        shi[(size_t)row*Cc + tid]       = __ushort_as_bfloat16(h0);
        shi[(size_t)row*Cc + tid + 256] = __ushort_as_bfloat16(h1);
        slo[(size_t)row*Cc + tid]       = __ushort_as_bfloat16(l0);
        slo[(size_t)row*Cc + tid + 256] = __ushort_as_bfloat16(l1);
    }
}

// ---------------- launch ----------------
extern "C" void kernel_launch(void* const* d_in, const int* in_sizes, int n_in,
                              void* d_out, int out_size) {
    (void)in_sizes; (void)n_in; (void)out_size;
    const float* x         = (const float*)d_in[0];
    const int*   ct        = (const int*)  d_in[1];
    const float* w_attn    = (const float*)d_in[2];
    const float* b_attn    = (const float*)d_in[3];
    const float* w_proj    = (const float*)d_in[4];
    const float* b_proj    = (const float*)d_in[5];
    const float* rpe_table = (const float*)d_in[6];
    const float* ln1_w     = (const float*)d_in[7];
    const float* ln1_b     = (const float*)d_in[8];
    const float* ln2_w     = (const float*)d_in[9];
    const float* ln2_b     = (const float*)d_in[10];
    const float* w_fc      = (const float*)d_in[11];
    const float* b_fc      = (const float*)d_in[12];
    const float* w_fc2     = (const float*)d_in[13];
    const float* b_fc2     = (const float*)d_in[14];
    float* out = (float*)d_out;

    float *res_, *x1_, *res2_;
    cudaGetSymbolAddress((void**)&res_,  g_res);
    cudaGetSymbolAddress((void**)&x1_,   g_x1);
    cudaGetSymbolAddress((void**)&res2_, g_res2);
    __nv_bfloat16 *ahi, *alo, *bhi, *blo;
    __nv_bfloat16 *wha, *wla, *whp, *wlp, *whf, *wlf, *whf2, *wlf2;
    cudaGetSymbolAddress((void**)&ahi,  g_ahi);
    cudaGetSymbolAddress((void**)&alo,  g_alo);
    cudaGetSymbolAddress((void**)&bhi,  g_bhi);
    cudaGetSymbolAddress((void**)&blo,  g_blo);
    cudaGetSymbolAddress((void**)&wha,  g_wh_attn);
    cudaGetSymbolAddress((void**)&wla,  g_wl_attn);
    cudaGetSymbolAddress((void**)&whp,  g_wh_proj);
    cudaGetSymbolAddress((void**)&wlp,  g_wl_proj);
    cudaGetSymbolAddress((void**)&whf,  g_wh_fc);
    cudaGetSymbolAddress((void**)&wlf,  g_wl_fc);
    cudaGetSymbolAddress((void**)&whf2, g_wh_fc2);
    cudaGetSymbolAddress((void**)&wlf2, g_wl_fc2);

    cudaFuncSetAttribute(attn_mma, cudaFuncAttributeMaxDynamicSharedMemorySize, ASM_TOT);
    cudaFuncSetAttribute(mma_gemm<0>, cudaFuncAttributeMaxDynamicSharedMemorySize, GSM_TOT);
    cudaFuncSetAttribute(mma_gemm<1>, cudaFuncAttributeMaxDynamicSharedMemorySize, GSM_TOT);
    cudaFuncSetAttribute(mma_gemm<2>, cudaFuncAttributeMaxDynamicSharedMemorySize, GSM_TOT);
    cudaFuncSetAttribute(mma_gemm<3>, cudaFuncAttributeMaxDynamicSharedMemorySize, GSM_TOT);

    // fork: side stream does wconv (needed by gemm0) then bucket (needed by attn)
    cudaEventRecord(g_evF, 0);
    cudaStreamWaitEvent(g_side, g_evF, 0);
    wconv_all<<<2048, 256, 0, g_side>>>(w_attn, wha, wla, w_proj, whp, wlp,
                                        w_fc, whf, wlf, w_fc2, whf2, wlf2);
    cudaEventRecord(g_evW, g_side);
    bucket_kernel<<<dim3(Tt, Bb), 128, 0, g_side>>>(ct);
    cudaEventRecord(g_evJ, g_side);

    // main stream: activation split runs concurrently with wconv
    aconv_kernel<<<(Mrows*Cc/4 + 255)/256, 256>>>((const float4*)x, (uint2*)ahi, (uint2*)alo, Mrows*Cc/4);
    cudaStreamWaitEvent(0, g_evW, 0);
    mma_gemm<0><<<dim3(24, 125), 256, GSM_TOT>>>(ahi, alo, wha, wla, b_attn,
                                                 nullptr, nullptr, nullptr, nullptr, Mrows, 3*Cc, Cc);

    // join: attention needs the bucket array
    cudaStreamWaitEvent(0, g_evJ, 0);
    attn_mma<<<dim3(8, Bb*Hh), 256, ASM_TOT>>>(rpe_table);

    // proj + resid -> ln1 (emits x1 split)
    mma_gemm<1><<<dim3(8, 125), 256, GSM_TOT>>>(ahi, alo, whp, wlp, b_proj,
                                                res_, x, nullptr, nullptr, Mrows, Cc, Cc);
    ln_kernel<<<Mrows, 256>>>(res_, ln1_w, ln1_b, x1_, ahi, alo);

    // fc + gelu (emits h split) -> fc2 + resid -> ln2
    mma_gemm<2><<<dim3(16, 125), 256, GSM_TOT>>>(ahi, alo, whf, wlf, b_fc,
                                                 nullptr, nullptr, bhi, blo, Mrows, 2*Cc, Cc);
    mma_gemm<3><<<dim3(8, 125), 256, GSM_TOT>>>(bhi, blo, whf2, wlf2, b_fc2,
                                                res2_, x1_, nullptr, nullptr, Mrows, Cc, 2*Cc);
    ln_kernel<<<Mrows, 256>>>(res2_, ln2_w, ln2_b, out, nullptr, nullptr);
}

// round 15
// speedup vs baseline: 1.5872x; 1.0375x over previous
#include <cuda_runtime.h>
#include <cuda_bf16.h>
#include <math.h>
#include <stdint.h>

#define Bb 32
#define Tt 500
#define Cc 512
#define Hh 8
#define Dd 64
#define Mrows (Bb*Tt)
#define NBUCKETS 49
#define TILES_A 62
#define TILES_B 63
#define ROWS_A (TILES_A*128)

// ---------------- scratch (static device globals; zero-initialized) ----------------
__device__ float g_res [(size_t)Mrows*Cc];
__device__ float g_x1  [(size_t)Mrows*Cc];
__device__ float g_res2[(size_t)Mrows*Cc];
__device__ unsigned char g_bucket[(size_t)Bb*Tt*Tt + 64];

// bf16 split buffers (padded; pad region stays zero)
__device__ __nv_bfloat16 g_qh[(size_t)(Bb*Hh*Tt + 64)*Dd], g_ql[(size_t)(Bb*Hh*Tt + 64)*Dd];
__device__ __nv_bfloat16 g_kh[(size_t)(Bb*Hh*Tt + 64)*Dd], g_kl[(size_t)(Bb*Hh*Tt + 64)*Dd];
__device__ __nv_bfloat16 g_vth[(size_t)Bb*Hh*Dd*512 + 1024], g_vtl[(size_t)Bb*Hh*Dd*512 + 1024];
__device__ __nv_bfloat16 g_ahi[(size_t)Mrows*1024 + 1024], g_alo[(size_t)Mrows*1024 + 1024];
__device__ __nv_bfloat16 g_bhi[(size_t)Mrows*1024 + 1024], g_blo[(size_t)Mrows*1024 + 1024];
__device__ __nv_bfloat16 g_wh_attn[1536*512], g_wl_attn[1536*512];
__device__ __nv_bfloat16 g_wh_proj[512*512],  g_wl_proj[512*512];
__device__ __nv_bfloat16 g_wh_fc[1024*512],   g_wl_fc[1024*512];
__device__ __nv_bfloat16 g_wh_fc2[512*1024],  g_wl_fc2[512*1024];

// ---------------- side stream + events, created before harness mem checkpoints ----
static cudaStream_t g_side;
static cudaEvent_t g_evF, g_evW, g_evJ, g_evG0, g_evAA, g_evB;
static struct SideInit {
    SideInit() {
        cudaStreamCreateWithFlags(&g_side, cudaStreamNonBlocking);
        cudaEventCreateWithFlags(&g_evF,  cudaEventDisableTiming);
        cudaEventCreateWithFlags(&g_evW,  cudaEventDisableTiming);
        cudaEventCreateWithFlags(&g_evJ,  cudaEventDisableTiming);
        cudaEventCreateWithFlags(&g_evG0, cudaEventDisableTiming);
        cudaEventCreateWithFlags(&g_evAA, cudaEventDisableTiming);
        cudaEventCreateWithFlags(&g_evB,  cudaEventDisableTiming);
    }
} g_sideInit;

// ---------------- helpers ----------------
__device__ __forceinline__ uint32_t smem_u32(const void* p) {
    uint32_t a;
    asm("{ .reg .u64 t; cvta.to.shared.u64 t, %1; cvt.u32.u64 %0, t; }" : "=r"(a) : "l"(p));
    return a;
}
__device__ __forceinline__ uint32_t swz128(uint32_t o) { return o ^ ((o >> 3) & 0x70); }

__device__ __forceinline__ void cp16(uint32_t dst, const void* src) {
    asm volatile("cp.async.cg.shared.global [%0], [%1], 16;" :: "r"(dst), "l"(src));
}
__device__ __forceinline__ void cp_commit() {
    asm volatile("cp.async.commit_group;" ::: "memory");
}
template<int N> __device__ __forceinline__ void cp_wait() {
    asm volatile("cp.async.wait_group %0;" :: "n"(N) : "memory");
}

#define LDSM4(r, addr) \
    asm volatile("ldmatrix.sync.aligned.m8n8.x4.shared.b16 {%0,%1,%2,%3}, [%4];" \
        : "=r"((r)[0]),"=r"((r)[1]),"=r"((r)[2]),"=r"((r)[3]) : "r"(addr))

#define MMA16816(d, a, b0, b1) \
    asm volatile("mma.sync.aligned.m16n8k16.row.col.f32.bf16.bf16.f32 " \
        "{%0,%1,%2,%3}, {%4,%5,%6,%7}, {%8,%9}, {%0,%1,%2,%3};" \
        : "+f"((d)[0]),"+f"((d)[1]),"+f"((d)[2]),"+f"((d)[3]) \
        : "r"((a)[0]),"r"((a)[1]),"r"((a)[2]),"r"((a)[3]), "r"(b0),"r"(b1))

__device__ __forceinline__ void split_bf16(float v, unsigned short& h, unsigned short& l) {
    __nv_bfloat16 hb = __float2bfloat16(v);
    __nv_bfloat16 lb = __float2bfloat16(v - __bfloat162float(hb));
    h = __bfloat16_as_ushort(hb);
    l = __bfloat16_as_ushort(lb);
}

// ---------------- bucket ids ----------------
__global__ void __launch_bounds__(128) bucket_kernel(const int* __restrict__ ct) {
    __shared__ unsigned char bres[32];
    const int t = blockIdx.x, b = blockIdx.y;
    if (threadIdx.x < 32) {
        float rel = (float)threadIdx.x;
        float idx;
        if (rel <= 12.0f) idx = rel;
        else idx = fminf(rintf(12.0f + logf(rel * (1.0f/12.0f)) * 5.7707801635558523f), 24.0f);
        bres[threadIdx.x] = (unsigned char)(int)(idx + 24.0f);
    }
    __syncthreads();
    const int j = threadIdx.x;
    if (j >= 125) return;
    const int2 c1 = ((const int2*)ct)[b*Tt + t];
    const int2* cs = ((const int2*)ct) + b*Tt + 4*j;
    uchar4 o;
    unsigned char* po = &o.x;
#pragma unroll
    for (int u = 0; u < 4; u++) {
        int2 c2 = cs[u];
        int dx = c1.x - c2.x, dy = c1.y - c2.y;
        int relI = (int)(sqrtf((float)(dx*dx + dy*dy)) * (1.0f/12.0f));
        po[u] = bres[relI];
    }
    *(uchar4*)(g_bucket + (size_t)b*(Tt*Tt) + (size_t)t*Tt + 4*j) = o;
}

// ---------------- bf16 split conversions ----------------
__global__ void __launch_bounds__(256) aconv_kernel(const float4* __restrict__ in,
    uint2* __restrict__ hi, uint2* __restrict__ lo, int n4)
{
    int i = blockIdx.x * blockDim.x + threadIdx.x;
    if (i >= n4) return;
    float4 f = in[i];
    unsigned short h0,h1,h2,h3,l0,l1,l2,l3;
    split_bf16(f.x, h0, l0); split_bf16(f.y, h1, l1);
    split_bf16(f.z, h2, l2); split_bf16(f.w, h3, l3);
    uint2 ho, lv;
    ho.x = (uint32_t)h0 | ((uint32_t)h1 << 16);
    ho.y = (uint32_t)h2 | ((uint32_t)h3 << 16);
    lv.x = (uint32_t)l0 | ((uint32_t)l1 << 16);
    lv.y = (uint32_t)l2 | ((uint32_t)l3 << 16);
    hi[i] = ho; lo[i] = lv;
}

// all four weights: W [K,N] fp32 -> WT [N,K] bf16 hi/lo, one merged launch
__global__ void __launch_bounds__(256) wconv_all(
    const float* __restrict__ W0, __nv_bfloat16* __restrict__ h0v, __nv_bfloat16* __restrict__ l0v,
    const float* __restrict__ W1, __nv_bfloat16* __restrict__ h1v, __nv_bfloat16* __restrict__ l1v,
    const float* __restrict__ W2, __nv_bfloat16* __restrict__ h2v, __nv_bfloat16* __restrict__ l2v,
    const float* __restrict__ W3, __nv_bfloat16* __restrict__ h3v, __nv_bfloat16* __restrict__ l3v)
{
    __shared__ float tile[32][33];
    int p = blockIdx.x;
    const float* W; __nv_bfloat16 *hi, *lo; int K, N, nb, kb;
    if (p < 768)       { W = W0; hi = h0v; lo = l0v; K = 512;  N = 1536; nb = p % 48;          kb = p / 48; }
    else if (p < 1024) { W = W1; hi = h1v; lo = l1v; K = 512;  N = 512;  nb = (p - 768) & 15;  kb = (p - 768) >> 4; }
    else if (p < 1536) { W = W2; hi = h2v; lo = l2v; K = 512;  N = 1024; nb = (p - 1024) & 31; kb = (p - 1024) >> 5; }
    else               { W = W3; hi = h3v; lo = l3v; K = 1024; N = 512;  nb = (p - 1536) & 15; kb = (p - 1536) >> 4; }
    nb <<= 5; kb <<= 5;
    int tx = threadIdx.x & 31, ty = threadIdx.x >> 5;
#pragma unroll
    for (int it = 0; it < 32; it += 8)
        tile[ty + it][tx] = W[(size_t)(kb + ty + it)*N + nb + tx];
    __syncthreads();
#pragma unroll
    for (int it = 0; it < 32; it += 8) {
        float f = tile[tx][ty + it];
        unsigned short h_, l_;
        split_bf16(f, h_, l_);
        size_t o = (size_t)(nb + ty + it)*K + kb + tx;
        hi[o] = __ushort_as_bfloat16(h_); lo[o] = __ushort_as_bfloat16(l_);
    }
}

// ---- mma.sync GEMM: CTA 128x64, KC=64, split bf16, cp.async 2-stage, 2 CTAs/SM ----
#define TA 16384
#define TB 8192
#define STAGE_B 49152
#define GSM_TOT 98304
template<int MODE>
__global__ void __launch_bounds__(256, 2) mma_gemm(
    const __nv_bfloat16* __restrict__ Ahi, const __nv_bfloat16* __restrict__ Alo,
    const __nv_bfloat16* __restrict__ Bhi, const __nv_bfloat16* __restrict__ Blo,
    const float* __restrict__ bias, float* __restrict__ Cout,
    const float* __restrict__ resid,
    __nv_bfloat16* __restrict__ Shi, __nv_bfloat16* __restrict__ Slo,
    int M, int N, int K, int tile_off)
{
    extern __shared__ char smraw[];
    const uint32_t sb = smem_u32(smraw);
    const int tid = threadIdx.x;
    const int wid = tid >> 5, lane = tid & 31;
    const int wm = wid & 3, wn = wid >> 2;
    const int m0 = (blockIdx.y + tile_off) << 7, n0 = blockIdx.x << 6;

    const int ldr = tid >> 3, ldu = tid & 7;

    auto issue = [&](int kc, int buf) {
        uint32_t base = sb + buf*STAGE_B;
#pragma unroll
        for (int p = 0; p < 4; p++) {
            int row = ldr + (p << 5);
            uint32_t d = swz128((uint32_t)(row << 7) + (ldu << 4));
            size_t ao = (size_t)(m0 + row)*K + kc + (ldu << 3);
            cp16(base + d,      Ahi + ao);
            cp16(base + TA + d, Alo + ao);
        }
#pragma unroll
        for (int p = 0; p < 2; p++) {
            int row = ldr + (p << 5);
            uint32_t d = swz128((uint32_t)(row << 7) + (ldu << 4));
            size_t bo = (size_t)(n0 + row)*K + kc + (ldu << 3);
            cp16(base + 2*TA + d,      Bhi + bo);
            cp16(base + 2*TA + TB + d, Blo + bo);
        }
        cp_commit();
    };

    float acc[2][4][4] = {};

    const int grp = lane >> 3, rim = lane & 7;
    const int arow0 = (wm << 5) + ((grp & 1) << 3) + rim;
    const int aku0  = grp >> 1;
    const int brow0 = (wn << 5) + ((grp >> 1) << 3) + rim;
    const int bku0  = grp & 1;

    issue(0, 0);
    const int nch = K >> 6;
    for (int c = 0; c < nch; c++) {
        if (c + 1 < nch) { issue((c + 1) << 6, (c + 1) & 1); cp_wait<1>(); }
        else             { cp_wait<0>(); }
        __syncthreads();
        const uint32_t base = sb + (c & 1)*STAGE_B;
#pragma unroll
        for (int ks = 0; ks < 4; ks++) {
            uint32_t ah[2][4], al[2][4];
#pragma unroll
            for (int mt = 0; mt < 2; mt++) {
                uint32_t off = swz128((uint32_t)((arow0 + (mt << 4)) << 7) + ((aku0 + (ks << 1)) << 4));
                LDSM4(ah[mt], base + off);
                LDSM4(al[mt], base + TA + off);
            }
            uint32_t bh[2][4], bl[2][4];
#pragma unroll
            for (int nt2 = 0; nt2 < 2; nt2++) {
                uint32_t off = swz128((uint32_t)((brow0 + (nt2 << 4)) << 7) + ((bku0 + (ks << 1)) << 4));
                LDSM4(bh[nt2], base + 2*TA + off);
                LDSM4(bl[nt2], base + 2*TA + TB + off);
            }
#pragma unroll
            for (int mt = 0; mt < 2; mt++)
#pragma unroll
                for (int nt = 0; nt < 4; nt++) {
                    const uint32_t* fh = &bh[nt >> 1][(nt & 1) << 1];
                    MMA16816(acc[mt][nt], ah[mt], fh[0], fh[1]);
                }
#pragma unroll
            for (int mt = 0; mt < 2; mt++)
#pragma unroll
                for (int nt = 0; nt < 4; nt++) {
                    const uint32_t* fl = &bl[nt >> 1][(nt & 1) << 1];
                    MMA16816(acc[mt][nt], ah[mt], fl[0], fl[1]);
                }
#pragma unroll
            for (int mt = 0; mt < 2; mt++)
#pragma unroll
                for (int nt = 0; nt < 4; nt++) {
                    const uint32_t* fh = &bh[nt >> 1][(nt & 1) << 1];
                    MMA16816(acc[mt][nt], al[mt], fh[0], fh[1]);
                }
        }
        __syncthreads();
    }

    // epilogue
#pragma unroll
    for (int mt = 0; mt < 2; mt++) {
#pragma unroll
        for (int half = 0; half < 2; half++) {
            int mrow = m0 + (wm << 5) + (mt << 4) + (half << 3) + (lane >> 2);
            int b_ = mrow / Tt, t = mrow - b_*Tt;
#pragma unroll
            for (int nt = 0; nt < 4; nt++) {
                int cix = n0 + (wn << 5) + (nt << 3) + ((lane & 3) << 1);
                float v0 = acc[mt][nt][half*2 + 0] + bias[cix];
                float v1 = acc[mt][nt][half*2 + 1] + bias[cix + 1];
                if (MODE == 0) {
                    unsigned short h0,l0,h1,l1;
                    split_bf16(v0, h0, l0); split_bf16(v1, h1, l1);
                    int sec = cix >> 9, cc2 = cix & 511, hh = cc2 >> 6, d = cc2 & 63;
                    int bh_ = b_*Hh + hh;
                    if (sec == 2) {
                        size_t r0i = ((size_t)(bh_*Dd + d))*512 + t;
                        size_t r1i = ((size_t)(bh_*Dd + d + 1))*512 + t;
                        g_vth[r0i] = __ushort_as_bfloat16(h0);
                        g_vth[r1i] = __ushort_as_bfloat16(h1);
                        g_vtl[r0i] = __ushort_as_bfloat16(l0);
                        g_vtl[r1i] = __ushort_as_bfloat16(l1);
                    } else {
                        size_t idx = ((size_t)(bh_*Tt + t))*Dd + d;
                        uint32_t ph = (uint32_t)h0 | ((uint32_t)h1 << 16);
                        uint32_t pl = (uint32_t)l0 | ((uint32_t)l1 << 16);
                        if (sec == 0) { *(uint32_t*)(g_qh + idx) = ph; *(uint32_t*)(g_ql + idx) = pl; }
                        else          { *(uint32_t*)(g_kh + idx) = ph; *(uint32_t*)(g_kl + idx) = pl; }
                    }
                } else if (MODE == 2) {
                    v0 = 0.5f * v0 * (1.0f + erff(v0 * 0.7071067811865475f));
                    v1 = 0.5f * v1 * (1.0f + erff(v1 * 0.7071067811865475f));
                    unsigned short h0,l0,h1,l1;
                    split_bf16(v0, h0, l0); split_bf16(v1, h1, l1);
                    size_t idx = (size_t)mrow*N + cix;
                    *(uint32_t*)(Shi + idx) = (uint32_t)h0 | ((uint32_t)h1 << 16);
                    *(uint32_t*)(Slo + idx) = (uint32_t)l0 | ((uint32_t)l1 << 16);
                } else {
                    float2 r = *(const float2*)(resid + (size_t)mrow*N + cix);
                    float2 o; o.x = v0 + r.x; o.y = v1 + r.y;
                    *(float2*)(Cout + (size_t)mrow*N + cix) = o;
                }
            }
        }
    }
}

// ---------------- mma.sync flash attention with RPE bias ----------------
#define SQH 0
#define SQL 8192
#define SKH 16384
#define SKL 24576
#define SVH 32768
#define SVL 40960
#define SPH 49152
#define SPL 57344
#define SPS 65536                    // float Ps[64][66]
#define SBK (SPS + 64*66*4)
#define SRP (SBK + 4096)
#define SRM (SRP + 256)
#define SRL (SRM + 256)
#define SRS (SRL + 256)
#define ASM_TOT (SRS + 256)

__global__ void __launch_bounds__(256) attn_mma(const float* __restrict__ rpe_table, int bh_off) {
    extern __shared__ char smraw[];
    const uint32_t sb = smem_u32(smraw);
    const int tid = threadIdx.x;
    const int wid = tid >> 5, lane = tid & 31;
    const int wm = wid & 3, wn = wid >> 2;
    const int qt = blockIdx.x;
    const int bh = blockIdx.y + bh_off;
    const int b_ = bh >> 3, h = bh & 7;
    const int hp = bh >> 5, bp = bh & 31;
    const int t0 = qt << 6;

    float* rpe = (float*)(smraw + SRP);
    float* row_m = (float*)(smraw + SRM);
    float* row_l = (float*)(smraw + SRL);
    float* row_sc = (float*)(smraw + SRS);
    float* Ps = (float*)(smraw + SPS);
    unsigned char* bkt = (unsigned char*)(smraw + SBK);

    if (tid < NBUCKETS) rpe[tid] = rpe_table[hp*NBUCKETS + tid];
    if (tid < 64) { row_m[tid] = -INFINITY; row_l[tid] = 0.0f; }

    const int ldr = tid >> 3, ldu = tid & 7;

    {
        const __nv_bfloat16* qh = g_qh + ((size_t)bh*Tt + t0)*Dd;
        const __nv_bfloat16* ql = g_ql + ((size_t)bh*Tt + t0)*Dd;
#pragma unroll
        for (int p = 0; p < 2; p++) {
            int r = ldr + (p << 5);
            uint32_t d = swz128((uint32_t)(r << 7) + (ldu << 4));
            cp16(sb + SQH + d, qh + (size_t)r*Dd + (ldu << 3));
            cp16(sb + SQL + d, ql + (size_t)r*Dd + (ldu << 3));
        }
        cp_commit();
    }

    const int grp = lane >> 3, rim = lane & 7;
    const int arow0 = (wm << 4) + ((grp & 1) << 3) + rim;
    const int aku0  = grp >> 1;
    const int brow0 = (wn << 5) + ((grp >> 1) << 3) + rim;
    const int bku0  = grp & 1;

    float O[4][4] = {};
    const unsigned char* bkb = g_bucket + (size_t)bp*Tt*Tt;
    const int r0 = wm*16 + (lane >> 2);

    for (int s0 = 0; s0 < Tt; s0 += 64) {
        __syncthreads();
        {
            const __nv_bfloat16* kh = g_kh + ((size_t)bh*Tt + s0)*Dd;
            const __nv_bfloat16* kl = g_kl + ((size_t)bh*Tt + s0)*Dd;
            const __nv_bfloat16* vh = g_vth + (size_t)bh*Dd*512 + s0;
            const __nv_bfloat16* vl = g_vtl + (size_t)bh*Dd*512 + s0;
#pragma unroll
            for (int p = 0; p < 2; p++) {
                int r = ldr + (p << 5);
                uint32_t d = swz128((uint32_t)(r << 7) + (ldu << 4));
                cp16(sb + SKH + d, kh + (size_t)r*Dd + (ldu << 3));
                cp16(sb + SKL + d, kl + (size_t)r*Dd + (ldu << 3));
                cp16(sb + SVH + d, vh + (size_t)r*512 + (ldu << 3));
                cp16(sb + SVL + d, vl + (size_t)r*512 + (ldu << 3));
            }
            cp_commit();
        }
#pragma unroll
        for (int it = 0; it < 4; it++) {
            int f = tid + it*256;
            int r = f >> 4;
            int c4 = (f & 15) << 2;
            uchar4 u4 = make_uchar4(0,0,0,0);
            if (t0 + r < Tt && s0 + c4 < Tt)
                u4 = *(const uchar4*)(bkb + (size_t)(t0 + r)*Tt + s0 + c4);
            *(uchar4*)(bkt + r*64 + c4) = u4;
        }
        cp_wait<0>();
        __syncthreads();

        // ---- S = Q K^T (3-term split, term-major issue) ----
        float sacc[4][4] = {};
#pragma unroll
        for (int ks = 0; ks < 4; ks++) {
            uint32_t qhf[4], qlf[4];
            uint32_t aoff = swz128((uint32_t)(arow0 << 7) + ((aku0 + (ks << 1)) << 4));
            LDSM4(qhf, sb + SQH + aoff);
            LDSM4(qlf, sb + SQL + aoff);
            uint32_t khf[2][4], klf[2][4];
#pragma unroll
            for (int nt2 = 0; nt2 < 2; nt2++) {
                uint32_t boff = swz128((uint32_t)((brow0 + (nt2 << 4)) << 7) + ((bku0 + (ks << 1)) << 4));
                LDSM4(khf[nt2], sb + SKH + boff);
                LDSM4(klf[nt2], sb + SKL + boff);
            }
#pragma unroll
            for (int nt = 0; nt < 4; nt++)
                MMA16816(sacc[nt], qhf, khf[nt >> 1][(nt & 1)*2], khf[nt >> 1][(nt & 1)*2 + 1]);
#pragma unroll
            for (int nt = 0; nt < 4; nt++)
                MMA16816(sacc[nt], qhf, klf[nt >> 1][(nt & 1)*2], klf[nt >> 1][(nt & 1)*2 + 1]);
#pragma unroll
            for (int nt = 0; nt < 4; nt++)
                MMA16816(sacc[nt], qlf, khf[nt >> 1][(nt & 1)*2], khf[nt >> 1][(nt & 1)*2 + 1]);
        }
#pragma unroll
        for (int nt = 0; nt < 4; nt++) {
            int c0 = wn*32 + nt*8 + ((lane & 3) << 1);
            bool oob0 = (s0 + c0 >= Tt), oob1 = (s0 + c0 + 1 >= Tt);
#pragma unroll
            for (int rr = 0; rr < 2; rr++) {
                int r = r0 + rr*8;
                float v0 = sacc[nt][rr*2+0]*0.125f + rpe[bkt[r*64 + c0]];
                float v1 = sacc[nt][rr*2+1]*0.125f + rpe[bkt[r*64 + c0 + 1]];
                if (oob0) v0 = -INFINITY;
                if (oob1) v1 = -INFINITY;
                float2 o; o.x = v0; o.y = v1;
                *(float2*)&Ps[r*66 + c0] = o;
            }
        }
        __syncthreads();

        // ---- fused online softmax + P -> bf16 hi/lo ----
        {
            int r = tid >> 2, qq = tid & 3;
            int cbase = qq << 4;
            float mx = -INFINITY;
#pragma unroll
            for (int u = 0; u < 16; u++) mx = fmaxf(mx, Ps[r*66 + cbase + u]);
            mx = fmaxf(mx, __shfl_xor_sync(0xffffffffu, mx, 1));
            mx = fmaxf(mx, __shfl_xor_sync(0xffffffffu, mx, 2));
            float m_old = row_m[r];
            float m_new = fmaxf(m_old, mx);
            float ssum = 0.f;
#pragma unroll
            for (int u2 = 0; u2 < 8; u2++) {
                int c = cbase + (u2 << 1);
                float p0 = __expf(Ps[r*66 + c]     - m_new);
                float p1 = __expf(Ps[r*66 + c + 1] - m_new);
                ssum += p0;
                ssum += p1;
                unsigned short h0, l0, h1, l1;
                split_bf16(p0, h0, l0);
                split_bf16(p1, h1, l1);
                uint32_t off = swz128((uint32_t)(r << 7) + (c << 1));
                *(uint32_t*)(smraw + SPH + off) = (uint32_t)h0 | ((uint32_t)h1 << 16);
                *(uint32_t*)(smraw + SPL + off) = (uint32_t)l0 | ((uint32_t)l1 << 16);
            }
            ssum += __shfl_xor_sync(0xffffffffu, ssum, 1);
            ssum += __shfl_xor_sync(0xffffffffu, ssum, 2);
            if (qq == 0) {
                float sc = __expf(m_old - m_new);
                row_sc[r] = sc;
                row_l[r] = row_l[r]*sc + ssum;
                row_m[r] = m_new;
            }
        }
        __syncthreads();

        // ---- O = O*scale + P V (term-major issue) ----
        {
            float sc0 = row_sc[r0], sc1 = row_sc[r0 + 8];
#pragma unroll
            for (int nt = 0; nt < 4; nt++) {
                O[nt][0] *= sc0; O[nt][1] *= sc0;
                O[nt][2] *= sc1; O[nt][3] *= sc1;
            }
#pragma unroll
            for (int ks = 0; ks < 4; ks++) {
                uint32_t phf[4], plf[4];
                uint32_t aoff = swz128((uint32_t)(arow0 << 7) + ((aku0 + (ks << 1)) << 4));
                LDSM4(phf, sb + SPH + aoff);
                LDSM4(plf, sb + SPL + aoff);
                uint32_t vhf[2][4], vlf[2][4];
#pragma unroll
                for (int nt2 = 0; nt2 < 2; nt2++) {
                    uint32_t boff = swz128((uint32_t)((brow0 + (nt2 << 4)) << 7) + ((bku0 + (ks << 1)) << 4));
                    LDSM4(vhf[nt2], sb + SVH + boff);
                    LDSM4(vlf[nt2], sb + SVL + boff);
                }
#pragma unroll
                for (int nt = 0; nt < 4; nt++)
                    MMA16816(O[nt], phf, vhf[nt >> 1][(nt & 1)*2], vhf[nt >> 1][(nt & 1)*2 + 1]);
#pragma unroll
                for (int nt = 0; nt < 4; nt++)
                    MMA16816(O[nt], phf, vlf[nt >> 1][(nt & 1)*2], vlf[nt >> 1][(nt & 1)*2 + 1]);
#pragma unroll
                for (int nt = 0; nt < 4; nt++)
                    MMA16816(O[nt], plf, vhf[nt >> 1][(nt & 1)*2], vhf[nt >> 1][(nt & 1)*2 + 1]);
            }
        }
    }

    // ---- finalize ----
    {
        float inv0 = 1.0f / row_l[r0];
        float inv1 = 1.0f / row_l[r0 + 8];
        int t_a = t0 + r0, t_b = t_a + 8;
#pragma unroll
        for (int nt = 0; nt < 4; nt++) {
            int c0 = wn*32 + nt*8 + ((lane & 3) << 1);
            if (t_a < Tt) {
                unsigned short h0,l0,h1,l1;
                split_bf16(O[nt][0]*inv0, h0, l0);
                split_bf16(O[nt][1]*inv0, h1, l1);
                size_t idx = ((size_t)(b_*Tt + t_a))*Cc + h*Dd + c0;
                *(uint32_t*)(g_ahi + idx) = (uint32_t)h0 | ((uint32_t)h1 << 16);
                *(uint32_t*)(g_alo + idx) = (uint32_t)l0 | ((uint32_t)l1 << 16);
            }
            if (t_b < Tt) {
                unsigned short h0,l0,h1,l1;
                split_bf16(O[nt][2]*inv1, h0, l0);
                split_bf16(O[nt][3]*inv1, h1, l1);
                size_t idx = ((size_t)(b_*Tt + t_b))*Cc + h*Dd + c0;
                *(uint32_t*)(g_ahi + idx) = (uint32_t)h0 | ((uint32_t)h1 << 16);
                *(uint32_t*)(g_alo + idx) = (uint32_t)l0 | ((uint32_t)l1 << 16);
            }
        }
    }
}

// ---------------- layernorm (optionally emits bf16 split) ----------------
__global__ void __launch_bounds__(256) ln_kernel(const float* __restrict__ in,
    const float* __restrict__ w, const float* __restrict__ b, float* __restrict__ out,
    __nv_bfloat16* __restrict__ shi, __nv_bfloat16* __restrict__ slo, int row_off)
{
    __shared__ float red[8];
    int row = blockIdx.x + row_off;
    const float* x = in + (size_t)row*Cc;
    int tid = threadIdx.x;
    float v0 = x[tid], v1 = x[tid + 256];
    float s = v0 + v1;
#pragma unroll
    for (int o = 16; o > 0; o >>= 1) s += __shfl_xor_sync(0xffffffffu, s, o);
    if ((tid & 31) == 0) red[tid >> 5] = s;
    __syncthreads();
    float tot = red[0]+red[1]+red[2]+red[3]+red[4]+red[5]+red[6]+red[7];
    float mean = tot * (1.0f/512.0f);
    float d0 = v0 - mean, d1 = v1 - mean;
    float s2 = d0*d0 + d1*d1;
#pragma unroll
    for (int o = 16; o > 0; o >>= 1) s2 += __shfl_xor_sync(0xffffffffu, s2, o);
    __syncthreads();
    if ((tid & 31) == 0) red[tid >> 5] = s2;
    __syncthreads();
    float tot2 = red[0]+red[1]+red[2]+red[3]+red[4]+red[5]+red[6]+red[7];
    float inv = rsqrtf(tot2 * (1.0f/512.0f) + 1e-5f);
    float o0 = d0*inv*w[tid]       + b[tid];
    float o1 = d1*inv*w[tid + 256] + b[tid + 256];
    out[(size_t)row*Cc + tid]       = o0;
    out[(size_t)row*Cc + tid + 256] = o1;
    if (shi) {
        unsigned short h0,l0,h1,l1;
        split_bf16(o0, h0, l0); split_bf16(o1, h1, l1);
        shi[(size_t)row*Cc + tid]       = __ushort_as_bfloat16(h0);
        shi[(size_t)row*Cc + tid + 256] = __ushort_as_bfloat16(h1);
        slo[(size_t)row*Cc + tid]       = __ushort_as_bfloat16(l0);
        slo[(size_t)row*Cc + tid + 256] = __ushort_as_bfloat16(l1);
    }
}

// ---------------- launch ----------------
extern "C" void kernel_launch(void* const* d_in, const int* in_sizes, int n_in,
                              void* d_out, int out_size) {
    (void)in_sizes; (void)n_in; (void)out_size;
    const float* x         = (const float*)d_in[0];
    const int*   ct        = (const int*)  d_in[1];
    const float* w_attn    = (const float*)d_in[2];
    const float* b_attn    = (const float*)d_in[3];
    const float* w_proj    = (const float*)d_in[4];
    const float* b_proj    = (const float*)d_in[5];
    const float* rpe_table = (const float*)d_in[6];
    const float* ln1_w     = (const float*)d_in[7];
    const float* ln1_b     = (const float*)d_in[8];
    const float* ln2_w     = (const float*)d_in[9];
    const float* ln2_b     = (const float*)d_in[10];
    const float* w_fc      = (const float*)d_in[11];
    const float* b_fc      = (const float*)d_in[12];
    const float* w_fc2     = (const float*)d_in[13];
    const float* b_fc2     = (const float*)d_in[14];
    float* out = (float*)d_out;

    float *res_, *x1_, *res2_;
    cudaGetSymbolAddress((void**)&res_,  g_res);
    cudaGetSymbolAddress((void**)&x1_,   g_x1);
    cudaGetSymbolAddress((void**)&res2_, g_res2);
    __nv_bfloat16 *ahi, *alo, *bhi, *blo;
    __nv_bfloat16 *wha, *wla, *whp, *wlp, *whf, *wlf, *whf2, *wlf2;
    cudaGetSymbolAddress((void**)&ahi,  g_ahi);
    cudaGetSymbolAddress((void**)&alo,  g_alo);
    cudaGetSymbolAddress((void**)&bhi,  g_bhi);
    cudaGetSymbolAddress((void**)&blo,  g_blo);
    cudaGetSymbolAddress((void**)&wha,  g_wh_attn);
    cudaGetSymbolAddress((void**)&wla,  g_wl_attn);
    cudaGetSymbolAddress((void**)&whp,  g_wh_proj);
    cudaGetSymbolAddress((void**)&wlp,  g_wl_proj);
    cudaGetSymbolAddress((void**)&whf,  g_wh_fc);
    cudaGetSymbolAddress((void**)&wlf,  g_wl_fc);
    cudaGetSymbolAddress((void**)&whf2, g_wh_fc2);
    cudaGetSymbolAddress((void**)&wlf2, g_wl_fc2);

    cudaFuncSetAttribute(attn_mma, cudaFuncAttributeMaxDynamicSharedMemorySize, ASM_TOT);
    cudaFuncSetAttribute(mma_gemm<0>, cudaFuncAttributeMaxDynamicSharedMemorySize, GSM_TOT);
    cudaFuncSetAttribute(mma_gemm<1>, cudaFuncAttributeMaxDynamicSharedMemorySize, GSM_TOT);
    cudaFuncSetAttribute(mma_gemm<2>, cudaFuncAttributeMaxDynamicSharedMemorySize, GSM_TOT);
    cudaFuncSetAttribute(mma_gemm<3>, cudaFuncAttributeMaxDynamicSharedMemorySize, GSM_TOT);

    // fork: side stream does wconv (needed by gemm0) then bucket (needed by attn)
    cudaEventRecord(g_evF, 0);
    cudaStreamWaitEvent(g_side, g_evF, 0);
    wconv_all<<<2048, 256, 0, g_side>>>(w_attn, wha, wla, w_proj, whp, wlp,
                                        w_fc, whf, wlf, w_fc2, whf2, wlf2);
    cudaEventRecord(g_evW, g_side);
    bucket_kernel<<<dim3(Tt, Bb), 128, 0, g_side>>>(ct);
    cudaEventRecord(g_evJ, g_side);

    // main stream: activation split runs concurrently with wconv
    aconv_kernel<<<(Mrows*Cc/4 + 255)/256, 256>>>((const float4*)x, (uint2*)ahi, (uint2*)alo, Mrows*Cc/4);
    cudaStreamWaitEvent(0, g_evW, 0);
    mma_gemm<0><<<dim3(24, 125), 256, GSM_TOT>>>(ahi, alo, wha, wla, b_attn,
                                                 nullptr, nullptr, nullptr, nullptr, Mrows, 3*Cc, Cc, 0);
    cudaEventRecord(g_evG0, 0);

    // ---- chain A (main stream): batches 0-15, gemm tiles 0..61 ----
    cudaStreamWaitEvent(0, g_evJ, 0);
    attn_mma<<<dim3(8, 128), 256, ASM_TOT>>>(rpe_table, 0);
    cudaEventRecord(g_evAA, 0);

    // ---- chain B (side stream): batches 16-31, gemm tiles 62..124 ----
    cudaStreamWaitEvent(g_side, g_evG0, 0);
    attn_mma<<<dim3(8, 128), 256, ASM_TOT, g_side>>>(rpe_table, 128);
    cudaStreamWaitEvent(g_side, g_evAA, 0);   // tile 62 spans batches 15/16
    mma_gemm<1><<<dim3(8, TILES_B), 256, GSM_TOT, g_side>>>(ahi, alo, whp, wlp, b_proj,
                                                res_, x, nullptr, nullptr, Mrows, Cc, Cc, TILES_A);
    ln_kernel<<<Mrows - ROWS_A, 256, 0, g_side>>>(res_, ln1_w, ln1_b, x1_, ahi, alo, ROWS_A);
    mma_gemm<2><<<dim3(16, TILES_B), 256, GSM_TOT, g_side>>>(ahi, alo, whf, wlf, b_fc,
                                                 nullptr, nullptr, bhi, blo, Mrows, 2*Cc, Cc, TILES_A);
    mma_gemm<3><<<dim3(8, TILES_B), 256, GSM_TOT, g_side>>>(bhi, blo, whf2, wlf2, b_fc2,
                                                res2_, x1_, nullptr, nullptr, Mrows, Cc, 2*Cc, TILES_A);
    ln_kernel<<<Mrows - ROWS_A, 256, 0, g_side>>>(res2_, ln2_w, ln2_b, out, nullptr, nullptr, ROWS_A);
    cudaEventRecord(g_evB, g_side);

    // ---- chain A continues on main ----
    mma_gemm<1><<<dim3(8, TILES_A), 256, GSM_TOT>>>(ahi, alo, whp, wlp, b_proj,
                                                res_, x, nullptr, nullptr, Mrows, Cc, Cc, 0);
    ln_kernel<<<ROWS_A, 256>>>(res_, ln1_w, ln1_b, x1_, ahi, alo, 0);
    mma_gemm<2><<<dim3(16, TILES_A), 256, GSM_TOT>>>(ahi, alo, whf, wlf, b_fc,
                                                 nullptr, nullptr, bhi, blo, Mrows, 2*Cc, Cc, 0);
    mma_gemm<3><<<dim3(8, TILES_A), 256, GSM_TOT>>>(bhi, blo, whf2, wlf2, b_fc2,
                                                res2_, x1_, nullptr, nullptr, Mrows, Cc, 2*Cc, 0);
    ln_kernel<<<ROWS_A, 256>>>(res2_, ln2_w, ln2_b, out, nullptr, nullptr, 0);

    // join
    cudaStreamWaitEvent(0, g_evB, 0);
}

// round 16
// speedup vs baseline: 1.6243x; 1.0234x over previous
#include <cuda_runtime.h>
#include <cuda_bf16.h>
#include <math.h>
#include <stdint.h>

#define Bb 32
#define Tt 500
#define Cc 512
#define Hh 8
#define Dd 64
#define Mrows (Bb*Tt)
#define NBUCKETS 49
#define TILES_A 62
#define TILES_B 63
#define ROWS_A (TILES_A*128)
#define G0_TILES_A 63
#define G0_TILES_B 62

// ---------------- scratch (static device globals; zero-initialized) ----------------
__device__ float g_res [(size_t)Mrows*Cc];
__device__ float g_x1  [(size_t)Mrows*Cc];
__device__ float g_res2[(size_t)Mrows*Cc];
__device__ unsigned char g_bucket[(size_t)Bb*Tt*Tt + 64];

// bf16 split buffers (padded; pad region stays zero)
__device__ __nv_bfloat16 g_qh[(size_t)(Bb*Hh*Tt + 64)*Dd], g_ql[(size_t)(Bb*Hh*Tt + 64)*Dd];
__device__ __nv_bfloat16 g_kh[(size_t)(Bb*Hh*Tt + 64)*Dd], g_kl[(size_t)(Bb*Hh*Tt + 64)*Dd];
__device__ __nv_bfloat16 g_vth[(size_t)Bb*Hh*Dd*512 + 1024], g_vtl[(size_t)Bb*Hh*Dd*512 + 1024];
__device__ __nv_bfloat16 g_ahi[(size_t)Mrows*1024 + 1024], g_alo[(size_t)Mrows*1024 + 1024];
__device__ __nv_bfloat16 g_bhi[(size_t)Mrows*1024 + 1024], g_blo[(size_t)Mrows*1024 + 1024];
__device__ __nv_bfloat16 g_wh_attn[1536*512], g_wl_attn[1536*512];
__device__ __nv_bfloat16 g_wh_proj[512*512],  g_wl_proj[512*512];
__device__ __nv_bfloat16 g_wh_fc[1024*512],   g_wl_fc[1024*512];
__device__ __nv_bfloat16 g_wh_fc2[512*1024],  g_wl_fc2[512*1024];

// ---------------- side stream + events, created before harness mem checkpoints ----
static cudaStream_t g_side;
static cudaEvent_t g_evF, g_evW, g_evJ, g_ev0A, g_evAA, g_evB;
static struct SideInit {
    SideInit() {
        cudaStreamCreateWithFlags(&g_side, cudaStreamNonBlocking);
        cudaEventCreateWithFlags(&g_evF,  cudaEventDisableTiming);
        cudaEventCreateWithFlags(&g_evW,  cudaEventDisableTiming);
        cudaEventCreateWithFlags(&g_evJ,  cudaEventDisableTiming);
        cudaEventCreateWithFlags(&g_ev0A, cudaEventDisableTiming);
        cudaEventCreateWithFlags(&g_evAA, cudaEventDisableTiming);
        cudaEventCreateWithFlags(&g_evB,  cudaEventDisableTiming);
    }
} g_sideInit;

// ---------------- helpers ----------------
__device__ __forceinline__ uint32_t smem_u32(const void* p) {
    uint32_t a;
    asm("{ .reg .u64 t; cvta.to.shared.u64 t, %1; cvt.u32.u64 %0, t; }" : "=r"(a) : "l"(p));
    return a;
}
__device__ __forceinline__ uint32_t swz128(uint32_t o) { return o ^ ((o >> 3) & 0x70); }

__device__ __forceinline__ void cp16(uint32_t dst, const void* src) {
    asm volatile("cp.async.cg.shared.global [%0], [%1], 16;" :: "r"(dst), "l"(src));
}
__device__ __forceinline__ void cp_commit() {
    asm volatile("cp.async.commit_group;" ::: "memory");
}
template<int N> __device__ __forceinline__ void cp_wait() {
    asm volatile("cp.async.wait_group %0;" :: "n"(N) : "memory");
}

#define LDSM4(r, addr) \
    asm volatile("ldmatrix.sync.aligned.m8n8.x4.shared.b16 {%0,%1,%2,%3}, [%4];" \
        : "=r"((r)[0]),"=r"((r)[1]),"=r"((r)[2]),"=r"((r)[3]) : "r"(addr))

#define MMA16816(d, a, b0, b1) \
    asm volatile("mma.sync.aligned.m16n8k16.row.col.f32.bf16.bf16.f32 " \
        "{%0,%1,%2,%3}, {%4,%5,%6,%7}, {%8,%9}, {%0,%1,%2,%3};" \
        : "+f"((d)[0]),"+f"((d)[1]),"+f"((d)[2]),"+f"((d)[3]) \
        : "r"((a)[0]),"r"((a)[1]),"r"((a)[2]),"r"((a)[3]), "r"(b0),"r"(b1))

__device__ __forceinline__ void split_bf16(float v, unsigned short& h, unsigned short& l) {
    __nv_bfloat16 hb = __float2bfloat16(v);
    __nv_bfloat16 lb = __float2bfloat16(v - __bfloat162float(hb));
    h = __bfloat16_as_ushort(hb);
    l = __bfloat16_as_ushort(lb);
}

// ---------------- bucket ids ----------------
__global__ void __launch_bounds__(128) bucket_kernel(const int* __restrict__ ct) {
    __shared__ unsigned char bres[32];
    const int t = blockIdx.x, b = blockIdx.y;
    if (threadIdx.x < 32) {
        float rel = (float)threadIdx.x;
        float idx;
        if (rel <= 12.0f) idx = rel;
        else idx = fminf(rintf(12.0f + logf(rel * (1.0f/12.0f)) * 5.7707801635558523f), 24.0f);
        bres[threadIdx.x] = (unsigned char)(int)(idx + 24.0f);
    }
    __syncthreads();
    const int j = threadIdx.x;
    if (j >= 125) return;
    const int2 c1 = ((const int2*)ct)[b*Tt + t];
    const int2* cs = ((const int2*)ct) + b*Tt + 4*j;
    uchar4 o;
    unsigned char* po = &o.x;
#pragma unroll
    for (int u = 0; u < 4; u++) {
        int2 c2 = cs[u];
        int dx = c1.x - c2.x, dy = c1.y - c2.y;
        int relI = (int)(sqrtf((float)(dx*dx + dy*dy)) * (1.0f/12.0f));
        po[u] = bres[relI];
    }
    *(uchar4*)(g_bucket + (size_t)b*(Tt*Tt) + (size_t)t*Tt + 4*j) = o;
}

// ---------------- bf16 split conversions ----------------
__global__ void __launch_bounds__(256) aconv_kernel(const float4* __restrict__ in,
    uint2* __restrict__ hi, uint2* __restrict__ lo, int n4)
{
    int i = blockIdx.x * blockDim.x + threadIdx.x;
    if (i >= n4) return;
    float4 f = in[i];
    unsigned short h0,h1,h2,h3,l0,l1,l2,l3;
    split_bf16(f.x, h0, l0); split_bf16(f.y, h1, l1);
    split_bf16(f.z, h2, l2); split_bf16(f.w, h3, l3);
    uint2 ho, lv;
    ho.x = (uint32_t)h0 | ((uint32_t)h1 << 16);
    ho.y = (uint32_t)h2 | ((uint32_t)h3 << 16);
    lv.x = (uint32_t)l0 | ((uint32_t)l1 << 16);
    lv.y = (uint32_t)l2 | ((uint32_t)l3 << 16);
    hi[i] = ho; lo[i] = lv;
}

// all four weights: W [K,N] fp32 -> WT [N,K] bf16 hi/lo, one merged launch
__global__ void __launch_bounds__(256) wconv_all(
    const float* __restrict__ W0, __nv_bfloat16* __restrict__ h0v, __nv_bfloat16* __restrict__ l0v,
    const float* __restrict__ W1, __nv_bfloat16* __restrict__ h1v, __nv_bfloat16* __restrict__ l1v,
    const float* __restrict__ W2, __nv_bfloat16* __restrict__ h2v, __nv_bfloat16* __restrict__ l2v,
    const float* __restrict__ W3, __nv_bfloat16* __restrict__ h3v, __nv_bfloat16* __restrict__ l3v)
{
    __shared__ float tile[32][33];
    int p = blockIdx.x;
    const float* W; __nv_bfloat16 *hi, *lo; int K, N, nb, kb;
    if (p < 768)       { W = W0; hi = h0v; lo = l0v; K = 512;  N = 1536; nb = p % 48;          kb = p / 48; }
    else if (p < 1024) { W = W1; hi = h1v; lo = l1v; K = 512;  N = 512;  nb = (p - 768) & 15;  kb = (p - 768) >> 4; }
    else if (p < 1536) { W = W2; hi = h2v; lo = l2v; K = 512;  N = 1024; nb = (p - 1024) & 31; kb = (p - 1024) >> 5; }
    else               { W = W3; hi = h3v; lo = l3v; K = 1024; N = 512;  nb = (p - 1536) & 15; kb = (p - 1536) >> 4; }
    nb <<= 5; kb <<= 5;
    int tx = threadIdx.x & 31, ty = threadIdx.x >> 5;
#pragma unroll
    for (int it = 0; it < 32; it += 8)
        tile[ty + it][tx] = W[(size_t)(kb + ty + it)*N + nb + tx];
    __syncthreads();
#pragma unroll
    for (int it = 0; it < 32; it += 8) {
        float f = tile[tx][ty + it];
        unsigned short h_, l_;
        split_bf16(f, h_, l_);
        size_t o = (size_t)(nb + ty + it)*K + kb + tx;
        hi[o] = __ushort_as_bfloat16(h_); lo[o] = __ushort_as_bfloat16(l_);
    }
}

// ---- mma.sync GEMM: CTA 128x64, KC=64, split bf16, cp.async 2-stage, 2 CTAs/SM ----
#define TA 16384
#define TB 8192
#define STAGE_B 49152
#define GSM_TOT 98304
template<int MODE>
__global__ void __launch_bounds__(256, 2) mma_gemm(
    const __nv_bfloat16* __restrict__ Ahi, const __nv_bfloat16* __restrict__ Alo,
    const __nv_bfloat16* __restrict__ Bhi, const __nv_bfloat16* __restrict__ Blo,
    const float* __restrict__ bias, float* __restrict__ Cout,
    const float* __restrict__ resid,
    __nv_bfloat16* __restrict__ Shi, __nv_bfloat16* __restrict__ Slo,
    int M, int N, int K, int tile_off)
{
    extern __shared__ char smraw[];
    const uint32_t sb = smem_u32(smraw);
    const int tid = threadIdx.x;
    const int wid = tid >> 5, lane = tid & 31;
    const int wm = wid & 3, wn = wid >> 2;
    const int m0 = (blockIdx.y + tile_off) << 7, n0 = blockIdx.x << 6;

    const int ldr = tid >> 3, ldu = tid & 7;

    auto issue = [&](int kc, int buf) {
        uint32_t base = sb + buf*STAGE_B;
#pragma unroll
        for (int p = 0; p < 4; p++) {
            int row = ldr + (p << 5);
            uint32_t d = swz128((uint32_t)(row << 7) + (ldu << 4));
            size_t ao = (size_t)(m0 + row)*K + kc + (ldu << 3);
            cp16(base + d,      Ahi + ao);
            cp16(base + TA + d, Alo + ao);
        }
#pragma unroll
        for (int p = 0; p < 2; p++) {
            int row = ldr + (p << 5);
            uint32_t d = swz128((uint32_t)(row << 7) + (ldu << 4));
            size_t bo = (size_t)(n0 + row)*K + kc + (ldu << 3);
            cp16(base + 2*TA + d,      Bhi + bo);
            cp16(base + 2*TA + TB + d, Blo + bo);
        }
        cp_commit();
    };

    float acc[2][4][4] = {};

    const int grp = lane >> 3, rim = lane & 7;
    const int arow0 = (wm << 5) + ((grp & 1) << 3) + rim;
    const int aku0  = grp >> 1;
    const int brow0 = (wn << 5) + ((grp >> 1) << 3) + rim;
    const int bku0  = grp & 1;

    issue(0, 0);
    const int nch = K >> 6;
    for (int c = 0; c < nch; c++) {
        if (c + 1 < nch) { issue((c + 1) << 6, (c + 1) & 1); cp_wait<1>(); }
        else             { cp_wait<0>(); }
        __syncthreads();
        const uint32_t base = sb + (c & 1)*STAGE_B;
#pragma unroll
        for (int ks = 0; ks < 4; ks++) {
            uint32_t ah[2][4], al[2][4];
#pragma unroll
            for (int mt = 0; mt < 2; mt++) {
                uint32_t off = swz128((uint32_t)((arow0 + (mt << 4)) << 7) + ((aku0 + (ks << 1)) << 4));
                LDSM4(ah[mt], base + off);
                LDSM4(al[mt], base + TA + off);
            }
            uint32_t bh[2][4], bl[2][4];
#pragma unroll
            for (int nt2 = 0; nt2 < 2; nt2++) {
                uint32_t off = swz128((uint32_t)((brow0 + (nt2 << 4)) << 7) + ((bku0 + (ks << 1)) << 4));
                LDSM4(bh[nt2], base + 2*TA + off);
                LDSM4(bl[nt2], base + 2*TA + TB + off);
            }
#pragma unroll
            for (int mt = 0; mt < 2; mt++)
#pragma unroll
                for (int nt = 0; nt < 4; nt++) {
                    const uint32_t* fh = &bh[nt >> 1][(nt & 1) << 1];
                    MMA16816(acc[mt][nt], ah[mt], fh[0], fh[1]);
                }
#pragma unroll
            for (int mt = 0; mt < 2; mt++)
#pragma unroll
                for (int nt = 0; nt < 4; nt++) {
                    const uint32_t* fl = &bl[nt >> 1][(nt & 1) << 1];
                    MMA16816(acc[mt][nt], ah[mt], fl[0], fl[1]);
                }
#pragma unroll
            for (int mt = 0; mt < 2; mt++)
#pragma unroll
                for (int nt = 0; nt < 4; nt++) {
                    const uint32_t* fh = &bh[nt >> 1][(nt & 1) << 1];
                    MMA16816(acc[mt][nt], al[mt], fh[0], fh[1]);
                }
        }
        __syncthreads();
    }

    // epilogue
#pragma unroll
    for (int mt = 0; mt < 2; mt++) {
#pragma unroll
        for (int half = 0; half < 2; half++) {
            int mrow = m0 + (wm << 5) + (mt << 4) + (half << 3) + (lane >> 2);
            int b_ = mrow / Tt, t = mrow - b_*Tt;
#pragma unroll
            for (int nt = 0; nt < 4; nt++) {
                int cix = n0 + (wn << 5) + (nt << 3) + ((lane & 3) << 1);
                float v0 = acc[mt][nt][half*2 + 0] + bias[cix];
                float v1 = acc[mt][nt][half*2 + 1] + bias[cix + 1];
                if (MODE == 0) {
                    unsigned short h0,l0,h1,l1;
                    split_bf16(v0, h0, l0); split_bf16(v1, h1, l1);
                    int sec = cix >> 9, cc2 = cix & 511, hh = cc2 >> 6, d = cc2 & 63;
                    int bh_ = b_*Hh + hh;
                    if (sec == 2) {
                        size_t r0i = ((size_t)(bh_*Dd + d))*512 + t;
                        size_t r1i = ((size_t)(bh_*Dd + d + 1))*512 + t;
                        g_vth[r0i] = __ushort_as_bfloat16(h0);
                        g_vth[r1i] = __ushort_as_bfloat16(h1);
                        g_vtl[r0i] = __ushort_as_bfloat16(l0);
                        g_vtl[r1i] = __ushort_as_bfloat16(l1);
                    } else {
                        size_t idx = ((size_t)(bh_*Tt + t))*Dd + d;
                        uint32_t ph = (uint32_t)h0 | ((uint32_t)h1 << 16);
                        uint32_t pl = (uint32_t)l0 | ((uint32_t)l1 << 16);
                        if (sec == 0) { *(uint32_t*)(g_qh + idx) = ph; *(uint32_t*)(g_ql + idx) = pl; }
                        else          { *(uint32_t*)(g_kh + idx) = ph; *(uint32_t*)(g_kl + idx) = pl; }
                    }
                } else if (MODE == 2) {
                    v0 = 0.5f * v0 * (1.0f + erff(v0 * 0.7071067811865475f));
                    v1 = 0.5f * v1 * (1.0f + erff(v1 * 0.7071067811865475f));
                    unsigned short h0,l0,h1,l1;
                    split_bf16(v0, h0, l0); split_bf16(v1, h1, l1);
                    size_t idx = (size_t)mrow*N + cix;
                    *(uint32_t*)(Shi + idx) = (uint32_t)h0 | ((uint32_t)h1 << 16);
                    *(uint32_t*)(Slo + idx) = (uint32_t)l0 | ((uint32_t)l1 << 16);
                } else {
                    float2 r = *(const float2*)(resid + (size_t)mrow*N + cix);
                    float2 o; o.x = v0 + r.x; o.y = v1 + r.y;
                    *(float2*)(Cout + (size_t)mrow*N + cix) = o;
                }
            }
        }
    }
}

// ---------------- mma.sync flash attention with RPE bias ----------------
#define SQH 0
#define SQL 8192
#define SKH 16384
#define SKL 24576
#define SVH 32768
#define SVL 40960
#define SPH 49152
#define SPL 57344
#define SPS 65536                    // float Ps[64][66]
#define SBK (SPS + 64*66*4)
#define SRP (SBK + 4096)
#define SRM (SRP + 256)
#define SRL (SRM + 256)
#define SRS (SRL + 256)
#define ASM_TOT (SRS + 256)

__global__ void __launch_bounds__(256) attn_mma(const float* __restrict__ rpe_table, int bh_off) {
    extern __shared__ char smraw[];
    const uint32_t sb = smem_u32(smraw);
    const int tid = threadIdx.x;
    const int wid = tid >> 5, lane = tid & 31;
    const int wm = wid & 3, wn = wid >> 2;
    const int qt = blockIdx.x;
    const int bh = blockIdx.y + bh_off;
    const int b_ = bh >> 3, h = bh & 7;
    const int hp = bh >> 5, bp = bh & 31;
    const int t0 = qt << 6;

    float* rpe = (float*)(smraw + SRP);
    float* row_m = (float*)(smraw + SRM);
    float* row_l = (float*)(smraw + SRL);
    float* row_sc = (float*)(smraw + SRS);
    float* Ps = (float*)(smraw + SPS);
    unsigned char* bkt = (unsigned char*)(smraw + SBK);

    if (tid < NBUCKETS) rpe[tid] = rpe_table[hp*NBUCKETS + tid];
    if (tid < 64) { row_m[tid] = -INFINITY; row_l[tid] = 0.0f; }

    const int ldr = tid >> 3, ldu = tid & 7;

    {
        const __nv_bfloat16* qh = g_qh + ((size_t)bh*Tt + t0)*Dd;
        const __nv_bfloat16* ql = g_ql + ((size_t)bh*Tt + t0)*Dd;
#pragma unroll
        for (int p = 0; p < 2; p++) {
            int r = ldr + (p << 5);
            uint32_t d = swz128((uint32_t)(r << 7) + (ldu << 4));
            cp16(sb + SQH + d, qh + (size_t)r*Dd + (ldu << 3));
            cp16(sb + SQL + d, ql + (size_t)r*Dd + (ldu << 3));
        }
        cp_commit();
    }

    const int grp = lane >> 3, rim = lane & 7;
    const int arow0 = (wm << 4) + ((grp & 1) << 3) + rim;
    const int aku0  = grp >> 1;
    const int brow0 = (wn << 5) + ((grp >> 1) << 3) + rim;
    const int bku0  = grp & 1;

    float O[4][4] = {};
    const unsigned char* bkb = g_bucket + (size_t)bp*Tt*Tt;
    const int r0 = wm*16 + (lane >> 2);

    for (int s0 = 0; s0 < Tt; s0 += 64) {
        __syncthreads();
        {
            const __nv_bfloat16* kh = g_kh + ((size_t)bh*Tt + s0)*Dd;
            const __nv_bfloat16* kl = g_kl + ((size_t)bh*Tt + s0)*Dd;
            const __nv_bfloat16* vh = g_vth + (size_t)bh*Dd*512 + s0;
            const __nv_bfloat16* vl = g_vtl + (size_t)bh*Dd*512 + s0;
#pragma unroll
            for (int p = 0; p < 2; p++) {
                int r = ldr + (p << 5);
                uint32_t d = swz128((uint32_t)(r << 7) + (ldu << 4));
                cp16(sb + SKH + d, kh + (size_t)r*Dd + (ldu << 3));
                cp16(sb + SKL + d, kl + (size_t)r*Dd + (ldu << 3));
                cp16(sb + SVH + d, vh + (size_t)r*512 + (ldu << 3));
                cp16(sb + SVL + d, vl + (size_t)r*512 + (ldu << 3));
            }
            cp_commit();
        }
#pragma unroll
        for (int it = 0; it < 4; it++) {
            int f = tid + it*256;
            int r = f >> 4;
            int c4 = (f & 15) << 2;
            uchar4 u4 = make_uchar4(0,0,0,0);
            if (t0 + r < Tt && s0 + c4 < Tt)
                u4 = *(const uchar4*)(bkb + (size_t)(t0 + r)*Tt + s0 + c4);
            *(uchar4*)(bkt + r*64 + c4) = u4;
        }
        cp_wait<0>();
        __syncthreads();

        // ---- S = Q K^T (3-term split, term-major issue) ----
        float sacc[4][4] = {};
#pragma unroll
        for (int ks = 0; ks < 4; ks++) {
            uint32_t qhf[4], qlf[4];
            uint32_t aoff = swz128((uint32_t)(arow0 << 7) + ((aku0 + (ks << 1)) << 4));
            LDSM4(qhf, sb + SQH + aoff);
            LDSM4(qlf, sb + SQL + aoff);
            uint32_t khf[2][4], klf[2][4];
#pragma unroll
            for (int nt2 = 0; nt2 < 2; nt2++) {
                uint32_t boff = swz128((uint32_t)((brow0 + (nt2 << 4)) << 7) + ((bku0 + (ks << 1)) << 4));
                LDSM4(khf[nt2], sb + SKH + boff);
                LDSM4(klf[nt2], sb + SKL + boff);
            }
#pragma unroll
            for (int nt = 0; nt < 4; nt++)
                MMA16816(sacc[nt], qhf, khf[nt >> 1][(nt & 1)*2], khf[nt >> 1][(nt & 1)*2 + 1]);
#pragma unroll
            for (int nt = 0; nt < 4; nt++)
                MMA16816(sacc[nt], qhf, klf[nt >> 1][(nt & 1)*2], klf[nt >> 1][(nt & 1)*2 + 1]);
#pragma unroll
            for (int nt = 0; nt < 4; nt++)
                MMA16816(sacc[nt], qlf, khf[nt >> 1][(nt & 1)*2], khf[nt >> 1][(nt & 1)*2 + 1]);
        }
#pragma unroll
        for (int nt = 0; nt < 4; nt++) {
            int c0 = wn*32 + nt*8 + ((lane & 3) << 1);
            bool oob0 = (s0 + c0 >= Tt), oob1 = (s0 + c0 + 1 >= Tt);
#pragma unroll
            for (int rr = 0; rr < 2; rr++) {
                int r = r0 + rr*8;
                float v0 = sacc[nt][rr*2+0]*0.125f + rpe[bkt[r*64 + c0]];
                float v1 = sacc[nt][rr*2+1]*0.125f + rpe[bkt[r*64 + c0 + 1]];
                if (oob0) v0 = -INFINITY;
                if (oob1) v1 = -INFINITY;
                float2 o; o.x = v0; o.y = v1;
                *(float2*)&Ps[r*66 + c0] = o;
            }
        }
        __syncthreads();

        // ---- fused online softmax + P -> bf16 hi/lo ----
        {
            int r = tid >> 2, qq = tid & 3;
            int cbase = qq << 4;
            float mx = -INFINITY;
#pragma unroll
            for (int u = 0; u < 16; u++) mx = fmaxf(mx, Ps[r*66 + cbase + u]);
            mx = fmaxf(mx, __shfl_xor_sync(0xffffffffu, mx, 1));
            mx = fmaxf(mx, __shfl_xor_sync(0xffffffffu, mx, 2));
            float m_old = row_m[r];
            float m_new = fmaxf(m_old, mx);
            float ssum = 0.f;
#pragma unroll
            for (int u2 = 0; u2 < 8; u2++) {
                int c = cbase + (u2 << 1);
                float p0 = __expf(Ps[r*66 + c]     - m_new);
                float p1 = __expf(Ps[r*66 + c + 1] - m_new);
                ssum += p0;
                ssum += p1;
                unsigned short h0, l0, h1, l1;
                split_bf16(p0, h0, l0);
                split_bf16(p1, h1, l1);
                uint32_t off = swz128((uint32_t)(r << 7) + (c << 1));
                *(uint32_t*)(smraw + SPH + off) = (uint32_t)h0 | ((uint32_t)h1 << 16);
                *(uint32_t*)(smraw + SPL + off) = (uint32_t)l0 | ((uint32_t)l1 << 16);
            }
            ssum += __shfl_xor_sync(0xffffffffu, ssum, 1);
            ssum += __shfl_xor_sync(0xffffffffu, ssum, 2);
            if (qq == 0) {
                float sc = __expf(m_old - m_new);
                row_sc[r] = sc;
                row_l[r] = row_l[r]*sc + ssum;
                row_m[r] = m_new;
            }
        }
        __syncthreads();

        // ---- O = O*scale + P V (term-major issue) ----
        {
            float sc0 = row_sc[r0], sc1 = row_sc[r0 + 8];
#pragma unroll
            for (int nt = 0; nt < 4; nt++) {
                O[nt][0] *= sc0; O[nt][1] *= sc0;
                O[nt][2] *= sc1; O[nt][3] *= sc1;
            }
#pragma unroll
            for (int ks = 0; ks < 4; ks++) {
                uint32_t phf[4], plf[4];
                uint32_t aoff = swz128((uint32_t)(arow0 << 7) + ((aku0 + (ks << 1)) << 4));
                LDSM4(phf, sb + SPH + aoff);
                LDSM4(plf, sb + SPL + aoff);
                uint32_t vhf[2][4], vlf[2][4];
#pragma unroll
                for (int nt2 = 0; nt2 < 2; nt2++) {
                    uint32_t boff = swz128((uint32_t)((brow0 + (nt2 << 4)) << 7) + ((bku0 + (ks << 1)) << 4));
                    LDSM4(vhf[nt2], sb + SVH + boff);
                    LDSM4(vlf[nt2], sb + SVL + boff);
                }
#pragma unroll
                for (int nt = 0; nt < 4; nt++)
                    MMA16816(O[nt], phf, vhf[nt >> 1][(nt & 1)*2], vhf[nt >> 1][(nt & 1)*2 + 1]);
#pragma unroll
                for (int nt = 0; nt < 4; nt++)
                    MMA16816(O[nt], phf, vlf[nt >> 1][(nt & 1)*2], vlf[nt >> 1][(nt & 1)*2 + 1]);
#pragma unroll
                for (int nt = 0; nt < 4; nt++)
                    MMA16816(O[nt], plf, vhf[nt >> 1][(nt & 1)*2], vhf[nt >> 1][(nt & 1)*2 + 1]);
            }
        }
    }

    // ---- finalize ----
    {
        float inv0 = 1.0f / row_l[r0];
        float inv1 = 1.0f / row_l[r0 + 8];
        int t_a = t0 + r0, t_b = t_a + 8;
#pragma unroll
        for (int nt = 0; nt < 4; nt++) {
            int c0 = wn*32 + nt*8 + ((lane & 3) << 1);
            if (t_a < Tt) {
                unsigned short h0,l0,h1,l1;
                split_bf16(O[nt][0]*inv0, h0, l0);
                split_bf16(O[nt][1]*inv0, h1, l1);
                size_t idx = ((size_t)(b_*Tt + t_a))*Cc + h*Dd + c0;
                *(uint32_t*)(g_ahi + idx) = (uint32_t)h0 | ((uint32_t)h1 << 16);
                *(uint32_t*)(g_alo + idx) = (uint32_t)l0 | ((uint32_t)l1 << 16);
            }
            if (t_b < Tt) {
                unsigned short h0,l0,h1,l1;
                split_bf16(O[nt][2]*inv1, h0, l0);
                split_bf16(O[nt][3]*inv1, h1, l1);
                size_t idx = ((size_t)(b_*Tt + t_b))*Cc + h*Dd + c0;
                *(uint32_t*)(g_ahi + idx) = (uint32_t)h0 | ((uint32_t)h1 << 16);
                *(uint32_t*)(g_alo + idx) = (uint32_t)l0 | ((uint32_t)l1 << 16);
            }
        }
    }
}

// ---------------- layernorm (optionally emits bf16 split) ----------------
__global__ void __launch_bounds__(256) ln_kernel(const float* __restrict__ in,
    const float* __restrict__ w, const float* __restrict__ b, float* __restrict__ out,
    __nv_bfloat16* __restrict__ shi, __nv_bfloat16* __restrict__ slo, int row_off)
{
    __shared__ float red[8];
    int row = blockIdx.x + row_off;
    const float* x = in + (size_t)row*Cc;
    int tid = threadIdx.x;
    float v0 = x[tid], v1 = x[tid + 256];
    float s = v0 + v1;
#pragma unroll
    for (int o = 16; o > 0; o >>= 1) s += __shfl_xor_sync(0xffffffffu, s, o);
    if ((tid & 31) == 0) red[tid >> 5] = s;
    __syncthreads();
    float tot = red[0]+red[1]+red[2]+red[3]+red[4]+red[5]+red[6]+red[7];
    float mean = tot * (1.0f/512.0f);
    float d0 = v0 - mean, d1 = v1 - mean;
    float s2 = d0*d0 + d1*d1;
#pragma unroll
    for (int o = 16; o > 0; o >>= 1) s2 += __shfl_xor_sync(0xffffffffu, s2, o);
    __syncthreads();
    if ((tid & 31) == 0) red[tid >> 5] = s2;
    __syncthreads();
    float tot2 = red[0]+red[1]+red[2]+red[3]+red[4]+red[5]+red[6]+red[7];
    float inv = rsqrtf(tot2 * (1.0f/512.0f) + 1e-5f);
    float o0 = d0*inv*w[tid]       + b[tid];
    float o1 = d1*inv*w[tid + 256] + b[tid + 256];
    out[(size_t)row*Cc + tid]       = o0;
    out[(size_t)row*Cc + tid + 256] = o1;
    if (shi) {
        unsigned short h0,l0,h1,l1;
        split_bf16(o0, h0, l0); split_bf16(o1, h1, l1);
        shi[(size_t)row*Cc + tid]       = __ushort_as_bfloat16(h0);
        shi[(size_t)row*Cc + tid + 256] = __ushort_as_bfloat16(h1);
        slo[(size_t)row*Cc + tid]       = __ushort_as_bfloat16(l0);
        slo[(size_t)row*Cc + tid + 256] = __ushort_as_bfloat16(l1);
    }
}

// ---------------- launch ----------------
extern "C" void kernel_launch(void* const* d_in, const int* in_sizes, int n_in,
                              void* d_out, int out_size) {
    (void)in_sizes; (void)n_in; (void)out_size;
    const float* x         = (const float*)d_in[0];
    const int*   ct        = (const int*)  d_in[1];
    const float* w_attn    = (const float*)d_in[2];
    const float* b_attn    = (const float*)d_in[3];
    const float* w_proj    = (const float*)d_in[4];
    const float* b_proj    = (const float*)d_in[5];
    const float* rpe_table = (const float*)d_in[6];
    const float* ln1_w     = (const float*)d_in[7];
    const float* ln1_b     = (const float*)d_in[8];
    const float* ln2_w     = (const float*)d_in[9];
    const float* ln2_b     = (const float*)d_in[10];
    const float* w_fc      = (const float*)d_in[11];
    const float* b_fc      = (const float*)d_in[12];
    const float* w_fc2     = (const float*)d_in[13];
    const float* b_fc2     = (const float*)d_in[14];
    float* out = (float*)d_out;

    float *res_, *x1_, *res2_;
    cudaGetSymbolAddress((void**)&res_,  g_res);
    cudaGetSymbolAddress((void**)&x1_,   g_x1);
    cudaGetSymbolAddress((void**)&res2_, g_res2);
    __nv_bfloat16 *ahi, *alo, *bhi, *blo;
    __nv_bfloat16 *wha, *wla, *whp, *wlp, *whf, *wlf, *whf2, *wlf2;
    cudaGetSymbolAddress((void**)&ahi,  g_ahi);
    cudaGetSymbolAddress((void**)&alo,  g_alo);
    cudaGetSymbolAddress((void**)&bhi,  g_bhi);
    cudaGetSymbolAddress((void**)&blo,  g_blo);
    cudaGetSymbolAddress((void**)&wha,  g_wh_attn);
    cudaGetSymbolAddress((void**)&wla,  g_wl_attn);
    cudaGetSymbolAddress((void**)&whp,  g_wh_proj);
    cudaGetSymbolAddress((void**)&wlp,  g_wl_proj);
    cudaGetSymbolAddress((void**)&whf,  g_wh_fc);
    cudaGetSymbolAddress((void**)&wlf,  g_wl_fc);
    cudaGetSymbolAddress((void**)&whf2, g_wh_fc2);
    cudaGetSymbolAddress((void**)&wlf2, g_wl_fc2);

    cudaFuncSetAttribute(attn_mma, cudaFuncAttributeMaxDynamicSharedMemorySize, ASM_TOT);
    cudaFuncSetAttribute(mma_gemm<0>, cudaFuncAttributeMaxDynamicSharedMemorySize, GSM_TOT);
    cudaFuncSetAttribute(mma_gemm<1>, cudaFuncAttributeMaxDynamicSharedMemorySize, GSM_TOT);
    cudaFuncSetAttribute(mma_gemm<2>, cudaFuncAttributeMaxDynamicSharedMemorySize, GSM_TOT);
    cudaFuncSetAttribute(mma_gemm<3>, cudaFuncAttributeMaxDynamicSharedMemorySize, GSM_TOT);

    // fork: side stream does wconv (needed by gemm0) then bucket (needed by attn)
    cudaEventRecord(g_evF, 0);
    cudaStreamWaitEvent(g_side, g_evF, 0);
    wconv_all<<<2048, 256, 0, g_side>>>(w_attn, wha, wla, w_proj, whp, wlp,
                                        w_fc, whf, wlf, w_fc2, whf2, wlf2);
    cudaEventRecord(g_evW, g_side);
    bucket_kernel<<<dim3(Tt, Bb), 128, 0, g_side>>>(ct);
    cudaEventRecord(g_evJ, g_side);

    // main: activation split (concurrent with wconv), then gemm0 split in two halves
    aconv_kernel<<<(Mrows*Cc/4 + 255)/256, 256>>>((const float4*)x, (uint2*)ahi, (uint2*)alo, Mrows*Cc/4);
    cudaStreamWaitEvent(0, g_evW, 0);
    mma_gemm<0><<<dim3(24, G0_TILES_A), 256, GSM_TOT>>>(ahi, alo, wha, wla, b_attn,
                                                 nullptr, nullptr, nullptr, nullptr, Mrows, 3*Cc, Cc, 0);
    cudaEventRecord(g_ev0A, 0);
    mma_gemm<0><<<dim3(24, G0_TILES_B), 256, GSM_TOT>>>(ahi, alo, wha, wla, b_attn,
                                                 nullptr, nullptr, nullptr, nullptr, Mrows, 3*Cc, Cc, G0_TILES_A);

    // ---- chain A (side stream): attnA (batches 0-15) overlaps gemm0B, then its tail ----
    cudaStreamWaitEvent(g_side, g_ev0A, 0);        // bucket already ordered on side
    attn_mma<<<dim3(8, 128), 256, ASM_TOT, g_side>>>(rpe_table, 0);
    cudaEventRecord(g_evAA, g_side);
    mma_gemm<1><<<dim3(8, TILES_A), 256, GSM_TOT, g_side>>>(ahi, alo, whp, wlp, b_proj,
                                                res_, x, nullptr, nullptr, Mrows, Cc, Cc, 0);
    ln_kernel<<<ROWS_A, 256, 0, g_side>>>(res_, ln1_w, ln1_b, x1_, ahi, alo, 0);
    mma_gemm<2><<<dim3(16, TILES_A), 256, GSM_TOT, g_side>>>(ahi, alo, whf, wlf, b_fc,
                                                 nullptr, nullptr, bhi, blo, Mrows, 2*Cc, Cc, 0);
    mma_gemm<3><<<dim3(8, TILES_A), 256, GSM_TOT, g_side>>>(bhi, blo, whf2, wlf2, b_fc2,
                                                res2_, x1_, nullptr, nullptr, Mrows, Cc, 2*Cc, 0);
    ln_kernel<<<ROWS_A, 256, 0, g_side>>>(res2_, ln2_w, ln2_b, out, nullptr, nullptr, 0);
    cudaEventRecord(g_evB, g_side);

    // ---- chain B (main stream): attnB (batches 16-31) after gemm0B, then its tail ----
    cudaStreamWaitEvent(0, g_evJ, 0);              // bucket needed by attnB
    attn_mma<<<dim3(8, 128), 256, ASM_TOT>>>(rpe_table, 128);
    cudaStreamWaitEvent(0, g_evAA, 0);             // tile 62 spans batches 15/16
    mma_gemm<1><<<dim3(8, TILES_B), 256, GSM_TOT>>>(ahi, alo, whp, wlp, b_proj,
                                                res_, x, nullptr, nullptr, Mrows, Cc, Cc, TILES_A);
    ln_kernel<<<Mrows - ROWS_A, 256>>>(res_, ln1_w, ln1_b, x1_, ahi, alo, ROWS_A);
    mma_gemm<2><<<dim3(16, TILES_B), 256, GSM_TOT>>>(ahi, alo, whf, wlf, b_fc,
                                                 nullptr, nullptr, bhi, blo, Mrows, 2*Cc, Cc, TILES_A);
    mma_gemm<3><<<dim3(8, TILES_B), 256, GSM_TOT>>>(bhi, blo, whf2, wlf2, b_fc2,
                                                res2_, x1_, nullptr, nullptr, Mrows, Cc, 2*Cc, TILES_A);
    ln_kernel<<<Mrows - ROWS_A, 256>>>(res2_, ln2_w, ln2_b, out, nullptr, nullptr, ROWS_A);

    // join
    cudaStreamWaitEvent(0, g_evB, 0);
}

// round 17
// speedup vs baseline: 1.6416x; 1.0107x over previous
#include <cuda_runtime.h>
#include <cuda_bf16.h>
#include <math.h>
#include <stdint.h>

#define Bb 32
#define Tt 500
#define Cc 512
#define Hh 8
#define Dd 64
#define Mrows (Bb*Tt)
#define NBUCKETS 49
#define TILES_A 62
#define TILES_B 63
#define ROWS_A (TILES_A*128)
#define G0_TILES_A 63
#define G0_TILES_B 62

// ---------------- scratch (static device globals; zero-initialized) ----------------
__device__ float g_res [(size_t)Mrows*Cc];
__device__ float g_x1  [(size_t)Mrows*Cc];
__device__ float g_res2[(size_t)Mrows*Cc];
__device__ unsigned char g_bucket[(size_t)Bb*Tt*Tt + 64];

// bf16 split buffers (padded; pad region stays zero)
__device__ __nv_bfloat16 g_qh[(size_t)(Bb*Hh*Tt + 64)*Dd], g_ql[(size_t)(Bb*Hh*Tt + 64)*Dd];
__device__ __nv_bfloat16 g_kh[(size_t)(Bb*Hh*Tt + 64)*Dd], g_kl[(size_t)(Bb*Hh*Tt + 64)*Dd];
__device__ __nv_bfloat16 g_vth[(size_t)Bb*Hh*Dd*512 + 1024], g_vtl[(size_t)Bb*Hh*Dd*512 + 1024];
__device__ __nv_bfloat16 g_ahi[(size_t)Mrows*1024 + 1024], g_alo[(size_t)Mrows*1024 + 1024];
__device__ __nv_bfloat16 g_bhi[(size_t)Mrows*1024 + 1024], g_blo[(size_t)Mrows*1024 + 1024];
__device__ __nv_bfloat16 g_wh_attn[1536*512], g_wl_attn[1536*512];
__device__ __nv_bfloat16 g_wh_proj[512*512],  g_wl_proj[512*512];
__device__ __nv_bfloat16 g_wh_fc[1024*512],   g_wl_fc[1024*512];
__device__ __nv_bfloat16 g_wh_fc2[512*1024],  g_wl_fc2[512*1024];

// ---------------- side stream + events, created before harness mem checkpoints ----
static cudaStream_t g_side;
static cudaEvent_t g_evF, g_evW, g_evJ, g_ev0A, g_evAA, g_evB;
static struct SideInit {
    SideInit() {
        cudaStreamCreateWithFlags(&g_side, cudaStreamNonBlocking);
        cudaEventCreateWithFlags(&g_evF,  cudaEventDisableTiming);
        cudaEventCreateWithFlags(&g_evW,  cudaEventDisableTiming);
        cudaEventCreateWithFlags(&g_evJ,  cudaEventDisableTiming);
        cudaEventCreateWithFlags(&g_ev0A, cudaEventDisableTiming);
        cudaEventCreateWithFlags(&g_evAA, cudaEventDisableTiming);
        cudaEventCreateWithFlags(&g_evB,  cudaEventDisableTiming);
    }
} g_sideInit;

// ---------------- helpers ----------------
__device__ __forceinline__ uint32_t smem_u32(const void* p) {
    uint32_t a;
    asm("{ .reg .u64 t; cvta.to.shared.u64 t, %1; cvt.u32.u64 %0, t; }" : "=r"(a) : "l"(p));
    return a;
}
__device__ __forceinline__ uint32_t swz128(uint32_t o) { return o ^ ((o >> 3) & 0x70); }

__device__ __forceinline__ void cp16(uint32_t dst, const void* src) {
    asm volatile("cp.async.cg.shared.global [%0], [%1], 16;" :: "r"(dst), "l"(src));
}
__device__ __forceinline__ void cp_commit() {
    asm volatile("cp.async.commit_group;" ::: "memory");
}
template<int N> __device__ __forceinline__ void cp_wait() {
    asm volatile("cp.async.wait_group %0;" :: "n"(N) : "memory");
}

#define LDSM4(r, addr) \
    asm volatile("ldmatrix.sync.aligned.m8n8.x4.shared.b16 {%0,%1,%2,%3}, [%4];" \
        : "=r"((r)[0]),"=r"((r)[1]),"=r"((r)[2]),"=r"((r)[3]) : "r"(addr))

#define MMA16816(d, a, b0, b1) \
    asm volatile("mma.sync.aligned.m16n8k16.row.col.f32.bf16.bf16.f32 " \
        "{%0,%1,%2,%3}, {%4,%5,%6,%7}, {%8,%9}, {%0,%1,%2,%3};" \
        : "+f"((d)[0]),"+f"((d)[1]),"+f"((d)[2]),"+f"((d)[3]) \
        : "r"((a)[0]),"r"((a)[1]),"r"((a)[2]),"r"((a)[3]), "r"(b0),"r"(b1))

__device__ __forceinline__ void split_bf16(float v, unsigned short& h, unsigned short& l) {
    __nv_bfloat16 hb = __float2bfloat16(v);
    __nv_bfloat16 lb = __float2bfloat16(v - __bfloat162float(hb));
    h = __bfloat16_as_ushort(hb);
    l = __bfloat16_as_ushort(lb);
}

// ---------------- bucket ids: symmetric 64x64 tile pairs + 32-entry rel table ----
// bucket(t,s) == bucket(s,t); compute pairs (i >= j) once, mirror via smem.
// Table + per-pair ops are bit-identical to the original path (validated in R9).
__global__ void __launch_bounds__(256) bucket_kernel(const int* __restrict__ ct) {
    __shared__ int2 rc[64], cc[64];
    __shared__ unsigned char bres[32];
    __shared__ unsigned char tl[64][68];
    const int b = blockIdx.y;
    int p = blockIdx.x;
    int i = 0;
    while (p >= i + 1) { p -= i + 1; i++; }   // p -> (i, j), j <= i, 36 pairs for 8 tiles
    const int j = p;
    const int t0 = i << 6, s0 = j << 6;
    const int R  = (Tt - t0 < 64) ? (Tt - t0) : 64;
    const int Cn = (Tt - s0 < 64) ? (Tt - s0) : 64;
    const int tid = threadIdx.x;

    if (tid < 32) {
        float rel = (float)tid;
        float idx;
        if (rel <= 12.0f) idx = rel;
        else idx = fminf(rintf(12.0f + logf(rel * (1.0f/12.0f)) * 5.7707801635558523f), 24.0f);
        bres[tid] = (unsigned char)(int)(idx + 24.0f);
    }
    if (tid < 64) { if (tid < R) rc[tid] = ((const int2*)ct)[b*Tt + t0 + tid]; }
    else if (tid < 128) { int u = tid - 64; if (u < Cn) cc[u] = ((const int2*)ct)[b*Tt + s0 + u]; }
    __syncthreads();

    unsigned char* bko = g_bucket + (size_t)b*(Tt*Tt);
#pragma unroll
    for (int it = 0; it < 4; it++) {
        int f = tid + (it << 8);
        int r = f >> 4, c4 = (f & 15) << 2;
        if (r < R && c4 < Cn) {                  // R, Cn are multiples of 4 (64 or 52)
            int2 c1 = rc[r];
            uchar4 o;
            unsigned char* po = &o.x;
#pragma unroll
            for (int u = 0; u < 4; u++) {
                int2 c2 = cc[c4 + u];
                int dx = c1.x - c2.x, dy = c1.y - c2.y;
                int relI = (int)(sqrtf((float)(dx*dx + dy*dy)) * (1.0f/12.0f));
                po[u] = bres[relI];
            }
            *(uchar4*)&tl[r][c4] = o;
            *(uchar4*)(bko + (size_t)(t0 + r)*Tt + s0 + c4) = o;
        }
    }
    if (i == j) return;
    __syncthreads();
    // mirror: bucket(s, t) = bucket(t, s)
#pragma unroll
    for (int it = 0; it < 4; it++) {
        int f = tid + (it << 8);
        int sr = f >> 4, tc4 = (f & 15) << 2;
        if (sr < Cn && tc4 < R) {
            uchar4 o;
            o.x = tl[tc4 + 0][sr]; o.y = tl[tc4 + 1][sr];
            o.z = tl[tc4 + 2][sr]; o.w = tl[tc4 + 3][sr];
            *(uchar4*)(bko + (size_t)(s0 + sr)*Tt + t0 + tc4) = o;
        }
    }
}

// ---------------- bf16 split conversions ----------------
__global__ void __launch_bounds__(256) aconv_kernel(const float4* __restrict__ in,
    uint2* __restrict__ hi, uint2* __restrict__ lo, int n4)
{
    int i = blockIdx.x * blockDim.x + threadIdx.x;
    if (i >= n4) return;
    float4 f = in[i];
    unsigned short h0,h1,h2,h3,l0,l1,l2,l3;
    split_bf16(f.x, h0, l0); split_bf16(f.y, h1, l1);
    split_bf16(f.z, h2, l2); split_bf16(f.w, h3, l3);
    uint2 ho, lv;
    ho.x = (uint32_t)h0 | ((uint32_t)h1 << 16);
    ho.y = (uint32_t)h2 | ((uint32_t)h3 << 16);
    lv.x = (uint32_t)l0 | ((uint32_t)l1 << 16);
    lv.y = (uint32_t)l2 | ((uint32_t)l3 << 16);
    hi[i] = ho; lo[i] = lv;
}

// all four weights: W [K,N] fp32 -> WT [N,K] bf16 hi/lo, one merged launch
__global__ void __launch_bounds__(256) wconv_all(
    const float* __restrict__ W0, __nv_bfloat16* __restrict__ h0v, __nv_bfloat16* __restrict__ l0v,
    const float* __restrict__ W1, __nv_bfloat16* __restrict__ h1v, __nv_bfloat16* __restrict__ l1v,
    const float* __restrict__ W2, __nv_bfloat16* __restrict__ h2v, __nv_bfloat16* __restrict__ l2v,
    const float* __restrict__ W3, __nv_bfloat16* __restrict__ h3v, __nv_bfloat16* __restrict__ l3v)
{
    __shared__ float tile[32][33];
    int p = blockIdx.x;
    const float* W; __nv_bfloat16 *hi, *lo; int K, N, nb, kb;
    if (p < 768)       { W = W0; hi = h0v; lo = l0v; K = 512;  N = 1536; nb = p % 48;          kb = p / 48; }
    else if (p < 1024) { W = W1; hi = h1v; lo = l1v; K = 512;  N = 512;  nb = (p - 768) & 15;  kb = (p - 768) >> 4; }
    else if (p < 1536) { W = W2; hi = h2v; lo = l2v; K = 512;  N = 1024; nb = (p - 1024) & 31; kb = (p - 1024) >> 5; }
    else               { W = W3; hi = h3v; lo = l3v; K = 1024; N = 512;  nb = (p - 1536) & 15; kb = (p - 1536) >> 4; }
    nb <<= 5; kb <<= 5;
    int tx = threadIdx.x & 31, ty = threadIdx.x >> 5;
#pragma unroll
    for (int it = 0; it < 32; it += 8)
        tile[ty + it][tx] = W[(size_t)(kb + ty + it)*N + nb + tx];
    __syncthreads();
#pragma unroll
    for (int it = 0; it < 32; it += 8) {
        float f = tile[tx][ty + it];
        unsigned short h_, l_;
        split_bf16(f, h_, l_);
        size_t o = (size_t)(nb + ty + it)*K + kb + tx;
        hi[o] = __ushort_as_bfloat16(h_); lo[o] = __ushort_as_bfloat16(l_);
    }
}

// ---- mma.sync GEMM: CTA 128x64, KC=64, split bf16, cp.async 2-stage, 2 CTAs/SM ----
// single barrier per chunk: cp_wait -> sync -> issue(next) -> compute
#define TA 16384
#define TB 8192
#define STAGE_B 49152
#define GSM_TOT 98304
template<int MODE>
__global__ void __launch_bounds__(256, 2) mma_gemm(
    const __nv_bfloat16* __restrict__ Ahi, const __nv_bfloat16* __restrict__ Alo,
    const __nv_bfloat16* __restrict__ Bhi, const __nv_bfloat16* __restrict__ Blo,
    const float* __restrict__ bias, float* __restrict__ Cout,
    const float* __restrict__ resid,
    __nv_bfloat16* __restrict__ Shi, __nv_bfloat16* __restrict__ Slo,
    int M, int N, int K, int tile_off)
{
    extern __shared__ char smraw[];
    const uint32_t sb = smem_u32(smraw);
    const int tid = threadIdx.x;
    const int wid = tid >> 5, lane = tid & 31;
    const int wm = wid & 3, wn = wid >> 2;
    const int m0 = (blockIdx.y + tile_off) << 7, n0 = blockIdx.x << 6;

    const int ldr = tid >> 3, ldu = tid & 7;

    auto issue = [&](int kc, int buf) {
        uint32_t base = sb + buf*STAGE_B;
#pragma unroll
        for (int p = 0; p < 4; p++) {
            int row = ldr + (p << 5);
            uint32_t d = swz128((uint32_t)(row << 7) + (ldu << 4));
            size_t ao = (size_t)(m0 + row)*K + kc + (ldu << 3);
            cp16(base + d,      Ahi + ao);
            cp16(base + TA + d, Alo + ao);
        }
#pragma unroll
        for (int p = 0; p < 2; p++) {
            int row = ldr + (p << 5);
            uint32_t d = swz128((uint32_t)(row << 7) + (ldu << 4));
            size_t bo = (size_t)(n0 + row)*K + kc + (ldu << 3);
            cp16(base + 2*TA + d,      Bhi + bo);
            cp16(base + 2*TA + TB + d, Blo + bo);
        }
        cp_commit();
    };

    float acc[2][4][4] = {};

    const int grp = lane >> 3, rim = lane & 7;
    const int arow0 = (wm << 5) + ((grp & 1) << 3) + rim;
    const int aku0  = grp >> 1;
    const int brow0 = (wn << 5) + ((grp >> 1) << 3) + rim;
    const int bku0  = grp & 1;

    issue(0, 0);
    const int nch = K >> 6;
    for (int c = 0; c < nch; c++) {
        cp_wait<0>();
        __syncthreads();
        if (c + 1 < nch) issue((c + 1) << 6, (c + 1) & 1);
        const uint32_t base = sb + (c & 1)*STAGE_B;
#pragma unroll
        for (int ks = 0; ks < 4; ks++) {
            uint32_t ah[2][4], al[2][4];
#pragma unroll
            for (int mt = 0; mt < 2; mt++) {
                uint32_t off = swz128((uint32_t)((arow0 + (mt << 4)) << 7) + ((aku0 + (ks << 1)) << 4));
                LDSM4(ah[mt], base + off);
                LDSM4(al[mt], base + TA + off);
            }
            uint32_t bh[2][4], bl[2][4];
#pragma unroll
            for (int nt2 = 0; nt2 < 2; nt2++) {
                uint32_t off = swz128((uint32_t)((brow0 + (nt2 << 4)) << 7) + ((bku0 + (ks << 1)) << 4));
                LDSM4(bh[nt2], base + 2*TA + off);
                LDSM4(bl[nt2], base + 2*TA + TB + off);
            }
#pragma unroll
            for (int mt = 0; mt < 2; mt++)
#pragma unroll
                for (int nt = 0; nt < 4; nt++) {
                    const uint32_t* fh = &bh[nt >> 1][(nt & 1) << 1];
                    MMA16816(acc[mt][nt], ah[mt], fh[0], fh[1]);
                }
#pragma unroll
            for (int mt = 0; mt < 2; mt++)
#pragma unroll
                for (int nt = 0; nt < 4; nt++) {
                    const uint32_t* fl = &bl[nt >> 1][(nt & 1) << 1];
                    MMA16816(acc[mt][nt], ah[mt], fl[0], fl[1]);
                }
#pragma unroll
            for (int mt = 0; mt < 2; mt++)
#pragma unroll
                for (int nt = 0; nt < 4; nt++) {
                    const uint32_t* fh = &bh[nt >> 1][(nt & 1) << 1];
                    MMA16816(acc[mt][nt], al[mt], fh[0], fh[1]);
                }
        }
    }

    // epilogue
#pragma unroll
    for (int mt = 0; mt < 2; mt++) {
#pragma unroll
        for (int half = 0; half < 2; half++) {
            int mrow = m0 + (wm << 5) + (mt << 4) + (half << 3) + (lane >> 2);
            int b_ = mrow / Tt, t = mrow - b_*Tt;
#pragma unroll
            for (int nt = 0; nt < 4; nt++) {
                int cix = n0 + (wn << 5) + (nt << 3) + ((lane & 3) << 1);
                float v0 = acc[mt][nt][half*2 + 0] + bias[cix];
                float v1 = acc[mt][nt][half*2 + 1] + bias[cix + 1];
                if (MODE == 0) {
                    unsigned short h0,l0,h1,l1;
                    split_bf16(v0, h0, l0); split_bf16(v1, h1, l1);
                    int sec = cix >> 9, cc2 = cix & 511, hh = cc2 >> 6, d = cc2 & 63;
                    int bh_ = b_*Hh + hh;
                    if (sec == 2) {
                        size_t r0i = ((size_t)(bh_*Dd + d))*512 + t;
                        size_t r1i = ((size_t)(bh_*Dd + d + 1))*512 + t;
                        g_vth[r0i] = __ushort_as_bfloat16(h0);
                        g_vth[r1i] = __ushort_as_bfloat16(h1);
                        g_vtl[r0i] = __ushort_as_bfloat16(l0);
                        g_vtl[r1i] = __ushort_as_bfloat16(l1);
                    } else {
                        size_t idx = ((size_t)(bh_*Tt + t))*Dd + d;
                        uint32_t ph = (uint32_t)h0 | ((uint32_t)h1 << 16);
                        uint32_t pl = (uint32_t)l0 | ((uint32_t)l1 << 16);
                        if (sec == 0) { *(uint32_t*)(g_qh + idx) = ph; *(uint32_t*)(g_ql + idx) = pl; }
                        else          { *(uint32_t*)(g_kh + idx) = ph; *(uint32_t*)(g_kl + idx) = pl; }
                    }
                } else if (MODE == 2) {
                    v0 = 0.5f * v0 * (1.0f + erff(v0 * 0.7071067811865475f));
                    v1 = 0.5f * v1 * (1.0f + erff(v1 * 0.7071067811865475f));
                    unsigned short h0,l0,h1,l1;
                    split_bf16(v0, h0, l0); split_bf16(v1, h1, l1);
                    size_t idx = (size_t)mrow*N + cix;
                    *(uint32_t*)(Shi + idx) = (uint32_t)h0 | ((uint32_t)h1 << 16);
                    *(uint32_t*)(Slo + idx) = (uint32_t)l0 | ((uint32_t)l1 << 16);
                } else {
                    float2 r = *(const float2*)(resid + (size_t)mrow*N + cix);
                    float2 o; o.x = v0 + r.x; o.y = v1 + r.y;
                    *(float2*)(Cout + (size_t)mrow*N + cix) = o;
                }
            }
        }
    }
}

// ---------------- mma.sync flash attention with RPE bias ----------------
#define SQH 0
#define SQL 8192
#define SKH 16384
#define SKL 24576
#define SVH 32768
#define SVL 40960
#define SPH 49152
#define SPL 57344
#define SPS 65536                    // float Ps[64][66]
#define SBK (SPS + 64*66*4)
#define SRP (SBK + 4096)
#define SRM (SRP + 256)
#define SRL (SRM + 256)
#define SRS (SRL + 256)
#define ASM_TOT (SRS + 256)

__global__ void __launch_bounds__(256) attn_mma(const float* __restrict__ rpe_table, int bh_off) {
    extern __shared__ char smraw[];
    const uint32_t sb = smem_u32(smraw);
    const int tid = threadIdx.x;
    const int wid = tid >> 5, lane = tid & 31;
    const int wm = wid & 3, wn = wid >> 2;
    const int qt = blockIdx.x;
    const int bh = blockIdx.y + bh_off;
    const int b_ = bh >> 3, h = bh & 7;
    const int hp = bh >> 5, bp = bh & 31;
    const int t0 = qt << 6;

    float* rpe = (float*)(smraw + SRP);
    float* row_m = (float*)(smraw + SRM);
    float* row_l = (float*)(smraw + SRL);
    float* row_sc = (float*)(smraw + SRS);
    float* Ps = (float*)(smraw + SPS);
    unsigned char* bkt = (unsigned char*)(smraw + SBK);

    if (tid < NBUCKETS) rpe[tid] = rpe_table[hp*NBUCKETS + tid];
    if (tid < 64) { row_m[tid] = -INFINITY; row_l[tid] = 0.0f; }

    const int ldr = tid >> 3, ldu = tid & 7;

    {
        const __nv_bfloat16* qh = g_qh + ((size_t)bh*Tt + t0)*Dd;
        const __nv_bfloat16* ql = g_ql + ((size_t)bh*Tt + t0)*Dd;
#pragma unroll
        for (int p = 0; p < 2; p++) {
            int r = ldr + (p << 5);
            uint32_t d = swz128((uint32_t)(r << 7) + (ldu << 4));
            cp16(sb + SQH + d, qh + (size_t)r*Dd + (ldu << 3));
            cp16(sb + SQL + d, ql + (size_t)r*Dd + (ldu << 3));
        }
        cp_commit();
    }

    const int grp = lane >> 3, rim = lane & 7;
    const int arow0 = (wm << 4) + ((grp & 1) << 3) + rim;
    const int aku0  = grp >> 1;
    const int brow0 = (wn << 5) + ((grp >> 1) << 3) + rim;
    const int bku0  = grp & 1;

    float O[4][4] = {};
    const unsigned char* bkb = g_bucket + (size_t)bp*Tt*Tt;
    const int r0 = wm*16 + (lane >> 2);

    for (int s0 = 0; s0 < Tt; s0 += 64) {
        __syncthreads();
        {
            const __nv_bfloat16* kh = g_kh + ((size_t)bh*Tt + s0)*Dd;
            const __nv_bfloat16* kl = g_kl + ((size_t)bh*Tt + s0)*Dd;
            const __nv_bfloat16* vh = g_vth + (size_t)bh*Dd*512 + s0;
            const __nv_bfloat16* vl = g_vtl + (size_t)bh*Dd*512 + s0;
#pragma unroll
            for (int p = 0; p < 2; p++) {
                int r = ldr + (p << 5);
                uint32_t d = swz128((uint32_t)(r << 7) + (ldu << 4));
                cp16(sb + SKH + d, kh + (size_t)r*Dd + (ldu << 3));
                cp16(sb + SKL + d, kl + (size_t)r*Dd + (ldu << 3));
                cp16(sb + SVH + d, vh + (size_t)r*512 + (ldu << 3));
                cp16(sb + SVL + d, vl + (size_t)r*512 + (ldu << 3));
            }
            cp_commit();
        }
#pragma unroll
        for (int it = 0; it < 4; it++) {
            int f = tid + it*256;
            int r = f >> 4;
            int c4 = (f & 15) << 2;
            uchar4 u4 = make_uchar4(0,0,0,0);
            if (t0 + r < Tt && s0 + c4 < Tt)
                u4 = *(const uchar4*)(bkb + (size_t)(t0 + r)*Tt + s0 + c4);
            *(uchar4*)(bkt + r*64 + c4) = u4;
        }
        cp_wait<0>();
        __syncthreads();

        // ---- S = Q K^T (3-term split, term-major issue) ----
        float sacc[4][4] = {};
#pragma unroll
        for (int ks = 0; ks < 4; ks++) {
            uint32_t qhf[4], qlf[4];
            uint32_t aoff = swz128((uint32_t)(arow0 << 7) + ((aku0 + (ks << 1)) << 4));
            LDSM4(qhf, sb + SQH + aoff);
            LDSM4(qlf, sb + SQL + aoff);
            uint32_t khf[2][4], klf[2][4];
#pragma unroll
            for (int nt2 = 0; nt2 < 2; nt2++) {
                uint32_t boff = swz128((uint32_t)((brow0 + (nt2 << 4)) << 7) + ((bku0 + (ks << 1)) << 4));
                LDSM4(khf[nt2], sb + SKH + boff);
                LDSM4(klf[nt2], sb + SKL + boff);
            }
#pragma unroll
            for (int nt = 0; nt < 4; nt++)
                MMA16816(sacc[nt], qhf, khf[nt >> 1][(nt & 1)*2], khf[nt >> 1][(nt & 1)*2 + 1]);
#pragma unroll
            for (int nt = 0; nt < 4; nt++)
                MMA16816(sacc[nt], qhf, klf[nt >> 1][(nt & 1)*2], klf[nt >> 1][(nt & 1)*2 + 1]);
#pragma unroll
            for (int nt = 0; nt < 4; nt++)
                MMA16816(sacc[nt], qlf, khf[nt >> 1][(nt & 1)*2], khf[nt >> 1][(nt & 1)*2 + 1]);
        }
#pragma unroll
        for (int nt = 0; nt < 4; nt++) {
            int c0 = wn*32 + nt*8 + ((lane & 3) << 1);
            bool oob0 = (s0 + c0 >= Tt), oob1 = (s0 + c0 + 1 >= Tt);
#pragma unroll
            for (int rr = 0; rr < 2; rr++) {
                int r = r0 + rr*8;
                float v0 = sacc[nt][rr*2+0]*0.125f + rpe[bkt[r*64 + c0]];
                float v1 = sacc[nt][rr*2+1]*0.125f + rpe[bkt[r*64 + c0 + 1]];
                if (oob0) v0 = -INFINITY;
                if (oob1) v1 = -INFINITY;
                float2 o; o.x = v0; o.y = v1;
                *(float2*)&Ps[r*66 + c0] = o;
            }
        }
        __syncthreads();

        // ---- fused online softmax + P -> bf16 hi/lo ----
        {
            int r = tid >> 2, qq = tid & 3;
            int cbase = qq << 4;
            float mx = -INFINITY;
#pragma unroll
            for (int u = 0; u < 16; u++) mx = fmaxf(mx, Ps[r*66 + cbase + u]);
            mx = fmaxf(mx, __shfl_xor_sync(0xffffffffu, mx, 1));
            mx = fmaxf(mx, __shfl_xor_sync(0xffffffffu, mx, 2));
            float m_old = row_m[r];
            float m_new = fmaxf(m_old, mx);
            float ssum = 0.f;
#pragma unroll
            for (int u2 = 0; u2 < 8; u2++) {
                int c = cbase + (u2 << 1);
                float p0 = __expf(Ps[r*66 + c]     - m_new);
                float p1 = __expf(Ps[r*66 + c + 1] - m_new);
                ssum += p0;
                ssum += p1;
                unsigned short h0, l0, h1, l1;
                split_bf16(p0, h0, l0);
                split_bf16(p1, h1, l1);
                uint32_t off = swz128((uint32_t)(r << 7) + (c << 1));
                *(uint32_t*)(smraw + SPH + off) = (uint32_t)h0 | ((uint32_t)h1 << 16);
                *(uint32_t*)(smraw + SPL + off) = (uint32_t)l0 | ((uint32_t)l1 << 16);
            }
            ssum += __shfl_xor_sync(0xffffffffu, ssum, 1);
            ssum += __shfl_xor_sync(0xffffffffu, ssum, 2);
            if (qq == 0) {
                float sc = __expf(m_old - m_new);
                row_sc[r] = sc;
                row_l[r] = row_l[r]*sc + ssum;
                row_m[r] = m_new;
            }
        }
        __syncthreads();

        // ---- O = O*scale + P V (term-major issue) ----
        {
            float sc0 = row_sc[r0], sc1 = row_sc[r0 + 8];
#pragma unroll
            for (int nt = 0; nt < 4; nt++) {
                O[nt][0] *= sc0; O[nt][1] *= sc0;
                O[nt][2] *= sc1; O[nt][3] *= sc1;
            }
#pragma unroll
            for (int ks = 0; ks < 4; ks++) {
                uint32_t phf[4], plf[4];
                uint32_t aoff = swz128((uint32_t)(arow0 << 7) + ((aku0 + (ks << 1)) << 4));
                LDSM4(phf, sb + SPH + aoff);
                LDSM4(plf, sb + SPL + aoff);
                uint32_t vhf[2][4], vlf[2][4];
#pragma unroll
                for (int nt2 = 0; nt2 < 2; nt2++) {
                    uint32_t boff = swz128((uint32_t)((brow0 + (nt2 << 4)) << 7) + ((bku0 + (ks << 1)) << 4));
                    LDSM4(vhf[nt2], sb + SVH + boff);
                    LDSM4(vlf[nt2], sb + SVL + boff);
                }
#pragma unroll
                for (int nt = 0; nt < 4; nt++)
                    MMA16816(O[nt], phf, vhf[nt >> 1][(nt & 1)*2], vhf[nt >> 1][(nt & 1)*2 + 1]);
#pragma unroll
                for (int nt = 0; nt < 4; nt++)
                    MMA16816(O[nt], phf, vlf[nt >> 1][(nt & 1)*2], vlf[nt >> 1][(nt & 1)*2 + 1]);
#pragma unroll
                for (int nt = 0; nt < 4; nt++)
                    MMA16816(O[nt], plf, vhf[nt >> 1][(nt & 1)*2], vhf[nt >> 1][(nt & 1)*2 + 1]);
            }
        }
    }

    // ---- finalize ----
    {
        float inv0 = 1.0f / row_l[r0];
        float inv1 = 1.0f / row_l[r0 + 8];
        int t_a = t0 + r0, t_b = t_a + 8;
#pragma unroll
        for (int nt = 0; nt < 4; nt++) {
            int c0 = wn*32 + nt*8 + ((lane & 3) << 1);
            if (t_a < Tt) {
                unsigned short h0,l0,h1,l1;
                split_bf16(O[nt][0]*inv0, h0, l0);
                split_bf16(O[nt][1]*inv0, h1, l1);
                size_t idx = ((size_t)(b_*Tt + t_a))*Cc + h*Dd + c0;
                *(uint32_t*)(g_ahi + idx) = (uint32_t)h0 | ((uint32_t)h1 << 16);
                *(uint32_t*)(g_alo + idx) = (uint32_t)l0 | ((uint32_t)l1 << 16);
            }
            if (t_b < Tt) {
                unsigned short h0,l0,h1,l1;
                split_bf16(O[nt][2]*inv1, h0, l0);
                split_bf16(O[nt][3]*inv1, h1, l1);
                size_t idx = ((size_t)(b_*Tt + t_b))*Cc + h*Dd + c0;
                *(uint32_t*)(g_ahi + idx) = (uint32_t)h0 | ((uint32_t)h1 << 16);
                *(uint32_t*)(g_alo + idx) = (uint32_t)l0 | ((uint32_t)l1 << 16);
            }
        }
    }
}

// ---------------- layernorm (optionally emits bf16 split) ----------------
__global__ void __launch_bounds__(256) ln_kernel(const float* __restrict__ in,
    const float* __restrict__ w, const float* __restrict__ b, float* __restrict__ out,
    __nv_bfloat16* __restrict__ shi, __nv_bfloat16* __restrict__ slo, int row_off)
{
    __shared__ float red[8];
    int row = blockIdx.x + row_off;
    const float* x = in + (size_t)row*Cc;
    int tid = threadIdx.x;
    float v0 = x[tid], v1 = x[tid + 256];
    float s = v0 + v1;
#pragma unroll
    for (int o = 16; o > 0; o >>= 1) s += __shfl_xor_sync(0xffffffffu, s, o);
    if ((tid & 31) == 0) red[tid >> 5] = s;
    __syncthreads();
    float tot = red[0]+red[1]+red[2]+red[3]+red[4]+red[5]+red[6]+red[7];
    float mean = tot * (1.0f/512.0f);
    float d0 = v0 - mean, d1 = v1 - mean;
    float s2 = d0*d0 + d1*d1;
#pragma unroll
    for (int o = 16; o > 0; o >>= 1) s2 += __shfl_xor_sync(0xffffffffu, s2, o);
    __syncthreads();
    if ((tid & 31) == 0) red[tid >> 5] = s2;
    __syncthreads();
    float tot2 = red[0]+red[1]+red[2]+red[3]+red[4]+red[5]+red[6]+red[7];
    float inv = rsqrtf(tot2 * (1.0f/512.0f) + 1e-5f);
    float o0 = d0*inv*w[tid]       + b[tid];
    float o1 = d1*inv*w[tid + 256] + b[tid + 256];
    out[(size_t)row*Cc + tid]       = o0;
    out[(size_t)row*Cc + tid + 256] = o1;
    if (shi) {
        unsigned short h0,l0,h1,l1;
        split_bf16(o0, h0, l0); split_bf16(o1, h1, l1);
        shi[(size_t)row*Cc + tid]       = __ushort_as_bfloat16(h0);
        shi[(size_t)row*Cc + tid + 256] = __ushort_as_bfloat16(h1);
        slo[(size_t)row*Cc + tid]       = __ushort_as_bfloat16(l0);
        slo[(size_t)row*Cc + tid + 256] = __ushort_as_bfloat16(l1);
    }
}

// ---------------- launch ----------------
extern "C" void kernel_launch(void* const* d_in, const int* in_sizes, int n_in,
                              void* d_out, int out_size) {
    (void)in_sizes; (void)n_in; (void)out_size;
    const float* x         = (const float*)d_in[0];
    const int*   ct        = (const int*)  d_in[1];
    const float* w_attn    = (const float*)d_in[2];
    const float* b_attn    = (const float*)d_in[3];
    const float* w_proj    = (const float*)d_in[4];
    const float* b_proj    = (const float*)d_in[5];
    const float* rpe_table = (const float*)d_in[6];
    const float* ln1_w     = (const float*)d_in[7];
    const float* ln1_b     = (const float*)d_in[8];
    const float* ln2_w     = (const float*)d_in[9];
    const float* ln2_b     = (const float*)d_in[10];
    const float* w_fc      = (const float*)d_in[11];
    const float* b_fc      = (const float*)d_in[12];
    const float* w_fc2     = (const float*)d_in[13];
    const float* b_fc2     = (const float*)d_in[14];
    float* out = (float*)d_out;

    float *res_, *x1_, *res2_;
    cudaGetSymbolAddress((void**)&res_,  g_res);
    cudaGetSymbolAddress((void**)&x1_,   g_x1);
    cudaGetSymbolAddress((void**)&res2_, g_res2);
    __nv_bfloat16 *ahi, *alo, *bhi, *blo;
    __nv_bfloat16 *wha, *wla, *whp, *wlp, *whf, *wlf, *whf2, *wlf2;
    cudaGetSymbolAddress((void**)&ahi,  g_ahi);
    cudaGetSymbolAddress((void**)&alo,  g_alo);
    cudaGetSymbolAddress((void**)&bhi,  g_bhi);
    cudaGetSymbolAddress((void**)&blo,  g_blo);
    cudaGetSymbolAddress((void**)&wha,  g_wh_attn);
    cudaGetSymbolAddress((void**)&wla,  g_wl_attn);
    cudaGetSymbolAddress((void**)&whp,  g_wh_proj);
    cudaGetSymbolAddress((void**)&wlp,  g_wl_proj);
    cudaGetSymbolAddress((void**)&whf,  g_wh_fc);
    cudaGetSymbolAddress((void**)&wlf,  g_wl_fc);
    cudaGetSymbolAddress((void**)&whf2, g_wh_fc2);
    cudaGetSymbolAddress((void**)&wlf2, g_wl_fc2);

    cudaFuncSetAttribute(attn_mma, cudaFuncAttributeMaxDynamicSharedMemorySize, ASM_TOT);
    cudaFuncSetAttribute(mma_gemm<0>, cudaFuncAttributeMaxDynamicSharedMemorySize, GSM_TOT);
    cudaFuncSetAttribute(mma_gemm<1>, cudaFuncAttributeMaxDynamicSharedMemorySize, GSM_TOT);
    cudaFuncSetAttribute(mma_gemm<2>, cudaFuncAttributeMaxDynamicSharedMemorySize, GSM_TOT);
    cudaFuncSetAttribute(mma_gemm<3>, cudaFuncAttributeMaxDynamicSharedMemorySize, GSM_TOT);

    // fork: side stream does wconv (needed by gemm0) then bucket (needed by attn)
    cudaEventRecord(g_evF, 0);
    cudaStreamWaitEvent(g_side, g_evF, 0);
    wconv_all<<<2048, 256, 0, g_side>>>(w_attn, wha, wla, w_proj, whp, wlp,
                                        w_fc, whf, wlf, w_fc2, whf2, wlf2);
    cudaEventRecord(g_evW, g_side);
    bucket_kernel<<<dim3(36, Bb), 256, 0, g_side>>>(ct);
    cudaEventRecord(g_evJ, g_side);

    // main: activation split (concurrent with wconv), then gemm0 split in two halves
    aconv_kernel<<<(Mrows*Cc/4 + 255)/256, 256>>>((const float4*)x, (uint2*)ahi, (uint2*)alo, Mrows*Cc/4);
    cudaStreamWaitEvent(0, g_evW, 0);
    mma_gemm<0><<<dim3(24, G0_TILES_A), 256, GSM_TOT>>>(ahi, alo, wha, wla, b_attn,
                                                 nullptr, nullptr, nullptr, nullptr, Mrows, 3*Cc, Cc, 0);
    cudaEventRecord(g_ev0A, 0);
    mma_gemm<0><<<dim3(24, G0_TILES_B), 256, GSM_TOT>>>(ahi, alo, wha, wla, b_attn,
                                                 nullptr, nullptr, nullptr, nullptr, Mrows, 3*Cc, Cc, G0_TILES_A);

    // ---- chain A (side stream): attnA (batches 0-15) overlaps gemm0B, then its tail ----
    cudaStreamWaitEvent(g_side, g_ev0A, 0);        // bucket already ordered on side
    attn_mma<<<dim3(8, 128), 256, ASM_TOT, g_side>>>(rpe_table, 0);
    cudaEventRecord(g_evAA, g_side);
    mma_gemm<1><<<dim3(8, TILES_A), 256, GSM_TOT, g_side>>>(ahi, alo, whp, wlp, b_proj,
                                                res_, x, nullptr, nullptr, Mrows, Cc, Cc, 0);
    ln_kernel<<<ROWS_A, 256, 0, g_side>>>(res_, ln1_w, ln1_b, x1_, ahi, alo, 0);
    mma_gemm<2><<<dim3(16, TILES_A), 256, GSM_TOT, g_side>>>(ahi, alo, whf, wlf, b_fc,
                                                 nullptr, nullptr, bhi, blo, Mrows, 2*Cc, Cc, 0);
    mma_gemm<3><<<dim3(8, TILES_A), 256, GSM_TOT, g_side>>>(bhi, blo, whf2, wlf2, b_fc2,
                                                res2_, x1_, nullptr, nullptr, Mrows, Cc, 2*Cc, 0);
    ln_kernel<<<ROWS_A, 256, 0, g_side>>>(res2_, ln2_w, ln2_b, out, nullptr, nullptr, 0);
    cudaEventRecord(g_evB, g_side);

    // ---- chain B (main stream): attnB (batches 16-31) after gemm0B, then its tail ----
    cudaStreamWaitEvent(0, g_evJ, 0);              // bucket needed by attnB
    attn_mma<<<dim3(8, 128), 256, ASM_TOT>>>(rpe_table, 128);
    cudaStreamWaitEvent(0, g_evAA, 0);             // tile 62 spans batches 15/16
    mma_gemm<1><<<dim3(8, TILES_B), 256, GSM_TOT>>>(ahi, alo, whp, wlp, b_proj,
                                                res_, x, nullptr, nullptr, Mrows, Cc, Cc, TILES_A);
    ln_kernel<<<Mrows - ROWS_A, 256>>>(res_, ln1_w, ln1_b, x1_, ahi, alo, ROWS_A);
    mma_gemm<2><<<dim3(16, TILES_B), 256, GSM_TOT>>>(ahi, alo, whf, wlf, b_fc,
                                                 nullptr, nullptr, bhi, blo, Mrows, 2*Cc, Cc, TILES_A);
    mma_gemm<3><<<dim3(8, TILES_B), 256, GSM_TOT>>>(bhi, blo, whf2, wlf2, b_fc2,
                                                res2_, x1_, nullptr, nullptr, Mrows, Cc, 2*Cc, TILES_A);
    ln_kernel<<<Mrows - ROWS_A, 256>>>(res2_, ln2_w, ln2_b, out, nullptr, nullptr, ROWS_A);

    // join
    cudaStreamWaitEvent(0, g_evB, 0);
}